// round 12
// baseline (speedup 1.0000x reference)
#include <cuda_runtime.h>
#include <cuda_bf16.h>
#include <cuda_fp16.h>
#include <math.h>
#include <stdint.h>

// Problem constants
#define BB    2
#define NN    1024
#define DD    512
#define HH    8
#define DH    64
#define KKB   4
#define VV    32000
#define INNER 1536
#define CKW   3
#define MROWS (BB*NN)     // 2048
#define BHN   (BB*HH)     // 16
#define TOTAL_PASSES 8

#define AMS  40    // A smem stride (16-bit elems): 32 data + 8 pad
#define QS   72    // attention smem stride (64 + 8)
#define NS   3     // GEMM pipeline stages

typedef __nv_bfloat16 bf16;
typedef __half h16;

// ---------------- fp32 scratch ----------------------------------------------
__device__ __align__(16) float g_X  [MROWS*DD];
__device__ __align__(16) float g_Q  [MROWS*DD];
__device__ __align__(16) float g_Qi [MROWS*DD];
__device__ __align__(16) float g_Qn [MROWS*DD];
__device__ __align__(16) float g_Hf [(size_t)MROWS*INNER];

// ---------------- activation scratch -----------------------------------------
__device__ __align__(16) h16 g_Hch [MROWS*DD], g_Hcl [MROWS*DD];
__device__ __align__(16) h16 g_mbh [MROWS*DD], g_mbl [MROWS*DD];
__device__ __align__(16) h16 g_Q2h [MROWS*DD], g_Q2l [MROWS*DD];
__device__ __align__(16) h16 g_Hvh [(size_t)MROWS*INNER], g_Hvl [(size_t)MROWS*INNER];
__device__ __align__(16) h16 g_Qnh [MROWS*DD], g_Qnl [MROWS*DD];
__device__ __align__(16) bf16 g_PQh [MROWS*DD], g_PQl [MROWS*DD];
__device__ __align__(16) bf16 g_PKh [MROWS*DD], g_PKl [MROWS*DD];
__device__ __align__(16) bf16 g_Vh  [MROWS*DD], g_Vl  [MROWS*DD];

// ---------------- single-fp16 weight scratch ---------------------------------
__device__ __align__(16) h16 g_WQh [KKB*DD*DD];
__device__ __align__(16) h16 g_WKh [KKB*DD*DD];
__device__ __align__(16) h16 g_WVh [KKB*DD*DD];
__device__ __align__(16) h16 g_WOh [KKB*DD*DD];
__device__ __align__(16) h16 g_WUh [(size_t)KKB*DD*2*INNER];
__device__ __align__(16) h16 g_WDh [(size_t)KKB*INNER*DD];
__device__ __align__(16) h16 g_LMh [(size_t)VV*DD];

// ---------------- helpers ----------------------------------------------------
__device__ __forceinline__ float siluf(float x) { return x / (1.0f + expf(-x)); }

__device__ __forceinline__ bool read_halted(const void* p, int b)
{
    const unsigned char* u8 = (const unsigned char*)p;
    if (u8[1] != 0) return u8[b] != 0;
    return ((const int*)p)[b] != 0;
}
__device__ __forceinline__ uint32_t smem_u32(const void* p) {
    uint32_t a;
    asm("{ .reg .u64 t; cvta.to.shared.u64 t, %1; cvt.u32.u64 %0, t; }"
        : "=r"(a) : "l"(p));
    return a;
}
__device__ __forceinline__ void ldm4(uint32_t* r, uint32_t a) {
    asm volatile("ldmatrix.sync.aligned.m8n8.x4.shared.b16 {%0,%1,%2,%3}, [%4];"
                 : "=r"(r[0]), "=r"(r[1]), "=r"(r[2]), "=r"(r[3]) : "r"(a));
}
__device__ __forceinline__ void ldm4t(uint32_t* r, uint32_t a) {
    asm volatile("ldmatrix.sync.aligned.m8n8.x4.trans.shared.b16 {%0,%1,%2,%3}, [%4];"
                 : "=r"(r[0]), "=r"(r[1]), "=r"(r[2]), "=r"(r[3]) : "r"(a));
}
__device__ __forceinline__ void mma_bf16(float* c, const uint32_t* a, const uint32_t* b) {
    asm volatile("mma.sync.aligned.m16n8k16.row.col.f32.bf16.bf16.f32 "
                 "{%0,%1,%2,%3}, {%4,%5,%6,%7}, {%8,%9}, {%0,%1,%2,%3};"
                 : "+f"(c[0]), "+f"(c[1]), "+f"(c[2]), "+f"(c[3])
                 : "r"(a[0]), "r"(a[1]), "r"(a[2]), "r"(a[3]),
                   "r"(b[0]), "r"(b[1]));
}
__device__ __forceinline__ void mma_f16(float* c, const uint32_t* a, const uint32_t* b) {
    asm volatile("mma.sync.aligned.m16n8k16.row.col.f32.f16.f16.f32 "
                 "{%0,%1,%2,%3}, {%4,%5,%6,%7}, {%8,%9}, {%0,%1,%2,%3};"
                 : "+f"(c[0]), "+f"(c[1]), "+f"(c[2]), "+f"(c[3])
                 : "r"(a[0]), "r"(a[1]), "r"(a[2]), "r"(a[3]),
                   "r"(b[0]), "r"(b[1]));
}
__device__ __forceinline__ uint32_t pack2(bf16 a, bf16 b) {
    return (uint32_t)__bfloat16_as_ushort(a) |
           ((uint32_t)__bfloat16_as_ushort(b) << 16);
}
__device__ __forceinline__ uint32_t pack2h(h16 a, h16 b) {
    return (uint32_t)__half_as_ushort(a) |
           ((uint32_t)__half_as_ushort(b) << 16);
}
__device__ __forceinline__ void split1(float v, bf16& h, bf16& l) {
    h = __float2bfloat16(v);
    l = __float2bfloat16(v - __bfloat162float(h));
}
__device__ __forceinline__ void split1h(float v, h16& h, h16& l) {
    h = __float2half_rn(v);
    l = __float2half_rn(v - __half2float(h));
}
__device__ __forceinline__ void cpa16(uint32_t s, const void* g) {
    asm volatile("cp.async.cg.shared.global [%0], [%1], 16;" :: "r"(s), "l"(g));
}
#define CP_COMMIT() asm volatile("cp.async.commit_group;" ::: "memory")
#define CP_WAIT0()  asm volatile("cp.async.wait_group 0;" ::: "memory")
#define CP_WAIT1()  asm volatile("cp.async.wait_group 1;" ::: "memory")
#define CP_WAIT2()  asm volatile("cp.async.wait_group 2;" ::: "memory")

// ---------------- converters --------------------------------------------------
__global__ void cvt_h_kernel(const float* __restrict__ src, h16* __restrict__ d, int n4)
{
    int i = blockIdx.x * 256 + threadIdx.x;
    if (i >= n4) return;
    float4 v = *(const float4*)(src + (size_t)i * 4);
    uint2 o;
    o.x = pack2h(__float2half_rn(v.x), __float2half_rn(v.y));
    o.y = pack2h(__float2half_rn(v.z), __float2half_rn(v.w));
    *(uint2*)(d + (size_t)i * 4) = o;
}

__global__ void cvt_up_kernel(const float* __restrict__ src, h16* __restrict__ d)
{
    int gi = blockIdx.x * 256 + threadIdx.x;
    int total = KKB * DD * (2 * INNER) / 8;
    if (gi >= total) return;
    int cg8 = gi % (2 * INNER / 8);
    int row = gi / (2 * INNER / 8);
    int cg = cg8 * 4;
    size_t rb = (size_t)row * (2 * INNER);
    float4 gsrc = *(const float4*)(src + rb + cg);
    float4 usrc = *(const float4*)(src + rb + INNER + cg);
    float gv[4] = {gsrc.x, gsrc.y, gsrc.z, gsrc.w};
    float uv[4] = {usrc.x, usrc.y, usrc.z, usrc.w};
    uint32_t w[4];
    #pragma unroll
    for (int q = 0; q < 4; q++)
        w[q] = pack2h(__float2half_rn(gv[q]), __float2half_rn(uv[q]));
    size_t db = rb + (size_t)cg8 * 8;
    *(uint4*)(d + db) = make_uint4(w[0], w[1], w[2], w[3]);
}

// ---------------- 3-stage pipelined fp16x2 GEMM body -------------------------
// smem: [Ah s0..s2 | Al s0..s2 | B s0..s2]
template <int BN>
__device__ __forceinline__ void stage_gemm(
    uint32_t base, int st, int kc, int tid, int m0, int n0,
    const h16* __restrict__ Ah, const h16* __restrict__ Al, int lda,
    const h16* __restrict__ B, int ldb)
{
    constexpr int BNS_ = (BN == 128) ? 136 : 72;
    constexpr uint32_t ASZ = 128 * AMS, BSZ = 32 * BNS_;
    const uint32_t oAh = 0, oAl = NS * ASZ * 2, oB = 2 * NS * ASZ * 2;
    #pragma unroll
    for (int it2 = 0; it2 < 2; it2++) {
        int g = tid + 256 * it2;
        int row = g >> 2, c8 = (g & 3) * 8;
        size_t go = (size_t)(m0 + row) * lda + kc * 32 + c8;
        uint32_t so = (uint32_t)(st * ASZ + row * AMS + c8) * 2;
        cpa16(base + oAh + so, Ah + go);
        cpa16(base + oAl + so, Al + go);
    }
    {
        if (BN == 128) {
            #pragma unroll
            for (int it2 = 0; it2 < 2; it2++) {
                int g = tid + 256 * it2;
                int row = g >> 4, c8 = (g & 15) * 8;
                size_t go = (size_t)(kc * 32 + row) * ldb + n0 + c8;
                uint32_t so = (uint32_t)(st * BSZ + row * BNS_ + c8) * 2;
                cpa16(base + oB + so, B + go);
            }
        } else {
            int g = tid;
            int row = g >> 3, c8 = (g & 7) * 8;
            size_t go = (size_t)(kc * 32 + row) * ldb + n0 + c8;
            uint32_t so = (uint32_t)(st * BSZ + row * BNS_ + c8) * 2;
            cpa16(base + oB + so, B + go);
        }
    }
}

// epi: 0 fp32, 1 bf16 hi/lo elu+1, 2 fp32 addP+alpha*acc, 3 fp32 addP+acc,
//      4 bf16 hi/lo plain, 5 fused swiglu -> fp32 Hf
template <int BN>
__device__ __forceinline__ void gemm_pipe(
    h16* smem,
    const h16* __restrict__ Ah, const h16* __restrict__ Al, int lda,
    const h16* __restrict__ B, int ldb,
    float* __restrict__ Cf, bf16* __restrict__ Ch, bf16* __restrict__ Cl, int ldc,
    int m0, int n0, int kch, int epi, const float* __restrict__ addP, float alpha)
{
    constexpr int BNS_ = (BN == 128) ? 136 : 72;
    constexpr int NJ = BN / 16;
    constexpr uint32_t ASZ = 128 * AMS, BSZ = 32 * BNS_;
    const uint32_t base = smem_u32(smem);
    const uint32_t oAh = 0, oAl = NS * ASZ * 2, oB = 2 * NS * ASZ * 2;
    const int tid = threadIdx.x, lane = tid & 31, wid = tid >> 5;
    const int warp_m = wid >> 1, warp_n = wid & 1;

    float acc[2][NJ][4];
    #pragma unroll
    for (int i = 0; i < 2; i++)
        #pragma unroll
        for (int j = 0; j < NJ; j++)
            #pragma unroll
            for (int q = 0; q < 4; q++) acc[i][j][q] = 0.0f;

    stage_gemm<BN>(base, 0, 0, tid, m0, n0, Ah, Al, lda, B, ldb);
    CP_COMMIT();
    if (1 < kch) {
        stage_gemm<BN>(base, 1, 1, tid, m0, n0, Ah, Al, lda, B, ldb);
        CP_COMMIT();
    }

    int st = 0;
    for (int kc = 0; kc < kch; kc++) {
        if (kc + 2 < kch) {
            stage_gemm<BN>(base, (kc + 2) % NS, kc + 2, tid, m0, n0, Ah, Al, lda, B, ldb);
            CP_COMMIT();
            CP_WAIT2();
        } else if (kc + 1 < kch) {
            CP_WAIT1();
        } else {
            CP_WAIT0();
        }
        __syncthreads();

        #pragma unroll
        for (int s = 0; s < 2; s++) {
            uint32_t ah[2][4], al[2][4], bh[NJ][2];
            #pragma unroll
            for (int i = 0; i < 2; i++) {
                int r  = warp_m * 32 + i * 16 + (lane & 15);
                int kb = s * 16 + ((lane >> 4) << 3);
                uint32_t so = (uint32_t)(st * ASZ + r * AMS + kb) * 2;
                ldm4(ah[i], base + oAh + so);
                ldm4(al[i], base + oAl + so);
            }
            #pragma unroll
            for (int j2 = 0; j2 < NJ / 2; j2++) {
                int kk = s * 16 + (lane & 7) + ((lane >> 3) & 1) * 8;
                int nn = warp_n * (BN / 2) + j2 * 16 + (lane >> 4) * 8;
                uint32_t so = (uint32_t)(st * BSZ + kk * BNS_ + nn) * 2;
                uint32_t q[4];
                ldm4t(q, base + oB + so);
                bh[2*j2][0] = q[0]; bh[2*j2][1] = q[1];
                bh[2*j2+1][0] = q[2]; bh[2*j2+1][1] = q[3];
            }
            #pragma unroll
            for (int i = 0; i < 2; i++)
                #pragma unroll
                for (int j = 0; j < NJ; j++) {
                    mma_f16(acc[i][j], ah[i], bh[j]);
                    mma_f16(acc[i][j], al[i], bh[j]);
                }
        }
        __syncthreads();
        st = (st + 1 == NS) ? 0 : st + 1;
    }

    #pragma unroll
    for (int i = 0; i < 2; i++) {
        int m = m0 + warp_m * 32 + i * 16 + (lane >> 2);
        #pragma unroll
        for (int j = 0; j < NJ; j++) {
            int n = n0 + warp_n * (BN / 2) + j * 8 + (lane & 3) * 2;
            float v0 = acc[i][j][0], v1 = acc[i][j][1];
            float v2 = acc[i][j][2], v3 = acc[i][j][3];
            if (epi == 5) {
                int col = n >> 1;
                Cf[(size_t)m * INNER + col]       = siluf(v0) * v1;
                Cf[(size_t)(m + 8) * INNER + col] = siluf(v2) * v3;
                continue;
            }
            size_t i0 = (size_t)m * ldc + n;
            size_t i1 = (size_t)(m + 8) * ldc + n;
            if (epi == 1 || epi == 4) {
                if (epi == 1) {
                    v0 = (v0 > 0.f) ? v0 + 1.f : expf(v0);
                    v1 = (v1 > 0.f) ? v1 + 1.f : expf(v1);
                    v2 = (v2 > 0.f) ? v2 + 1.f : expf(v2);
                    v3 = (v3 > 0.f) ? v3 + 1.f : expf(v3);
                }
                bf16 h0, h1, h2, h3, l0, l1, l2, l3;
                split1(v0, h0, l0); split1(v1, h1, l1);
                split1(v2, h2, l2); split1(v3, h3, l3);
                *(uint32_t*)(Ch + i0) = pack2(h0, h1);
                *(uint32_t*)(Cl + i0) = pack2(l0, l1);
                *(uint32_t*)(Ch + i1) = pack2(h2, h3);
                *(uint32_t*)(Cl + i1) = pack2(l2, l3);
            } else {
                if (epi == 2) {
                    v0 = addP[i0] + alpha * v0; v1 = addP[i0+1] + alpha * v1;
                    v2 = addP[i1] + alpha * v2; v3 = addP[i1+1] + alpha * v3;
                } else if (epi == 3) {
                    v0 += addP[i0]; v1 += addP[i0+1];
                    v2 += addP[i1]; v3 += addP[i1+1];
                }
                *(float2*)(Cf + i0) = make_float2(v0, v1);
                *(float2*)(Cf + i1) = make_float2(v2, v3);
            }
        }
    }
}

// smem sizes (bytes): 3 stages
#define SM_G128 87552    // 3*(2*5120 + 4352)*2
#define SM_G64  75264    // 3*(2*5120 + 2304)*2
#define SM_LM   153600   // 3*(2*10240 + 5120)*2
#define ATT_SMEM 184320

// ---------------- GEMM wrappers (2 CTAs/SM) -----------------------------------
__global__ void __launch_bounds__(256, 2) mma_proj(
    const h16* __restrict__ Ah, const h16* __restrict__ Al, int kIdx)
{
    extern __shared__ __align__(16) h16 dsm[];
    int z = blockIdx.z;
    size_t wo = (size_t)kIdx * DD * DD;
    const h16* B = (z == 0) ? g_WQh + wo : (z == 1) ? g_WKh + wo : g_WVh + wo;
    bf16* Ch = (z == 0) ? g_PQh : (z == 1) ? g_PKh : g_Vh;
    bf16* Cl = (z == 0) ? g_PQl : (z == 1) ? g_PKl : g_Vl;
    gemm_pipe<128>(dsm, Ah, Al, DD, B, DD,
                   nullptr, Ch, Cl, DD, blockIdx.y * 128, blockIdx.x * 128,
                   DD / 32, (z < 2) ? 1 : 4, nullptr, 0.f);
}

__global__ void __launch_bounds__(256, 2) mma_wo(
    const h16* __restrict__ Ah, const h16* __restrict__ Al, int kIdx,
    float* __restrict__ C, const float* __restrict__ addP,
    const float* __restrict__ dt)
{
    extern __shared__ __align__(16) h16 dsm[];
    size_t wo = (size_t)kIdx * DD * DD;
    float d = dt[kIdx];
    float alpha = (d > 20.0f) ? d : log1pf(expf(d));
    gemm_pipe<64>(dsm, Ah, Al, DD, g_WOh + wo, DD,
                  C, nullptr, nullptr, DD, blockIdx.y * 128, blockIdx.x * 64,
                  DD / 32, 2, addP, alpha);
}

__global__ void __launch_bounds__(256, 2) mma_up(
    const h16* __restrict__ Ah, const h16* __restrict__ Al, int kIdx,
    float* __restrict__ Hf)
{
    extern __shared__ __align__(16) h16 dsm[];
    size_t wo = (size_t)kIdx * DD * 2 * INNER;
    gemm_pipe<128>(dsm, Ah, Al, DD, g_WUh + wo, 2 * INNER,
                   Hf, nullptr, nullptr, 2 * INNER, blockIdx.y * 128, blockIdx.x * 128,
                   DD / 32, 5, nullptr, 0.f);
}

__global__ void __launch_bounds__(256, 2) mma_down(
    const h16* __restrict__ Ah, const h16* __restrict__ Al, int kIdx,
    float* __restrict__ C, const float* __restrict__ addP)
{
    extern __shared__ __align__(16) h16 dsm[];
    size_t wo = (size_t)kIdx * INNER * DD;
    gemm_pipe<64>(dsm, Ah, Al, INNER, g_WDh + wo, DD,
                  C, nullptr, nullptr, DD, blockIdx.y * 128, blockIdx.x * 64,
                  INNER / 32, 3, addP, 0.f);
}

// ---------------- fused flash attention (bf16x3, 2-stage K/V) -----------------
__device__ __forceinline__ void stage_kv(
    uint32_t base, int st, int kt, int tid, size_t rowbase,
    const bf16* __restrict__ PKh, const bf16* __restrict__ PKl,
    const bf16* __restrict__ Vh,  const bf16* __restrict__ Vl)
{
    const uint32_t QSZB = 128 * QS * 2;
    const uint32_t oKh = 2 * QSZB + st * QSZB;
    const uint32_t oKl = 4 * QSZB + st * QSZB;
    const uint32_t oVh = 6 * QSZB + st * QSZB;
    const uint32_t oVl = 8 * QSZB + st * QSZB;
    #pragma unroll
    for (int it2 = 0; it2 < 4; it2++) {
        int g = tid + 256 * it2;
        int row = g >> 3, c8 = (g & 7) * 8;
        size_t go = rowbase + (size_t)(kt * 128 + row) * DD + c8;
        uint32_t so = (uint32_t)(row * QS + c8) * 2;
        cpa16(base + oKh + so, PKh + go);
        cpa16(base + oKl + so, PKl + go);
        cpa16(base + oVh + so, Vh + go);
        cpa16(base + oVl + so, Vl + go);
    }
}

__global__ void __launch_bounds__(256) attn_fused(
    const bf16* __restrict__ PQh, const bf16* __restrict__ PQl,
    const bf16* __restrict__ PKh, const bf16* __restrict__ PKl,
    const bf16* __restrict__ Vh,  const bf16* __restrict__ Vl,
    h16* __restrict__ Mh, h16* __restrict__ Ml)
{
    extern __shared__ __align__(16) bf16 dsmb[];
    const uint32_t base = smem_u32(dsmb);
    const uint32_t QSZB = 128 * QS * 2;

    const int tid = threadIdx.x, lane = tid & 31, w = tid >> 5;
    const int bh = blockIdx.y, b = bh >> 3, h = bh & 7;
    const int q0 = blockIdx.x * 128;
    const size_t rowbase = (size_t)(b * NN) * DD + h * DH;

    #pragma unroll
    for (int it2 = 0; it2 < 4; it2++) {
        int g = tid + 256 * it2;
        int row = g >> 3, c8 = (g & 7) * 8;
        size_t go = rowbase + (size_t)(q0 + row) * DD + c8;
        uint32_t so = (uint32_t)(row * QS + c8) * 2;
        cpa16(base + so, PQh + go);
        cpa16(base + QSZB + so, PQl + go);
    }
    stage_kv(base, 0, 0, tid, rowbase, PKh, PKl, Vh, Vl);
    CP_COMMIT();
    CP_WAIT0();
    __syncthreads();

    uint32_t qh[4][4], ql[4][4];
    #pragma unroll
    for (int s = 0; s < 4; s++) {
        int r  = w * 16 + (lane & 15);
        int kb = s * 16 + ((lane >> 4) << 3);
        uint32_t so = (uint32_t)(r * QS + kb) * 2;
        ldm4(qh[s], base + so);
        ldm4(ql[s], base + QSZB + so);
    }

    float oacc[8][4];
    #pragma unroll
    for (int j = 0; j < 8; j++)
        #pragma unroll
        for (int q = 0; q < 4; q++) oacc[j][q] = 0.0f;
    float p0 = 0.0f, p1 = 0.0f;

    int st = 0;
    for (int kt = 0; kt < NN / 128; kt++) {
        if (kt + 1 < NN / 128) {
            stage_kv(base, st ^ 1, kt + 1, tid, rowbase, PKh, PKl, Vh, Vl);
            CP_COMMIT();
            CP_WAIT1();
        } else {
            CP_WAIT0();
        }
        __syncthreads();

        const uint32_t oKh = 2 * QSZB + st * QSZB;
        const uint32_t oKl = 4 * QSZB + st * QSZB;
        const uint32_t oVh = 6 * QSZB + st * QSZB;
        const uint32_t oVl = 8 * QSZB + st * QSZB;

        #pragma unroll
        for (int t = 0; t < 8; t++) {
            float sacc[2][4] = {};
            #pragma unroll
            for (int s = 0; s < 4; s++) {
                int r  = t * 16 + (lane & 7) + ((lane >> 4) << 3);
                int kb = s * 16 + (((lane >> 3) & 1) << 3);
                uint32_t so = (uint32_t)(r * QS + kb) * 2;
                uint32_t kh[4], kl[4];
                ldm4(kh, base + oKh + so);
                ldm4(kl, base + oKl + so);
                mma_bf16(sacc[0], qh[s], kh + 0);
                mma_bf16(sacc[0], ql[s], kh + 0);
                mma_bf16(sacc[0], qh[s], kl + 0);
                mma_bf16(sacc[1], qh[s], kh + 2);
                mma_bf16(sacc[1], ql[s], kh + 2);
                mma_bf16(sacc[1], qh[s], kl + 2);
            }
            float w2[2][4];
            #pragma unroll
            for (int f = 0; f < 2; f++)
                #pragma unroll
                for (int q = 0; q < 4; q++) {
                    float x = fmaxf(sacc[f][q], 0.0f);
                    w2[f][q] = x * x;
                }
            p0 += w2[0][0] + w2[0][1] + w2[1][0] + w2[1][1];
            p1 += w2[0][2] + w2[0][3] + w2[1][2] + w2[1][3];
            uint32_t wh[4], wl[4];
            {
                bf16 h0, h1, l0, l1;
                split1(w2[0][0], h0, l0); split1(w2[0][1], h1, l1);
                wh[0] = pack2(h0, h1); wl[0] = pack2(l0, l1);
                split1(w2[0][2], h0, l0); split1(w2[0][3], h1, l1);
                wh[1] = pack2(h0, h1); wl[1] = pack2(l0, l1);
                split1(w2[1][0], h0, l0); split1(w2[1][1], h1, l1);
                wh[2] = pack2(h0, h1); wl[2] = pack2(l0, l1);
                split1(w2[1][2], h0, l0); split1(w2[1][3], h1, l1);
                wh[3] = pack2(h0, h1); wl[3] = pack2(l0, l1);
            }
            #pragma unroll
            for (int n = 0; n < 4; n++) {
                int kk = t * 16 + (lane & 7) + ((lane >> 3) & 1) * 8;
                int nn = n * 16 + (lane >> 4) * 8;
                uint32_t so = (uint32_t)(kk * QS + nn) * 2;
                uint32_t vh[4], vl[4];
                ldm4t(vh, base + oVh + so);
                ldm4t(vl, base + oVl + so);
                mma_bf16(oacc[2*n],   wh, vh + 0);
                mma_bf16(oacc[2*n],   wl, vh + 0);
                mma_bf16(oacc[2*n],   wh, vl + 0);
                mma_bf16(oacc[2*n+1], wh, vh + 2);
                mma_bf16(oacc[2*n+1], wl, vh + 2);
                mma_bf16(oacc[2*n+1], wh, vl + 2);
            }
        }
        __syncthreads();
        st ^= 1;
    }

    p0 += __shfl_xor_sync(0xFFFFFFFFu, p0, 1);
    p0 += __shfl_xor_sync(0xFFFFFFFFu, p0, 2);
    p1 += __shfl_xor_sync(0xFFFFFFFFu, p1, 1);
    p1 += __shfl_xor_sync(0xFFFFFFFFu, p1, 2);
    float rd0 = 1.0f / (p0 + 1.0f);
    float rd1 = 1.0f / (p1 + 1.0f);

    int r0 = q0 + w * 16 + (lane >> 2);
    int r1 = r0 + 8;
    #pragma unroll
    for (int j = 0; j < 8; j++) {
        int d = j * 8 + (lane & 3) * 2;
        size_t i0 = rowbase + (size_t)r0 * DD + d;
        size_t i1 = rowbase + (size_t)r1 * DD + d;
        uint32_t vh0 = *(const uint32_t*)(Vh + i0), vl0 = *(const uint32_t*)(Vl + i0);
        uint32_t vh1 = *(const uint32_t*)(Vh + i1), vl1 = *(const uint32_t*)(Vl + i1);
        float vp00 = __bfloat162float(__ushort_as_bfloat16((unsigned short)(vh0 & 0xFFFF))) +
                     __bfloat162float(__ushort_as_bfloat16((unsigned short)(vl0 & 0xFFFF)));
        float vp01 = __bfloat162float(__ushort_as_bfloat16((unsigned short)(vh0 >> 16))) +
                     __bfloat162float(__ushort_as_bfloat16((unsigned short)(vl0 >> 16)));
        float vp10 = __bfloat162float(__ushort_as_bfloat16((unsigned short)(vh1 & 0xFFFF))) +
                     __bfloat162float(__ushort_as_bfloat16((unsigned short)(vl1 & 0xFFFF)));
        float vp11 = __bfloat162float(__ushort_as_bfloat16((unsigned short)(vh1 >> 16))) +
                     __bfloat162float(__ushort_as_bfloat16((unsigned short)(vl1 >> 16)));
        float m00 = oacc[j][0] * rd0 - vp00;
        float m01 = oacc[j][1] * rd0 - vp01;
        float m10 = oacc[j][2] * rd1 - vp10;
        float m11 = oacc[j][3] * rd1 - vp11;
        h16 h0, h1, l0, l1;
        split1h(m00, h0, l0); split1h(m01, h1, l1);
        *(uint32_t*)(Mh + i0) = pack2h(h0, h1);
        *(uint32_t*)(Ml + i0) = pack2h(l0, l1);
        split1h(m10, h0, l0); split1h(m11, h1, l1);
        *(uint32_t*)(Mh + i1) = pack2h(h0, h1);
        *(uint32_t*)(Ml + i1) = pack2h(l0, l1);
    }
}

// ---------------- LM head: 256x128 tiles, 512 threads, 3-stage fp16x2 ---------
__device__ __forceinline__ void stage_lm(
    uint32_t base, int st, int kc, int tid, int m0, int n0,
    const h16* __restrict__ Ah, const h16* __restrict__ Al)
{
    constexpr uint32_t ASZ = 256 * AMS, BSZ = 128 * AMS;
    const uint32_t oAh = 0, oAl = NS * ASZ * 2, oB = 2 * NS * ASZ * 2;
    #pragma unroll
    for (int it2 = 0; it2 < 2; it2++) {
        int g = tid + 512 * it2;
        int row = g >> 2, c8 = (g & 3) * 8;
        uint32_t so = (uint32_t)(st * ASZ + row * AMS + c8) * 2;
        size_t ga = (size_t)(m0 + row) * DD + kc * 32 + c8;
        cpa16(base + oAh + so, Ah + ga);
        cpa16(base + oAl + so, Al + ga);
    }
    {
        int g = tid;
        int row = g >> 2, c8 = (g & 3) * 8;
        uint32_t so = (uint32_t)(st * BSZ + row * AMS + c8) * 2;
        size_t gb = (size_t)(n0 + row) * DD + kc * 32 + c8;
        cpa16(base + oB + so, g_LMh + gb);
    }
}

__global__ void __launch_bounds__(512)
lm_head_mma(const h16* __restrict__ Ah, const h16* __restrict__ Al,
            float* __restrict__ C)
{
    extern __shared__ __align__(16) h16 dsm[];
    constexpr uint32_t ASZ = 256 * AMS, BSZ = 128 * AMS;
    const uint32_t base = smem_u32(dsm);
    const uint32_t oAh = 0, oAl = NS * ASZ * 2, oB = 2 * NS * ASZ * 2;
    const int tid = threadIdx.x, lane = tid & 31, wid = tid >> 5;
    const int warp_m = wid >> 1, warp_n = wid & 1;
    const int m0 = blockIdx.y * 256, n0 = blockIdx.x * 128;

    float acc[2][8][4];
    #pragma unroll
    for (int i = 0; i < 2; i++)
        #pragma unroll
        for (int j = 0; j < 8; j++)
            #pragma unroll
            for (int q = 0; q < 4; q++) acc[i][j][q] = 0.0f;

    stage_lm(base, 0, 0, tid, m0, n0, Ah, Al);
    CP_COMMIT();
    stage_lm(base, 1, 1, tid, m0, n0, Ah, Al);
    CP_COMMIT();

    int st = 0;
    for (int kc = 0; kc < 16; kc++) {
        if (kc + 2 < 16) {
            stage_lm(base, (kc + 2) % NS, kc + 2, tid, m0, n0, Ah, Al);
            CP_COMMIT();
            CP_WAIT2();
        } else if (kc + 1 < 16) {
            CP_WAIT1();
        } else {
            CP_WAIT0();
        }
        __syncthreads();

        #pragma unroll
        for (int s = 0; s < 2; s++) {
            uint32_t ah[2][4], al[2][4], bh[8][2];
            #pragma unroll
            for (int i = 0; i < 2; i++) {
                int r  = warp_m * 32 + i * 16 + (lane & 15);
                int kb = s * 16 + ((lane >> 4) << 3);
                uint32_t so = (uint32_t)(st * ASZ + r * AMS + kb) * 2;
                ldm4(ah[i], base + oAh + so);
                ldm4(al[i], base + oAl + so);
            }
            #pragma unroll
            for (int j = 0; j < 4; j++) {
                int r  = warp_n * 64 + j * 16 + (lane & 7) + ((lane >> 4) << 3);
                int kb = s * 16 + (((lane >> 3) & 1) << 3);
                uint32_t so = (uint32_t)(st * BSZ + r * AMS + kb) * 2;
                uint32_t q[4];
                ldm4(q, base + oB + so);
                bh[2*j][0] = q[0]; bh[2*j][1] = q[1];
                bh[2*j+1][0] = q[2]; bh[2*j+1][1] = q[3];
            }
            #pragma unroll
            for (int i = 0; i < 2; i++)
                #pragma unroll
                for (int j = 0; j < 8; j++) {
                    mma_f16(acc[i][j], ah[i], bh[j]);
                    mma_f16(acc[i][j], al[i], bh[j]);
                }
        }
        __syncthreads();
        st = (st + 1 == NS) ? 0 : st + 1;
    }

    #pragma unroll
    for (int i = 0; i < 2; i++) {
        int m = m0 + warp_m * 32 + i * 16 + (lane >> 2);
        #pragma unroll
        for (int j = 0; j < 8; j++) {
            int n = n0 + warp_n * 64 + j * 8 + (lane & 3) * 2;
            *(float2*)(C + (size_t)m * VV + n) =
                make_float2(acc[i][j][0], acc[i][j][1]);
            *(float2*)(C + (size_t)(m + 8) * VV + n) =
                make_float2(acc[i][j][2], acc[i][j][3]);
        }
    }
}

// ---------------- init -------------------------------------------------------
__global__ void init_kernel(const int* __restrict__ inputs,
                            const int* __restrict__ carry_inputs,
                            const void* __restrict__ halted,
                            const float* __restrict__ carry_hidden,
                            const float* __restrict__ init_hidden,
                            const float* __restrict__ emb,
                            const float* __restrict__ pos,
                            const float* __restrict__ in_s,
                            const float* __restrict__ in_b)
{
    int r = blockIdx.x;
    int b = r / NN, n = r % NN;
    int t = threadIdx.x;
    bool h = read_halted(halted, b);
    int idx = h ? inputs[r] : carry_inputs[r];
    const float* e = emb + (size_t)idx * DD;
    const float* p = pos + (size_t)n * DD;

    float x0 = e[t]       + p[t];
    float x1 = e[t + 256] + p[t + 256];

    size_t base = (size_t)r * DD;
    g_Q[base + t]       = h ? init_hidden[t]       : carry_hidden[base + t];
    g_Q[base + t + 256] = h ? init_hidden[t + 256] : carry_hidden[base + t + 256];

    __shared__ float s_sum[256], s_sq[256];
    s_sum[t] = x0 + x1;
    s_sq[t]  = x0 * x0 + x1 * x1;
    __syncthreads();
    for (int o = 128; o > 0; o >>= 1) {
        if (t < o) { s_sum[t] += s_sum[t + o]; s_sq[t] += s_sq[t + o]; }
        __syncthreads();
    }
    float mu   = s_sum[0] * (1.0f / DD);
    float var  = s_sq[0] * (1.0f / DD) - mu * mu;
    float rstd = rsqrtf(var + 1e-5f);
    g_X[base + t]       = (x0 - mu) * rstd * in_s[t]       + in_b[t];
    g_X[base + t + 256] = (x1 - mu) * rstd * in_s[t + 256] + in_b[t + 256];
}

// ---------------- LayerNorm (fp32 in; optional fp32 out; fp16 hi/lo out) -----
__global__ void ln_kernel(const float* __restrict__ in, float* __restrict__ outf,
                          h16* __restrict__ outh, h16* __restrict__ outl,
                          const float* __restrict__ s, const float* __restrict__ bia,
                          const float* __restrict__ add)
{
    int r = blockIdx.x;
    int t = threadIdx.x;
    size_t base = (size_t)r * DD;
    float x0 = in[base + t];
    float x1 = in[base + t + 256];

    __shared__ float s_sum[256], s_sq[256];
    s_sum[t] = x0 + x1;
    s_sq[t]  = x0 * x0 + x1 * x1;
    __syncthreads();
    for (int o = 128; o > 0; o >>= 1) {
        if (t < o) { s_sum[t] += s_sum[t + o]; s_sq[t] += s_sq[t + o]; }
        __syncthreads();
    }
    float mu   = s_sum[0] * (1.0f / DD);
    float var  = s_sq[0] * (1.0f / DD) - mu * mu;
    float rstd = rsqrtf(var + 1e-5f);
    float v0 = (x0 - mu) * rstd * s[t]       + bia[t];
    float v1 = (x1 - mu) * rstd * s[t + 256] + bia[t + 256];
    if (add) { v0 += add[base + t]; v1 += add[base + t + 256]; }
    if (outf) { outf[base + t] = v0; outf[base + t + 256] = v1; }
    if (outh) {
        h16 h0, l0, h1, l1;
        split1h(v0, h0, l0); split1h(v1, h1, l1);
        outh[base + t] = h0;       outl[base + t] = l0;
        outh[base + t + 256] = h1; outl[base + t + 256] = l1;
    }
}

// ---------------- depthwise conv k=3 + bias + silu -> fp16 hi/lo --------------
__global__ void conv_kernel(const float* __restrict__ Hf, const float* __restrict__ w,
                            const float* __restrict__ bias,
                            h16* __restrict__ outh, h16* __restrict__ outl)
{
    size_t i = (size_t)blockIdx.x * 256 + threadIdx.x;
    if (i >= (size_t)MROWS * INNER) return;
    size_t row = i / INNER;
    int c = (int)(i % INNER);
    int n = (int)(row % NN);
    const float* wc = w + (size_t)c * CKW;
    float acc = bias[c];
    if (n > 0)      acc += wc[0] * Hf[(row - 1) * INNER + c];
    acc += wc[1] * Hf[row * INNER + c];
    if (n < NN - 1) acc += wc[2] * Hf[(row + 1) * INNER + c];
    float v = siluf(acc);
    h16 h, l;
    split1h(v, h, l);
    outh[i] = h;
    outl[i] = l;
}

// ---------------- halt head --------------------------------------------------
__global__ void halt_kernel(const float* __restrict__ Qn, const float* __restrict__ hw,
                            const float* __restrict__ hb, float* __restrict__ out)
{
    int b = blockIdx.x;
    int t = threadIdx.x;
    __shared__ float md[DD];
    for (int d = t; d < DD; d += 256) {
        float s = 0.0f;
        for (int n = 0; n < NN; n++)
            s += Qn[((size_t)(b * NN + n)) * DD + d];
        md[d] = s * (1.0f / NN);
    }
    __syncthreads();
    __shared__ float r0[256], r1[256];
    float p0 = 0.0f, p1 = 0.0f;
    for (int d = t; d < DD; d += 256) {
        p0 += md[d] * hw[d];
        p1 += md[d] * hw[DD + d];
    }
    r0[t] = p0; r1[t] = p1;
    __syncthreads();
    for (int o = 128; o > 0; o >>= 1) {
        if (t < o) { r0[t] += r0[t + o]; r1[t] += r1[t + o]; }
        __syncthreads();
    }
    if (t == 0) {
        out[b * 2 + 0] = r0[0] + hb[0];
        out[b * 2 + 1] = r1[0] + hb[1];
    }
}

// ---------------- host orchestration -----------------------------------------
static void cvt_h(const float* src, h16* d, size_t n)
{
    int n4 = (int)(n / 4);
    cvt_h_kernel<<<(n4 + 255) / 256, 256>>>(src, d, n4);
}

extern "C" void kernel_launch(void* const* d_in, const int* in_sizes, int n_in,
                              void* d_out, int out_size)
{
    const int*   inputs       = (const int*)d_in[0];
    const float* carry_hidden = (const float*)d_in[2];
    const void*  halted       = d_in[4];
    const int*   carry_inputs = (const int*)d_in[5];
    const float* init_hidden  = (const float*)d_in[7];
    const float* emb          = (const float*)d_in[8];
    const float* pos          = (const float*)d_in[9];
    const float* in_s         = (const float*)d_in[10];
    const float* in_b         = (const float*)d_in[11];
    const float* fin_s        = (const float*)d_in[12];
    const float* fin_b        = (const float*)d_in[13];
    const float* lm_w         = (const float*)d_in[14];
    const float* halt_w       = (const float*)d_in[15];
    const float* halt_b       = (const float*)d_in[16];
    const float* dt           = (const float*)d_in[17];
    const float* W_Q          = (const float*)d_in[18];
    const float* W_K          = (const float*)d_in[19];
    const float* W_V          = (const float*)d_in[20];
    const float* W_O          = (const float*)d_in[21];
    const float* W_up         = (const float*)d_in[22];
    const float* dw_w         = (const float*)d_in[23];
    const float* dw_b         = (const float*)d_in[24];
    const float* W_down       = (const float*)d_in[25];
    const float* n1_s         = (const float*)d_in[26];
    const float* n1_b         = (const float*)d_in[27];
    const float* n2_s         = (const float*)d_in[28];
    const float* n2_b         = (const float*)d_in[29];

    float *X, *Q, *Qi, *Qn, *Hf;
    h16 *Hch, *Hcl, *mbh, *mbl, *Q2h, *Q2l, *Hvh, *Hvl, *Qnh, *Qnl;
    bf16 *PQh, *PQl, *PKh, *PKl, *Vh, *Vl;
    h16 *WQh, *WKh, *WVh, *WOh, *WUh, *WDh, *LMh;
    cudaGetSymbolAddress((void**)&X,   g_X);
    cudaGetSymbolAddress((void**)&Q,   g_Q);
    cudaGetSymbolAddress((void**)&Qi,  g_Qi);
    cudaGetSymbolAddress((void**)&Qn,  g_Qn);
    cudaGetSymbolAddress((void**)&Hf,  g_Hf);
    cudaGetSymbolAddress((void**)&Hch, g_Hch); cudaGetSymbolAddress((void**)&Hcl, g_Hcl);
    cudaGetSymbolAddress((void**)&PQh, g_PQh); cudaGetSymbolAddress((void**)&PQl, g_PQl);
    cudaGetSymbolAddress((void**)&PKh, g_PKh); cudaGetSymbolAddress((void**)&PKl, g_PKl);
    cudaGetSymbolAddress((void**)&Vh,  g_Vh);  cudaGetSymbolAddress((void**)&Vl,  g_Vl);
    cudaGetSymbolAddress((void**)&mbh, g_mbh); cudaGetSymbolAddress((void**)&mbl, g_mbl);
    cudaGetSymbolAddress((void**)&Q2h, g_Q2h); cudaGetSymbolAddress((void**)&Q2l, g_Q2l);
    cudaGetSymbolAddress((void**)&Hvh, g_Hvh); cudaGetSymbolAddress((void**)&Hvl, g_Hvl);
    cudaGetSymbolAddress((void**)&Qnh, g_Qnh); cudaGetSymbolAddress((void**)&Qnl, g_Qnl);
    cudaGetSymbolAddress((void**)&WQh, g_WQh);
    cudaGetSymbolAddress((void**)&WKh, g_WKh);
    cudaGetSymbolAddress((void**)&WVh, g_WVh);
    cudaGetSymbolAddress((void**)&WOh, g_WOh);
    cudaGetSymbolAddress((void**)&WUh, g_WUh);
    cudaGetSymbolAddress((void**)&WDh, g_WDh);
    cudaGetSymbolAddress((void**)&LMh, g_LMh);

    float* out = (float*)d_out;

    cudaFuncSetAttribute(attn_fused, cudaFuncAttributeMaxDynamicSharedMemorySize, ATT_SMEM);
    cudaFuncSetAttribute(mma_proj,   cudaFuncAttributeMaxDynamicSharedMemorySize, SM_G128);
    cudaFuncSetAttribute(mma_up,     cudaFuncAttributeMaxDynamicSharedMemorySize, SM_G128);
    cudaFuncSetAttribute(mma_wo,     cudaFuncAttributeMaxDynamicSharedMemorySize, SM_G64);
    cudaFuncSetAttribute(mma_down,   cudaFuncAttributeMaxDynamicSharedMemorySize, SM_G64);
    cudaFuncSetAttribute(lm_head_mma, cudaFuncAttributeMaxDynamicSharedMemorySize, SM_LM);

    cvt_h(W_Q,    WQh, (size_t)KKB * DD * DD);
    cvt_h(W_K,    WKh, (size_t)KKB * DD * DD);
    cvt_h(W_V,    WVh, (size_t)KKB * DD * DD);
    cvt_h(W_O,    WOh, (size_t)KKB * DD * DD);
    {
        int total = KKB * DD * (2 * INNER) / 8;
        cvt_up_kernel<<<(total + 255) / 256, 256>>>(W_up, WUh);
    }
    cvt_h(W_down, WDh, (size_t)KKB * INNER * DD);
    cvt_h(lm_w,   LMh, (size_t)VV * DD);

    init_kernel<<<MROWS, 256>>>(inputs, carry_inputs, halted, carry_hidden,
                                init_hidden, emb, pos, in_s, in_b);

    dim3 gP(DD / 128, MROWS / 128, 3);        // (4, 16, 3)
    dim3 gO64(DD / 64, MROWS / 128);          // (8, 16) = 128 CTAs
    dim3 gUP(2 * INNER / 128, MROWS / 128);   // (24, 16)
    dim3 gAT(NN / 128, BHN);                  // (8, 16)

    for (int it = 0; it < TOTAL_PASSES; it++) {
        int k = it % KKB;

        ln_kernel<<<MROWS, 256>>>(Q, nullptr, Hch, Hcl,
                                  n1_s + k * DD, n1_b + k * DD, X);

        mma_proj<<<gP, 256, SM_G128>>>(Hch, Hcl, k);

        attn_fused<<<gAT, 256, ATT_SMEM>>>(PQh, PQl, PKh, PKl, Vh, Vl, mbh, mbl);

        mma_wo<<<gO64, 256, SM_G64>>>(mbh, mbl, k, Qi, Q, dt);

        ln_kernel<<<MROWS, 256>>>(Qi, nullptr, Q2h, Q2l,
                                  n2_s + k * DD, n2_b + k * DD, nullptr);
        mma_up<<<gUP, 256, SM_G128>>>(Q2h, Q2l, k, Hf);    // fused swiglu
        int tot = MROWS * INNER;
        conv_kernel<<<(tot + 255) / 256, 256>>>(Hf, dw_w + (size_t)k * INNER * CKW,
                                                dw_b + (size_t)k * INNER, Hvh, Hvl);
        mma_down<<<gO64, 256, SM_G64>>>(Hvh, Hvl, k, Q, Qi);
    }

    ln_kernel<<<MROWS, 256>>>(Q, Qn, Qnh, Qnl, fin_s, fin_b, nullptr);
    dim3 gLM(VV / 128, MROWS / 256);          // (250, 8)
    lm_head_mma<<<gLM, 512, SM_LM>>>(Qnh, Qnl, out);
    halt_kernel<<<BB, 256>>>(Qn, halt_w, halt_b, out + (size_t)MROWS * VV);
}

// round 13
// speedup vs baseline: 1.0191x; 1.0191x over previous
#include <cuda_runtime.h>
#include <cuda_bf16.h>
#include <cuda_fp16.h>
#include <math.h>
#include <stdint.h>

// Problem constants
#define BB    2
#define NN    1024
#define DD    512
#define HH    8
#define DH    64
#define KKB   4
#define VV    32000
#define INNER 1536
#define CKW   3
#define MROWS (BB*NN)     // 2048
#define BHN   (BB*HH)     // 16
#define TOTAL_PASSES 8

#define AMS  40    // A smem stride (16-bit elems): 32 data + 8 pad
#define QS   72    // attention smem stride (64 + 8)

typedef __nv_bfloat16 bf16;
typedef __half h16;

// ---------------- fp32 scratch ----------------------------------------------
__device__ __align__(16) float g_X  [MROWS*DD];
__device__ __align__(16) float g_Q  [MROWS*DD];
__device__ __align__(16) float g_Qi [MROWS*DD];
__device__ __align__(16) float g_Qn [MROWS*DD];
__device__ __align__(16) float g_Hf [(size_t)MROWS*INNER];

// ---------------- activation scratch -----------------------------------------
__device__ __align__(16) h16 g_Hch [MROWS*DD], g_Hcl [MROWS*DD];
__device__ __align__(16) h16 g_mbh [MROWS*DD], g_mbl [MROWS*DD];
__device__ __align__(16) h16 g_Q2h [MROWS*DD], g_Q2l [MROWS*DD];
__device__ __align__(16) h16 g_Hvh [(size_t)MROWS*INNER], g_Hvl [(size_t)MROWS*INNER];
__device__ __align__(16) h16 g_Qnh [MROWS*DD], g_Qnl [MROWS*DD];
__device__ __align__(16) bf16 g_PQh [MROWS*DD], g_PQl [MROWS*DD];
__device__ __align__(16) bf16 g_PKh [MROWS*DD], g_PKl [MROWS*DD];
__device__ __align__(16) bf16 g_Vh  [MROWS*DD], g_Vl  [MROWS*DD];

// ---------------- single-fp16 weight scratch ---------------------------------
__device__ __align__(16) h16 g_WQh [KKB*DD*DD];
__device__ __align__(16) h16 g_WKh [KKB*DD*DD];
__device__ __align__(16) h16 g_WVh [KKB*DD*DD];
__device__ __align__(16) h16 g_WOh [KKB*DD*DD];
__device__ __align__(16) h16 g_WUh [(size_t)KKB*DD*2*INNER];
__device__ __align__(16) h16 g_WDh [(size_t)KKB*INNER*DD];
__device__ __align__(16) h16 g_LMh [(size_t)VV*DD];

// ---------------- helpers ----------------------------------------------------
__device__ __forceinline__ float siluf(float x) { return x / (1.0f + expf(-x)); }

__device__ __forceinline__ bool read_halted(const void* p, int b)
{
    const unsigned char* u8 = (const unsigned char*)p;
    if (u8[1] != 0) return u8[b] != 0;
    return ((const int*)p)[b] != 0;
}
__device__ __forceinline__ uint32_t smem_u32(const void* p) {
    uint32_t a;
    asm("{ .reg .u64 t; cvta.to.shared.u64 t, %1; cvt.u32.u64 %0, t; }"
        : "=r"(a) : "l"(p));
    return a;
}
__device__ __forceinline__ void ldm4(uint32_t* r, uint32_t a) {
    asm volatile("ldmatrix.sync.aligned.m8n8.x4.shared.b16 {%0,%1,%2,%3}, [%4];"
                 : "=r"(r[0]), "=r"(r[1]), "=r"(r[2]), "=r"(r[3]) : "r"(a));
}
__device__ __forceinline__ void ldm4t(uint32_t* r, uint32_t a) {
    asm volatile("ldmatrix.sync.aligned.m8n8.x4.trans.shared.b16 {%0,%1,%2,%3}, [%4];"
                 : "=r"(r[0]), "=r"(r[1]), "=r"(r[2]), "=r"(r[3]) : "r"(a));
}
__device__ __forceinline__ void mma_bf16(float* c, const uint32_t* a, const uint32_t* b) {
    asm volatile("mma.sync.aligned.m16n8k16.row.col.f32.bf16.bf16.f32 "
                 "{%0,%1,%2,%3}, {%4,%5,%6,%7}, {%8,%9}, {%0,%1,%2,%3};"
                 : "+f"(c[0]), "+f"(c[1]), "+f"(c[2]), "+f"(c[3])
                 : "r"(a[0]), "r"(a[1]), "r"(a[2]), "r"(a[3]),
                   "r"(b[0]), "r"(b[1]));
}
__device__ __forceinline__ void mma_f16(float* c, const uint32_t* a, const uint32_t* b) {
    asm volatile("mma.sync.aligned.m16n8k16.row.col.f32.f16.f16.f32 "
                 "{%0,%1,%2,%3}, {%4,%5,%6,%7}, {%8,%9}, {%0,%1,%2,%3};"
                 : "+f"(c[0]), "+f"(c[1]), "+f"(c[2]), "+f"(c[3])
                 : "r"(a[0]), "r"(a[1]), "r"(a[2]), "r"(a[3]),
                   "r"(b[0]), "r"(b[1]));
}
__device__ __forceinline__ uint32_t pack2(bf16 a, bf16 b) {
    return (uint32_t)__bfloat16_as_ushort(a) |
           ((uint32_t)__bfloat16_as_ushort(b) << 16);
}
__device__ __forceinline__ uint32_t pack2h(h16 a, h16 b) {
    return (uint32_t)__half_as_ushort(a) |
           ((uint32_t)__half_as_ushort(b) << 16);
}
__device__ __forceinline__ void split1(float v, bf16& h, bf16& l) {
    h = __float2bfloat16(v);
    l = __float2bfloat16(v - __bfloat162float(h));
}
__device__ __forceinline__ void split1h(float v, h16& h, h16& l) {
    h = __float2half_rn(v);
    l = __float2half_rn(v - __half2float(h));
}
__device__ __forceinline__ void cpa16(uint32_t s, const void* g) {
    asm volatile("cp.async.cg.shared.global [%0], [%1], 16;" :: "r"(s), "l"(g));
}
#define CP_COMMIT() asm volatile("cp.async.commit_group;" ::: "memory")
#define CP_WAIT0()  asm volatile("cp.async.wait_group 0;" ::: "memory")
#define CP_WAIT1()  asm volatile("cp.async.wait_group 1;" ::: "memory")

// ---------------- converters --------------------------------------------------
__global__ void cvt_h_kernel(const float* __restrict__ src, h16* __restrict__ d, int n4)
{
    int i = blockIdx.x * 256 + threadIdx.x;
    if (i >= n4) return;
    float4 v = *(const float4*)(src + (size_t)i * 4);
    uint2 o;
    o.x = pack2h(__float2half_rn(v.x), __float2half_rn(v.y));
    o.y = pack2h(__float2half_rn(v.z), __float2half_rn(v.w));
    *(uint2*)(d + (size_t)i * 4) = o;
}

__global__ void cvt_up_kernel(const float* __restrict__ src, h16* __restrict__ d)
{
    int gi = blockIdx.x * 256 + threadIdx.x;
    int total = KKB * DD * (2 * INNER) / 8;
    if (gi >= total) return;
    int cg8 = gi % (2 * INNER / 8);
    int row = gi / (2 * INNER / 8);
    int cg = cg8 * 4;
    size_t rb = (size_t)row * (2 * INNER);
    float4 gsrc = *(const float4*)(src + rb + cg);
    float4 usrc = *(const float4*)(src + rb + INNER + cg);
    float gv[4] = {gsrc.x, gsrc.y, gsrc.z, gsrc.w};
    float uv[4] = {usrc.x, usrc.y, usrc.z, usrc.w};
    uint32_t w[4];
    #pragma unroll
    for (int q = 0; q < 4; q++)
        w[q] = pack2h(__float2half_rn(gv[q]), __float2half_rn(uv[q]));
    size_t db = rb + (size_t)cg8 * 8;
    *(uint4*)(d + db) = make_uint4(w[0], w[1], w[2], w[3]);
}

// ---------------- 2-stage pipelined fp16x2 GEMM body -------------------------
// A: fp16 hi/lo [M,K]; B: single fp16 [K,N] (trans ldmatrix).
// smem layout: [Ah s0 | Ah s1 | Al s0 | Al s1 | B s0 | B s1]
template <int BN>
__device__ __forceinline__ void stage_gemm(
    uint32_t base, int st, int kc, int tid, int m0, int n0,
    const h16* __restrict__ Ah, const h16* __restrict__ Al, int lda,
    const h16* __restrict__ B, int ldb)
{
    constexpr int BNS_ = (BN == 128) ? 136 : 72;
    constexpr uint32_t ASZ = 128 * AMS, BSZ = 32 * BNS_;
    const uint32_t oAh = 0, oAl = 2 * ASZ * 2, oB = 4 * ASZ * 2;
    #pragma unroll
    for (int it2 = 0; it2 < 2; it2++) {
        int g = tid + 256 * it2;
        int row = g >> 2, c8 = (g & 3) * 8;
        size_t go = (size_t)(m0 + row) * lda + kc * 32 + c8;
        uint32_t so = (uint32_t)(st * ASZ + row * AMS + c8) * 2;
        cpa16(base + oAh + so, Ah + go);
        cpa16(base + oAl + so, Al + go);
    }
    {
        if (BN == 128) {
            #pragma unroll
            for (int it2 = 0; it2 < 2; it2++) {
                int g = tid + 256 * it2;
                int row = g >> 4, c8 = (g & 15) * 8;
                size_t go = (size_t)(kc * 32 + row) * ldb + n0 + c8;
                uint32_t so = (uint32_t)(st * BSZ + row * BNS_ + c8) * 2;
                cpa16(base + oB + so, B + go);
            }
        } else {
            int g = tid;
            int row = g >> 3, c8 = (g & 7) * 8;
            size_t go = (size_t)(kc * 32 + row) * ldb + n0 + c8;
            uint32_t so = (uint32_t)(st * BSZ + row * BNS_ + c8) * 2;
            cpa16(base + oB + so, B + go);
        }
    }
}

// epi: 0 fp32, 1 bf16 hi/lo elu+1, 2 fp32 addP+alpha*acc, 3 fp32 addP+acc,
//      4 bf16 hi/lo plain, 5 fused swiglu -> fp32 Hf
template <int BN>
__device__ __forceinline__ void gemm_pipe(
    h16* smem,
    const h16* __restrict__ Ah, const h16* __restrict__ Al, int lda,
    const h16* __restrict__ B, int ldb,
    float* __restrict__ Cf, bf16* __restrict__ Ch, bf16* __restrict__ Cl, int ldc,
    int m0, int n0, int kch, int epi, const float* __restrict__ addP, float alpha)
{
    constexpr int BNS_ = (BN == 128) ? 136 : 72;
    constexpr int NJ = BN / 16;
    constexpr uint32_t ASZ = 128 * AMS, BSZ = 32 * BNS_;
    const uint32_t base = smem_u32(smem);
    const uint32_t oAh = 0, oAl = 2 * ASZ * 2, oB = 4 * ASZ * 2;
    const int tid = threadIdx.x, lane = tid & 31, wid = tid >> 5;
    const int warp_m = wid >> 1, warp_n = wid & 1;

    float acc[2][NJ][4];
    #pragma unroll
    for (int i = 0; i < 2; i++)
        #pragma unroll
        for (int j = 0; j < NJ; j++)
            #pragma unroll
            for (int q = 0; q < 4; q++) acc[i][j][q] = 0.0f;

    stage_gemm<BN>(base, 0, 0, tid, m0, n0, Ah, Al, lda, B, ldb);
    CP_COMMIT();

    int st = 0;
    for (int kc = 0; kc < kch; kc++) {
        if (kc + 1 < kch) {
            stage_gemm<BN>(base, st ^ 1, kc + 1, tid, m0, n0, Ah, Al, lda, B, ldb);
            CP_COMMIT();
            CP_WAIT1();
        } else {
            CP_WAIT0();
        }
        __syncthreads();

        #pragma unroll
        for (int s = 0; s < 2; s++) {
            uint32_t ah[2][4], al[2][4], bh[NJ][2];
            #pragma unroll
            for (int i = 0; i < 2; i++) {
                int r  = warp_m * 32 + i * 16 + (lane & 15);
                int kb = s * 16 + ((lane >> 4) << 3);
                uint32_t so = (uint32_t)(st * ASZ + r * AMS + kb) * 2;
                ldm4(ah[i], base + oAh + so);
                ldm4(al[i], base + oAl + so);
            }
            #pragma unroll
            for (int j2 = 0; j2 < NJ / 2; j2++) {
                int kk = s * 16 + (lane & 7) + ((lane >> 3) & 1) * 8;
                int nn = warp_n * (BN / 2) + j2 * 16 + (lane >> 4) * 8;
                uint32_t so = (uint32_t)(st * BSZ + kk * BNS_ + nn) * 2;
                uint32_t q[4];
                ldm4t(q, base + oB + so);
                bh[2*j2][0] = q[0]; bh[2*j2][1] = q[1];
                bh[2*j2+1][0] = q[2]; bh[2*j2+1][1] = q[3];
            }
            #pragma unroll
            for (int i = 0; i < 2; i++)
                #pragma unroll
                for (int j = 0; j < NJ; j++) {
                    mma_f16(acc[i][j], ah[i], bh[j]);
                    mma_f16(acc[i][j], al[i], bh[j]);
                }
        }
        __syncthreads();
        st ^= 1;
    }

    #pragma unroll
    for (int i = 0; i < 2; i++) {
        int m = m0 + warp_m * 32 + i * 16 + (lane >> 2);
        #pragma unroll
        for (int j = 0; j < NJ; j++) {
            int n = n0 + warp_n * (BN / 2) + j * 8 + (lane & 3) * 2;
            float v0 = acc[i][j][0], v1 = acc[i][j][1];
            float v2 = acc[i][j][2], v3 = acc[i][j][3];
            if (epi == 5) {
                int col = n >> 1;
                Cf[(size_t)m * INNER + col]       = siluf(v0) * v1;
                Cf[(size_t)(m + 8) * INNER + col] = siluf(v2) * v3;
                continue;
            }
            size_t i0 = (size_t)m * ldc + n;
            size_t i1 = (size_t)(m + 8) * ldc + n;
            if (epi == 1 || epi == 4) {
                if (epi == 1) {
                    v0 = (v0 > 0.f) ? v0 + 1.f : expf(v0);
                    v1 = (v1 > 0.f) ? v1 + 1.f : expf(v1);
                    v2 = (v2 > 0.f) ? v2 + 1.f : expf(v2);
                    v3 = (v3 > 0.f) ? v3 + 1.f : expf(v3);
                }
                bf16 h0, h1, h2, h3, l0, l1, l2, l3;
                split1(v0, h0, l0); split1(v1, h1, l1);
                split1(v2, h2, l2); split1(v3, h3, l3);
                *(uint32_t*)(Ch + i0) = pack2(h0, h1);
                *(uint32_t*)(Cl + i0) = pack2(l0, l1);
                *(uint32_t*)(Ch + i1) = pack2(h2, h3);
                *(uint32_t*)(Cl + i1) = pack2(l2, l3);
            } else {
                if (epi == 2) {
                    v0 = addP[i0] + alpha * v0; v1 = addP[i0+1] + alpha * v1;
                    v2 = addP[i1] + alpha * v2; v3 = addP[i1+1] + alpha * v3;
                } else if (epi == 3) {
                    v0 += addP[i0]; v1 += addP[i0+1];
                    v2 += addP[i1]; v3 += addP[i1+1];
                }
                *(float2*)(Cf + i0) = make_float2(v0, v1);
                *(float2*)(Cf + i1) = make_float2(v2, v3);
            }
        }
    }
}

#define SM_G128 58368
#define SM_G64  50176
#define SM_LM   102400
#define ATT_SMEM 184320

// ---------------- GEMM wrappers (2 CTAs/SM) -----------------------------------
__global__ void __launch_bounds__(256, 2) mma_proj(
    const h16* __restrict__ Ah, const h16* __restrict__ Al, int kIdx)
{
    extern __shared__ __align__(16) h16 dsm[];
    int z = blockIdx.z;
    size_t wo = (size_t)kIdx * DD * DD;
    const h16* B = (z == 0) ? g_WQh + wo : (z == 1) ? g_WKh + wo : g_WVh + wo;
    bf16* Ch = (z == 0) ? g_PQh : (z == 1) ? g_PKh : g_Vh;
    bf16* Cl = (z == 0) ? g_PQl : (z == 1) ? g_PKl : g_Vl;
    gemm_pipe<128>(dsm, Ah, Al, DD, B, DD,
                   nullptr, Ch, Cl, DD, blockIdx.y * 128, blockIdx.x * 128,
                   DD / 32, (z < 2) ? 1 : 4, nullptr, 0.f);
}

__global__ void __launch_bounds__(256, 2) mma_wo(
    const h16* __restrict__ Ah, const h16* __restrict__ Al, int kIdx,
    float* __restrict__ C, const float* __restrict__ addP,
    const float* __restrict__ dt)
{
    extern __shared__ __align__(16) h16 dsm[];
    size_t wo = (size_t)kIdx * DD * DD;
    float d = dt[kIdx];
    float alpha = (d > 20.0f) ? d : log1pf(expf(d));
    gemm_pipe<64>(dsm, Ah, Al, DD, g_WOh + wo, DD,
                  C, nullptr, nullptr, DD, blockIdx.y * 128, blockIdx.x * 64,
                  DD / 32, 2, addP, alpha);
}

__global__ void __launch_bounds__(256, 2) mma_up(
    const h16* __restrict__ Ah, const h16* __restrict__ Al, int kIdx,
    float* __restrict__ Hf)
{
    extern __shared__ __align__(16) h16 dsm[];
    size_t wo = (size_t)kIdx * DD * 2 * INNER;
    gemm_pipe<128>(dsm, Ah, Al, DD, g_WUh + wo, 2 * INNER,
                   Hf, nullptr, nullptr, 2 * INNER, blockIdx.y * 128, blockIdx.x * 128,
                   DD / 32, 5, nullptr, 0.f);
}

__global__ void __launch_bounds__(256, 2) mma_down(
    const h16* __restrict__ Ah, const h16* __restrict__ Al, int kIdx,
    float* __restrict__ C, const float* __restrict__ addP)
{
    extern __shared__ __align__(16) h16 dsm[];
    size_t wo = (size_t)kIdx * INNER * DD;
    gemm_pipe<64>(dsm, Ah, Al, INNER, g_WDh + wo, DD,
                  C, nullptr, nullptr, DD, blockIdx.y * 128, blockIdx.x * 64,
                  INNER / 32, 3, addP, 0.f);
}

// ---------------- fused flash attention (bf16x3, 2-stage K/V) -----------------
__device__ __forceinline__ void stage_kv(
    uint32_t base, int st, int kt, int tid, size_t rowbase,
    const bf16* __restrict__ PKh, const bf16* __restrict__ PKl,
    const bf16* __restrict__ Vh,  const bf16* __restrict__ Vl)
{
    const uint32_t QSZB = 128 * QS * 2;
    const uint32_t oKh = 2 * QSZB + st * QSZB;
    const uint32_t oKl = 4 * QSZB + st * QSZB;
    const uint32_t oVh = 6 * QSZB + st * QSZB;
    const uint32_t oVl = 8 * QSZB + st * QSZB;
    #pragma unroll
    for (int it2 = 0; it2 < 4; it2++) {
        int g = tid + 256 * it2;
        int row = g >> 3, c8 = (g & 7) * 8;
        size_t go = rowbase + (size_t)(kt * 128 + row) * DD + c8;
        uint32_t so = (uint32_t)(row * QS + c8) * 2;
        cpa16(base + oKh + so, PKh + go);
        cpa16(base + oKl + so, PKl + go);
        cpa16(base + oVh + so, Vh + go);
        cpa16(base + oVl + so, Vl + go);
    }
}

__global__ void __launch_bounds__(256) attn_fused(
    const bf16* __restrict__ PQh, const bf16* __restrict__ PQl,
    const bf16* __restrict__ PKh, const bf16* __restrict__ PKl,
    const bf16* __restrict__ Vh,  const bf16* __restrict__ Vl,
    h16* __restrict__ Mh, h16* __restrict__ Ml)
{
    extern __shared__ __align__(16) bf16 dsmb[];
    const uint32_t base = smem_u32(dsmb);
    const uint32_t QSZB = 128 * QS * 2;

    const int tid = threadIdx.x, lane = tid & 31, w = tid >> 5;
    const int bh = blockIdx.y, b = bh >> 3, h = bh & 7;
    const int q0 = blockIdx.x * 128;
    const size_t rowbase = (size_t)(b * NN) * DD + h * DH;

    #pragma unroll
    for (int it2 = 0; it2 < 4; it2++) {
        int g = tid + 256 * it2;
        int row = g >> 3, c8 = (g & 7) * 8;
        size_t go = rowbase + (size_t)(q0 + row) * DD + c8;
        uint32_t so = (uint32_t)(row * QS + c8) * 2;
        cpa16(base + so, PQh + go);
        cpa16(base + QSZB + so, PQl + go);
    }
    stage_kv(base, 0, 0, tid, rowbase, PKh, PKl, Vh, Vl);
    CP_COMMIT();
    CP_WAIT0();
    __syncthreads();

    uint32_t qh[4][4], ql[4][4];
    #pragma unroll
    for (int s = 0; s < 4; s++) {
        int r  = w * 16 + (lane & 15);
        int kb = s * 16 + ((lane >> 4) << 3);
        uint32_t so = (uint32_t)(r * QS + kb) * 2;
        ldm4(qh[s], base + so);
        ldm4(ql[s], base + QSZB + so);
    }

    float oacc[8][4];
    #pragma unroll
    for (int j = 0; j < 8; j++)
        #pragma unroll
        for (int q = 0; q < 4; q++) oacc[j][q] = 0.0f;
    float p0 = 0.0f, p1 = 0.0f;

    int st = 0;
    for (int kt = 0; kt < NN / 128; kt++) {
        if (kt + 1 < NN / 128) {
            stage_kv(base, st ^ 1, kt + 1, tid, rowbase, PKh, PKl, Vh, Vl);
            CP_COMMIT();
            CP_WAIT1();
        } else {
            CP_WAIT0();
        }
        __syncthreads();

        const uint32_t oKh = 2 * QSZB + st * QSZB;
        const uint32_t oKl = 4 * QSZB + st * QSZB;
        const uint32_t oVh = 6 * QSZB + st * QSZB;
        const uint32_t oVl = 8 * QSZB + st * QSZB;

        #pragma unroll
        for (int t = 0; t < 8; t++) {
            float sacc[2][4] = {};
            #pragma unroll
            for (int s = 0; s < 4; s++) {
                int r  = t * 16 + (lane & 7) + ((lane >> 4) << 3);
                int kb = s * 16 + (((lane >> 3) & 1) << 3);
                uint32_t so = (uint32_t)(r * QS + kb) * 2;
                uint32_t kh[4], kl[4];
                ldm4(kh, base + oKh + so);
                ldm4(kl, base + oKl + so);
                mma_bf16(sacc[0], qh[s], kh + 0);
                mma_bf16(sacc[0], ql[s], kh + 0);
                mma_bf16(sacc[0], qh[s], kl + 0);
                mma_bf16(sacc[1], qh[s], kh + 2);
                mma_bf16(sacc[1], ql[s], kh + 2);
                mma_bf16(sacc[1], qh[s], kl + 2);
            }
            float w2[2][4];
            #pragma unroll
            for (int f = 0; f < 2; f++)
                #pragma unroll
                for (int q = 0; q < 4; q++) {
                    float x = fmaxf(sacc[f][q], 0.0f);
                    w2[f][q] = x * x;
                }
            p0 += w2[0][0] + w2[0][1] + w2[1][0] + w2[1][1];
            p1 += w2[0][2] + w2[0][3] + w2[1][2] + w2[1][3];
            uint32_t wh[4], wl[4];
            {
                bf16 h0, h1, l0, l1;
                split1(w2[0][0], h0, l0); split1(w2[0][1], h1, l1);
                wh[0] = pack2(h0, h1); wl[0] = pack2(l0, l1);
                split1(w2[0][2], h0, l0); split1(w2[0][3], h1, l1);
                wh[1] = pack2(h0, h1); wl[1] = pack2(l0, l1);
                split1(w2[1][0], h0, l0); split1(w2[1][1], h1, l1);
                wh[2] = pack2(h0, h1); wl[2] = pack2(l0, l1);
                split1(w2[1][2], h0, l0); split1(w2[1][3], h1, l1);
                wh[3] = pack2(h0, h1); wl[3] = pack2(l0, l1);
            }
            #pragma unroll
            for (int n = 0; n < 4; n++) {
                int kk = t * 16 + (lane & 7) + ((lane >> 3) & 1) * 8;
                int nn = n * 16 + (lane >> 4) * 8;
                uint32_t so = (uint32_t)(kk * QS + nn) * 2;
                uint32_t vh[4], vl[4];
                ldm4t(vh, base + oVh + so);
                ldm4t(vl, base + oVl + so);
                mma_bf16(oacc[2*n],   wh, vh + 0);
                mma_bf16(oacc[2*n],   wl, vh + 0);
                mma_bf16(oacc[2*n],   wh, vl + 0);
                mma_bf16(oacc[2*n+1], wh, vh + 2);
                mma_bf16(oacc[2*n+1], wl, vh + 2);
                mma_bf16(oacc[2*n+1], wh, vl + 2);
            }
        }
        __syncthreads();
        st ^= 1;
    }

    p0 += __shfl_xor_sync(0xFFFFFFFFu, p0, 1);
    p0 += __shfl_xor_sync(0xFFFFFFFFu, p0, 2);
    p1 += __shfl_xor_sync(0xFFFFFFFFu, p1, 1);
    p1 += __shfl_xor_sync(0xFFFFFFFFu, p1, 2);
    float rd0 = 1.0f / (p0 + 1.0f);
    float rd1 = 1.0f / (p1 + 1.0f);

    int r0 = q0 + w * 16 + (lane >> 2);
    int r1 = r0 + 8;
    #pragma unroll
    for (int j = 0; j < 8; j++) {
        int d = j * 8 + (lane & 3) * 2;
        size_t i0 = rowbase + (size_t)r0 * DD + d;
        size_t i1 = rowbase + (size_t)r1 * DD + d;
        uint32_t vh0 = *(const uint32_t*)(Vh + i0), vl0 = *(const uint32_t*)(Vl + i0);
        uint32_t vh1 = *(const uint32_t*)(Vh + i1), vl1 = *(const uint32_t*)(Vl + i1);
        float vp00 = __bfloat162float(__ushort_as_bfloat16((unsigned short)(vh0 & 0xFFFF))) +
                     __bfloat162float(__ushort_as_bfloat16((unsigned short)(vl0 & 0xFFFF)));
        float vp01 = __bfloat162float(__ushort_as_bfloat16((unsigned short)(vh0 >> 16))) +
                     __bfloat162float(__ushort_as_bfloat16((unsigned short)(vl0 >> 16)));
        float vp10 = __bfloat162float(__ushort_as_bfloat16((unsigned short)(vh1 & 0xFFFF))) +
                     __bfloat162float(__ushort_as_bfloat16((unsigned short)(vl1 & 0xFFFF)));
        float vp11 = __bfloat162float(__ushort_as_bfloat16((unsigned short)(vh1 >> 16))) +
                     __bfloat162float(__ushort_as_bfloat16((unsigned short)(vl1 >> 16)));
        float m00 = oacc[j][0] * rd0 - vp00;
        float m01 = oacc[j][1] * rd0 - vp01;
        float m10 = oacc[j][2] * rd1 - vp10;
        float m11 = oacc[j][3] * rd1 - vp11;
        h16 h0, h1, l0, l1;
        split1h(m00, h0, l0); split1h(m01, h1, l1);
        *(uint32_t*)(Mh + i0) = pack2h(h0, h1);
        *(uint32_t*)(Ml + i0) = pack2h(l0, l1);
        split1h(m10, h0, l0); split1h(m11, h1, l1);
        *(uint32_t*)(Mh + i1) = pack2h(h0, h1);
        *(uint32_t*)(Ml + i1) = pack2h(l0, l1);
    }
}

// ---------------- LM head: 256x128 tiles, 512 threads, fp16x2 -----------------
__device__ __forceinline__ void stage_lm(
    uint32_t base, int st, int kc, int tid, int m0, int n0,
    const h16* __restrict__ Ah, const h16* __restrict__ Al)
{
    constexpr uint32_t ASZ = 256 * AMS, BSZ = 128 * AMS;
    const uint32_t oAh = 0, oAl = 2 * ASZ * 2, oB = 4 * ASZ * 2;
    #pragma unroll
    for (int it2 = 0; it2 < 2; it2++) {
        int g = tid + 512 * it2;
        int row = g >> 2, c8 = (g & 3) * 8;
        uint32_t so = (uint32_t)(st * ASZ + row * AMS + c8) * 2;
        size_t ga = (size_t)(m0 + row) * DD + kc * 32 + c8;
        cpa16(base + oAh + so, Ah + ga);
        cpa16(base + oAl + so, Al + ga);
    }
    {
        int g = tid;
        int row = g >> 2, c8 = (g & 3) * 8;
        uint32_t so = (uint32_t)(st * BSZ + row * AMS + c8) * 2;
        size_t gb = (size_t)(n0 + row) * DD + kc * 32 + c8;
        cpa16(base + oB + so, g_LMh + gb);
    }
}

__global__ void __launch_bounds__(512)
lm_head_mma(const h16* __restrict__ Ah, const h16* __restrict__ Al,
            float* __restrict__ C)
{
    extern __shared__ __align__(16) h16 dsm[];
    constexpr uint32_t ASZ = 256 * AMS, BSZ = 128 * AMS;
    const uint32_t base = smem_u32(dsm);
    const uint32_t oAh = 0, oAl = 2 * ASZ * 2, oB = 4 * ASZ * 2;
    const int tid = threadIdx.x, lane = tid & 31, wid = tid >> 5;
    const int warp_m = wid >> 1, warp_n = wid & 1;
    const int m0 = blockIdx.y * 256, n0 = blockIdx.x * 128;

    float acc[2][8][4];
    #pragma unroll
    for (int i = 0; i < 2; i++)
        #pragma unroll
        for (int j = 0; j < 8; j++)
            #pragma unroll
            for (int q = 0; q < 4; q++) acc[i][j][q] = 0.0f;

    stage_lm(base, 0, 0, tid, m0, n0, Ah, Al);
    CP_COMMIT();

    int st = 0;
    for (int kc = 0; kc < 16; kc++) {
        if (kc + 1 < 16) {
            stage_lm(base, st ^ 1, kc + 1, tid, m0, n0, Ah, Al);
            CP_COMMIT();
            CP_WAIT1();
        } else {
            CP_WAIT0();
        }
        __syncthreads();

        #pragma unroll
        for (int s = 0; s < 2; s++) {
            uint32_t ah[2][4], al[2][4], bh[8][2];
            #pragma unroll
            for (int i = 0; i < 2; i++) {
                int r  = warp_m * 32 + i * 16 + (lane & 15);
                int kb = s * 16 + ((lane >> 4) << 3);
                uint32_t so = (uint32_t)(st * ASZ + r * AMS + kb) * 2;
                ldm4(ah[i], base + oAh + so);
                ldm4(al[i], base + oAl + so);
            }
            #pragma unroll
            for (int j = 0; j < 4; j++) {
                int r  = warp_n * 64 + j * 16 + (lane & 7) + ((lane >> 4) << 3);
                int kb = s * 16 + (((lane >> 3) & 1) << 3);
                uint32_t so = (uint32_t)(st * BSZ + r * AMS + kb) * 2;
                uint32_t q[4];
                ldm4(q, base + oB + so);
                bh[2*j][0] = q[0]; bh[2*j][1] = q[1];
                bh[2*j+1][0] = q[2]; bh[2*j+1][1] = q[3];
            }
            #pragma unroll
            for (int i = 0; i < 2; i++)
                #pragma unroll
                for (int j = 0; j < 8; j++) {
                    mma_f16(acc[i][j], ah[i], bh[j]);
                    mma_f16(acc[i][j], al[i], bh[j]);
                }
        }
        __syncthreads();
        st ^= 1;
    }

    #pragma unroll
    for (int i = 0; i < 2; i++) {
        int m = m0 + warp_m * 32 + i * 16 + (lane >> 2);
        #pragma unroll
        for (int j = 0; j < 8; j++) {
            int n = n0 + warp_n * 64 + j * 8 + (lane & 3) * 2;
            *(float2*)(C + (size_t)m * VV + n) =
                make_float2(acc[i][j][0], acc[i][j][1]);
            *(float2*)(C + (size_t)(m + 8) * VV + n) =
                make_float2(acc[i][j][2], acc[i][j][3]);
        }
    }
}

// ---------------- init -------------------------------------------------------
__global__ void init_kernel(const int* __restrict__ inputs,
                            const int* __restrict__ carry_inputs,
                            const void* __restrict__ halted,
                            const float* __restrict__ carry_hidden,
                            const float* __restrict__ init_hidden,
                            const float* __restrict__ emb,
                            const float* __restrict__ pos,
                            const float* __restrict__ in_s,
                            const float* __restrict__ in_b)
{
    int r = blockIdx.x;
    int b = r / NN, n = r % NN;
    int t = threadIdx.x;
    bool h = read_halted(halted, b);
    int idx = h ? inputs[r] : carry_inputs[r];
    const float* e = emb + (size_t)idx * DD;
    const float* p = pos + (size_t)n * DD;

    float x0 = e[t]       + p[t];
    float x1 = e[t + 256] + p[t + 256];

    size_t base = (size_t)r * DD;
    g_Q[base + t]       = h ? init_hidden[t]       : carry_hidden[base + t];
    g_Q[base + t + 256] = h ? init_hidden[t + 256] : carry_hidden[base + t + 256];

    __shared__ float s_sum[256], s_sq[256];
    s_sum[t] = x0 + x1;
    s_sq[t]  = x0 * x0 + x1 * x1;
    __syncthreads();
    for (int o = 128; o > 0; o >>= 1) {
        if (t < o) { s_sum[t] += s_sum[t + o]; s_sq[t] += s_sq[t + o]; }
        __syncthreads();
    }
    float mu   = s_sum[0] * (1.0f / DD);
    float var  = s_sq[0] * (1.0f / DD) - mu * mu;
    float rstd = rsqrtf(var + 1e-5f);
    g_X[base + t]       = (x0 - mu) * rstd * in_s[t]       + in_b[t];
    g_X[base + t + 256] = (x1 - mu) * rstd * in_s[t + 256] + in_b[t + 256];
}

// ---------------- LayerNorm (fp32 in; optional fp32 out; fp16 hi/lo out) -----
__global__ void ln_kernel(const float* __restrict__ in, float* __restrict__ outf,
                          h16* __restrict__ outh, h16* __restrict__ outl,
                          const float* __restrict__ s, const float* __restrict__ bia,
                          const float* __restrict__ add)
{
    int r = blockIdx.x;
    int t = threadIdx.x;
    size_t base = (size_t)r * DD;
    float x0 = in[base + t];
    float x1 = in[base + t + 256];

    __shared__ float s_sum[256], s_sq[256];
    s_sum[t] = x0 + x1;
    s_sq[t]  = x0 * x0 + x1 * x1;
    __syncthreads();
    for (int o = 128; o > 0; o >>= 1) {
        if (t < o) { s_sum[t] += s_sum[t + o]; s_sq[t] += s_sq[t + o]; }
        __syncthreads();
    }
    float mu   = s_sum[0] * (1.0f / DD);
    float var  = s_sq[0] * (1.0f / DD) - mu * mu;
    float rstd = rsqrtf(var + 1e-5f);
    float v0 = (x0 - mu) * rstd * s[t]       + bia[t];
    float v1 = (x1 - mu) * rstd * s[t + 256] + bia[t + 256];
    if (add) { v0 += add[base + t]; v1 += add[base + t + 256]; }
    if (outf) { outf[base + t] = v0; outf[base + t + 256] = v1; }
    if (outh) {
        h16 h0, l0, h1, l1;
        split1h(v0, h0, l0); split1h(v1, h1, l1);
        outh[base + t] = h0;       outl[base + t] = l0;
        outh[base + t + 256] = h1; outl[base + t + 256] = l1;
    }
}

// ---------------- depthwise conv k=3 + bias + silu -> fp16 hi/lo --------------
__global__ void conv_kernel(const float* __restrict__ Hf, const float* __restrict__ w,
                            const float* __restrict__ bias,
                            h16* __restrict__ outh, h16* __restrict__ outl)
{
    size_t i = (size_t)blockIdx.x * 256 + threadIdx.x;
    if (i >= (size_t)MROWS * INNER) return;
    size_t row = i / INNER;
    int c = (int)(i % INNER);
    int n = (int)(row % NN);
    const float* wc = w + (size_t)c * CKW;
    float acc = bias[c];
    if (n > 0)      acc += wc[0] * Hf[(row - 1) * INNER + c];
    acc += wc[1] * Hf[row * INNER + c];
    if (n < NN - 1) acc += wc[2] * Hf[(row + 1) * INNER + c];
    float v = siluf(acc);
    h16 h, l;
    split1h(v, h, l);
    outh[i] = h;
    outl[i] = l;
}

// ---------------- halt head --------------------------------------------------
__global__ void halt_kernel(const float* __restrict__ Qn, const float* __restrict__ hw,
                            const float* __restrict__ hb, float* __restrict__ out)
{
    int b = blockIdx.x;
    int t = threadIdx.x;
    __shared__ float md[DD];
    for (int d = t; d < DD; d += 256) {
        float s = 0.0f;
        for (int n = 0; n < NN; n++)
            s += Qn[((size_t)(b * NN + n)) * DD + d];
        md[d] = s * (1.0f / NN);
    }
    __syncthreads();
    __shared__ float r0[256], r1[256];
    float p0 = 0.0f, p1 = 0.0f;
    for (int d = t; d < DD; d += 256) {
        p0 += md[d] * hw[d];
        p1 += md[d] * hw[DD + d];
    }
    r0[t] = p0; r1[t] = p1;
    __syncthreads();
    for (int o = 128; o > 0; o >>= 1) {
        if (t < o) { r0[t] += r0[t + o]; r1[t] += r1[t + o]; }
        __syncthreads();
    }
    if (t == 0) {
        out[b * 2 + 0] = r0[0] + hb[0];
        out[b * 2 + 1] = r1[0] + hb[1];
    }
}

// ---------------- host orchestration -----------------------------------------
static void cvt_h(const float* src, h16* d, size_t n)
{
    int n4 = (int)(n / 4);
    cvt_h_kernel<<<(n4 + 255) / 256, 256>>>(src, d, n4);
}

extern "C" void kernel_launch(void* const* d_in, const int* in_sizes, int n_in,
                              void* d_out, int out_size)
{
    const int*   inputs       = (const int*)d_in[0];
    const float* carry_hidden = (const float*)d_in[2];
    const void*  halted       = d_in[4];
    const int*   carry_inputs = (const int*)d_in[5];
    const float* init_hidden  = (const float*)d_in[7];
    const float* emb          = (const float*)d_in[8];
    const float* pos          = (const float*)d_in[9];
    const float* in_s         = (const float*)d_in[10];
    const float* in_b         = (const float*)d_in[11];
    const float* fin_s        = (const float*)d_in[12];
    const float* fin_b        = (const float*)d_in[13];
    const float* lm_w         = (const float*)d_in[14];
    const float* halt_w       = (const float*)d_in[15];
    const float* halt_b       = (const float*)d_in[16];
    const float* dt           = (const float*)d_in[17];
    const float* W_Q          = (const float*)d_in[18];
    const float* W_K          = (const float*)d_in[19];
    const float* W_V          = (const float*)d_in[20];
    const float* W_O          = (const float*)d_in[21];
    const float* W_up         = (const float*)d_in[22];
    const float* dw_w         = (const float*)d_in[23];
    const float* dw_b         = (const float*)d_in[24];
    const float* W_down       = (const float*)d_in[25];
    const float* n1_s         = (const float*)d_in[26];
    const float* n1_b         = (const float*)d_in[27];
    const float* n2_s         = (const float*)d_in[28];
    const float* n2_b         = (const float*)d_in[29];

    float *X, *Q, *Qi, *Qn, *Hf;
    h16 *Hch, *Hcl, *mbh, *mbl, *Q2h, *Q2l, *Hvh, *Hvl, *Qnh, *Qnl;
    bf16 *PQh, *PQl, *PKh, *PKl, *Vh, *Vl;
    h16 *WQh, *WKh, *WVh, *WOh, *WUh, *WDh, *LMh;
    cudaGetSymbolAddress((void**)&X,   g_X);
    cudaGetSymbolAddress((void**)&Q,   g_Q);
    cudaGetSymbolAddress((void**)&Qi,  g_Qi);
    cudaGetSymbolAddress((void**)&Qn,  g_Qn);
    cudaGetSymbolAddress((void**)&Hf,  g_Hf);
    cudaGetSymbolAddress((void**)&Hch, g_Hch); cudaGetSymbolAddress((void**)&Hcl, g_Hcl);
    cudaGetSymbolAddress((void**)&PQh, g_PQh); cudaGetSymbolAddress((void**)&PQl, g_PQl);
    cudaGetSymbolAddress((void**)&PKh, g_PKh); cudaGetSymbolAddress((void**)&PKl, g_PKl);
    cudaGetSymbolAddress((void**)&Vh,  g_Vh);  cudaGetSymbolAddress((void**)&Vl,  g_Vl);
    cudaGetSymbolAddress((void**)&mbh, g_mbh); cudaGetSymbolAddress((void**)&mbl, g_mbl);
    cudaGetSymbolAddress((void**)&Q2h, g_Q2h); cudaGetSymbolAddress((void**)&Q2l, g_Q2l);
    cudaGetSymbolAddress((void**)&Hvh, g_Hvh); cudaGetSymbolAddress((void**)&Hvl, g_Hvl);
    cudaGetSymbolAddress((void**)&Qnh, g_Qnh); cudaGetSymbolAddress((void**)&Qnl, g_Qnl);
    cudaGetSymbolAddress((void**)&WQh, g_WQh);
    cudaGetSymbolAddress((void**)&WKh, g_WKh);
    cudaGetSymbolAddress((void**)&WVh, g_WVh);
    cudaGetSymbolAddress((void**)&WOh, g_WOh);
    cudaGetSymbolAddress((void**)&WUh, g_WUh);
    cudaGetSymbolAddress((void**)&WDh, g_WDh);
    cudaGetSymbolAddress((void**)&LMh, g_LMh);

    float* out = (float*)d_out;

    cudaFuncSetAttribute(attn_fused, cudaFuncAttributeMaxDynamicSharedMemorySize, ATT_SMEM);
    cudaFuncSetAttribute(mma_proj,   cudaFuncAttributeMaxDynamicSharedMemorySize, SM_G128);
    cudaFuncSetAttribute(mma_up,     cudaFuncAttributeMaxDynamicSharedMemorySize, SM_G128);
    cudaFuncSetAttribute(mma_wo,     cudaFuncAttributeMaxDynamicSharedMemorySize, SM_G64);
    cudaFuncSetAttribute(mma_down,   cudaFuncAttributeMaxDynamicSharedMemorySize, SM_G64);
    cudaFuncSetAttribute(lm_head_mma, cudaFuncAttributeMaxDynamicSharedMemorySize, SM_LM);

    cvt_h(W_Q,    WQh, (size_t)KKB * DD * DD);
    cvt_h(W_K,    WKh, (size_t)KKB * DD * DD);
    cvt_h(W_V,    WVh, (size_t)KKB * DD * DD);
    cvt_h(W_O,    WOh, (size_t)KKB * DD * DD);
    {
        int total = KKB * DD * (2 * INNER) / 8;
        cvt_up_kernel<<<(total + 255) / 256, 256>>>(W_up, WUh);
    }
    cvt_h(W_down, WDh, (size_t)KKB * INNER * DD);
    cvt_h(lm_w,   LMh, (size_t)VV * DD);

    init_kernel<<<MROWS, 256>>>(inputs, carry_inputs, halted, carry_hidden,
                                init_hidden, emb, pos, in_s, in_b);

    dim3 gP(DD / 128, MROWS / 128, 3);        // (4, 16, 3)
    dim3 gO64(DD / 64, MROWS / 128);          // (8, 16) = 128 CTAs
    dim3 gUP(2 * INNER / 128, MROWS / 128);   // (24, 16)
    dim3 gAT(NN / 128, BHN);                  // (8, 16)

    for (int it = 0; it < TOTAL_PASSES; it++) {
        int k = it % KKB;

        ln_kernel<<<MROWS, 256>>>(Q, nullptr, Hch, Hcl,
                                  n1_s + k * DD, n1_b + k * DD, X);

        mma_proj<<<gP, 256, SM_G128>>>(Hch, Hcl, k);

        attn_fused<<<gAT, 256, ATT_SMEM>>>(PQh, PQl, PKh, PKl, Vh, Vl, mbh, mbl);

        mma_wo<<<gO64, 256, SM_G64>>>(mbh, mbl, k, Qi, Q, dt);

        ln_kernel<<<MROWS, 256>>>(Qi, nullptr, Q2h, Q2l,
                                  n2_s + k * DD, n2_b + k * DD, nullptr);
        mma_up<<<gUP, 256, SM_G128>>>(Q2h, Q2l, k, Hf);    // fused swiglu
        int tot = MROWS * INNER;
        conv_kernel<<<(tot + 255) / 256, 256>>>(Hf, dw_w + (size_t)k * INNER * CKW,
                                                dw_b + (size_t)k * INNER, Hvh, Hvl);
        mma_down<<<gO64, 256, SM_G64>>>(Hvh, Hvl, k, Q, Qi);
    }

    ln_kernel<<<MROWS, 256>>>(Q, Qn, Qnh, Qnl, fin_s, fin_b, nullptr);
    dim3 gLM(VV / 128, MROWS / 256);          // (250, 8)
    lm_head_mma<<<gLM, 512, SM_LM>>>(Qnh, Qnl, out);
    halt_kernel<<<BB, 256>>>(Qn, halt_w, halt_b, out + (size_t)MROWS * VV);
}

// round 14
// speedup vs baseline: 1.0659x; 1.0459x over previous
#include <cuda_runtime.h>
#include <cuda_bf16.h>
#include <cuda_fp16.h>
#include <math.h>
#include <stdint.h>

// Problem constants
#define BB    2
#define NN    1024
#define DD    512
#define HH    8
#define DH    64
#define KKB   4
#define VV    32000
#define INNER 1536
#define CKW   3
#define MROWS (BB*NN)     // 2048
#define BHN   (BB*HH)     // 16
#define TOTAL_PASSES 8

#define AMS  40    // A smem stride (16-bit elems): 32 data + 8 pad
#define QS   72    // attention smem stride (64 + 8)

typedef __nv_bfloat16 bf16;
typedef __half h16;

// ---------------- fp32 scratch ----------------------------------------------
__device__ __align__(16) float g_X  [MROWS*DD];
__device__ __align__(16) float g_Q  [MROWS*DD];
__device__ __align__(16) float g_Qi [MROWS*DD];
__device__ __align__(16) float g_Qn [MROWS*DD];
__device__ __align__(16) float g_Hf [(size_t)MROWS*INNER];

// ---------------- activation scratch -----------------------------------------
__device__ __align__(16) h16 g_Hch [MROWS*DD], g_Hcl [MROWS*DD];
__device__ __align__(16) h16 g_mbh [MROWS*DD], g_mbl [MROWS*DD];
__device__ __align__(16) h16 g_Q2h [MROWS*DD], g_Q2l [MROWS*DD];
__device__ __align__(16) h16 g_Hvh [(size_t)MROWS*INNER], g_Hvl [(size_t)MROWS*INNER];
__device__ __align__(16) h16 g_Qnh [MROWS*DD], g_Qnl [MROWS*DD];
__device__ __align__(16) bf16 g_PQh [MROWS*DD], g_PQl [MROWS*DD];
__device__ __align__(16) bf16 g_PKh [MROWS*DD], g_PKl [MROWS*DD];
__device__ __align__(16) bf16 g_Vh  [MROWS*DD], g_Vl  [MROWS*DD];

// ---------------- single-fp16 weight scratch ---------------------------------
__device__ __align__(16) h16 g_WQh [KKB*DD*DD];
__device__ __align__(16) h16 g_WKh [KKB*DD*DD];
__device__ __align__(16) h16 g_WVh [KKB*DD*DD];
__device__ __align__(16) h16 g_WOh [KKB*DD*DD];
__device__ __align__(16) h16 g_WUh [(size_t)KKB*DD*2*INNER];
__device__ __align__(16) h16 g_WDh [(size_t)KKB*INNER*DD];
__device__ __align__(16) h16 g_LMh [(size_t)VV*DD];

// ---------------- helpers ----------------------------------------------------
__device__ __forceinline__ float siluf(float x) { return x / (1.0f + expf(-x)); }

__device__ __forceinline__ bool read_halted(const void* p, int b)
{
    const unsigned char* u8 = (const unsigned char*)p;
    if (u8[1] != 0) return u8[b] != 0;
    return ((const int*)p)[b] != 0;
}
__device__ __forceinline__ uint32_t smem_u32(const void* p) {
    uint32_t a;
    asm("{ .reg .u64 t; cvta.to.shared.u64 t, %1; cvt.u32.u64 %0, t; }"
        : "=r"(a) : "l"(p));
    return a;
}
__device__ __forceinline__ void ldm4(uint32_t* r, uint32_t a) {
    asm volatile("ldmatrix.sync.aligned.m8n8.x4.shared.b16 {%0,%1,%2,%3}, [%4];"
                 : "=r"(r[0]), "=r"(r[1]), "=r"(r[2]), "=r"(r[3]) : "r"(a));
}
__device__ __forceinline__ void ldm4t(uint32_t* r, uint32_t a) {
    asm volatile("ldmatrix.sync.aligned.m8n8.x4.trans.shared.b16 {%0,%1,%2,%3}, [%4];"
                 : "=r"(r[0]), "=r"(r[1]), "=r"(r[2]), "=r"(r[3]) : "r"(a));
}
__device__ __forceinline__ void mma_bf16(float* c, const uint32_t* a, const uint32_t* b) {
    asm volatile("mma.sync.aligned.m16n8k16.row.col.f32.bf16.bf16.f32 "
                 "{%0,%1,%2,%3}, {%4,%5,%6,%7}, {%8,%9}, {%0,%1,%2,%3};"
                 : "+f"(c[0]), "+f"(c[1]), "+f"(c[2]), "+f"(c[3])
                 : "r"(a[0]), "r"(a[1]), "r"(a[2]), "r"(a[3]),
                   "r"(b[0]), "r"(b[1]));
}
__device__ __forceinline__ void mma_f16(float* c, const uint32_t* a, const uint32_t* b) {
    asm volatile("mma.sync.aligned.m16n8k16.row.col.f32.f16.f16.f32 "
                 "{%0,%1,%2,%3}, {%4,%5,%6,%7}, {%8,%9}, {%0,%1,%2,%3};"
                 : "+f"(c[0]), "+f"(c[1]), "+f"(c[2]), "+f"(c[3])
                 : "r"(a[0]), "r"(a[1]), "r"(a[2]), "r"(a[3]),
                   "r"(b[0]), "r"(b[1]));
}
__device__ __forceinline__ uint32_t pack2(bf16 a, bf16 b) {
    return (uint32_t)__bfloat16_as_ushort(a) |
           ((uint32_t)__bfloat16_as_ushort(b) << 16);
}
__device__ __forceinline__ uint32_t pack2h(h16 a, h16 b) {
    return (uint32_t)__half_as_ushort(a) |
           ((uint32_t)__half_as_ushort(b) << 16);
}
__device__ __forceinline__ void split1(float v, bf16& h, bf16& l) {
    h = __float2bfloat16(v);
    l = __float2bfloat16(v - __bfloat162float(h));
}
__device__ __forceinline__ void split1h(float v, h16& h, h16& l) {
    h = __float2half_rn(v);
    l = __float2half_rn(v - __half2float(h));
}
__device__ __forceinline__ void cpa16(uint32_t s, const void* g) {
    asm volatile("cp.async.cg.shared.global [%0], [%1], 16;" :: "r"(s), "l"(g));
}
#define CP_COMMIT() asm volatile("cp.async.commit_group;" ::: "memory")
#define CP_WAIT0()  asm volatile("cp.async.wait_group 0;" ::: "memory")
#define CP_WAIT1()  asm volatile("cp.async.wait_group 1;" ::: "memory")

// ---------------- converters --------------------------------------------------
__global__ void cvt_h_kernel(const float* __restrict__ src, h16* __restrict__ d, int n4)
{
    int i = blockIdx.x * 256 + threadIdx.x;
    if (i >= n4) return;
    float4 v = *(const float4*)(src + (size_t)i * 4);
    uint2 o;
    o.x = pack2h(__float2half_rn(v.x), __float2half_rn(v.y));
    o.y = pack2h(__float2half_rn(v.z), __float2half_rn(v.w));
    *(uint2*)(d + (size_t)i * 4) = o;
}

__global__ void cvt_up_kernel(const float* __restrict__ src, h16* __restrict__ d)
{
    int gi = blockIdx.x * 256 + threadIdx.x;
    int total = KKB * DD * (2 * INNER) / 8;
    if (gi >= total) return;
    int cg8 = gi % (2 * INNER / 8);
    int row = gi / (2 * INNER / 8);
    int cg = cg8 * 4;
    size_t rb = (size_t)row * (2 * INNER);
    float4 gsrc = *(const float4*)(src + rb + cg);
    float4 usrc = *(const float4*)(src + rb + INNER + cg);
    float gv[4] = {gsrc.x, gsrc.y, gsrc.z, gsrc.w};
    float uv[4] = {usrc.x, usrc.y, usrc.z, usrc.w};
    uint32_t w[4];
    #pragma unroll
    for (int q = 0; q < 4; q++)
        w[q] = pack2h(__float2half_rn(gv[q]), __float2half_rn(uv[q]));
    size_t db = rb + (size_t)cg8 * 8;
    *(uint4*)(d + db) = make_uint4(w[0], w[1], w[2], w[3]);
}

// ---------------- 2-stage pipelined fp16x2 GEMM body -------------------------
template <int BN>
__device__ __forceinline__ void stage_gemm(
    uint32_t base, int st, int kc, int tid, int m0, int n0,
    const h16* __restrict__ Ah, const h16* __restrict__ Al, int lda,
    const h16* __restrict__ B, int ldb)
{
    constexpr int BNS_ = (BN == 128) ? 136 : 72;
    constexpr uint32_t ASZ = 128 * AMS, BSZ = 32 * BNS_;
    const uint32_t oAh = 0, oAl = 2 * ASZ * 2, oB = 4 * ASZ * 2;
    #pragma unroll
    for (int it2 = 0; it2 < 2; it2++) {
        int g = tid + 256 * it2;
        int row = g >> 2, c8 = (g & 3) * 8;
        size_t go = (size_t)(m0 + row) * lda + kc * 32 + c8;
        uint32_t so = (uint32_t)(st * ASZ + row * AMS + c8) * 2;
        cpa16(base + oAh + so, Ah + go);
        cpa16(base + oAl + so, Al + go);
    }
    {
        if (BN == 128) {
            #pragma unroll
            for (int it2 = 0; it2 < 2; it2++) {
                int g = tid + 256 * it2;
                int row = g >> 4, c8 = (g & 15) * 8;
                size_t go = (size_t)(kc * 32 + row) * ldb + n0 + c8;
                uint32_t so = (uint32_t)(st * BSZ + row * BNS_ + c8) * 2;
                cpa16(base + oB + so, B + go);
            }
        } else {
            int g = tid;
            int row = g >> 3, c8 = (g & 7) * 8;
            size_t go = (size_t)(kc * 32 + row) * ldb + n0 + c8;
            uint32_t so = (uint32_t)(st * BSZ + row * BNS_ + c8) * 2;
            cpa16(base + oB + so, B + go);
        }
    }
}

// epi: 0 fp32, 1 bf16 hi/lo elu+1, 2 fp32 addP+alpha*acc, 3 fp32 addP+acc,
//      4 bf16 hi/lo plain, 5 fused swiglu -> fp32 Hf
template <int BN>
__device__ __forceinline__ void gemm_pipe(
    h16* smem,
    const h16* __restrict__ Ah, const h16* __restrict__ Al, int lda,
    const h16* __restrict__ B, int ldb,
    float* __restrict__ Cf, bf16* __restrict__ Ch, bf16* __restrict__ Cl, int ldc,
    int m0, int n0, int kch, int epi, const float* __restrict__ addP, float alpha)
{
    constexpr int BNS_ = (BN == 128) ? 136 : 72;
    constexpr int NJ = BN / 16;
    constexpr uint32_t ASZ = 128 * AMS, BSZ = 32 * BNS_;
    const uint32_t base = smem_u32(smem);
    const uint32_t oAh = 0, oAl = 2 * ASZ * 2, oB = 4 * ASZ * 2;
    const int tid = threadIdx.x, lane = tid & 31, wid = tid >> 5;
    const int warp_m = wid >> 1, warp_n = wid & 1;

    float acc[2][NJ][4];
    #pragma unroll
    for (int i = 0; i < 2; i++)
        #pragma unroll
        for (int j = 0; j < NJ; j++)
            #pragma unroll
            for (int q = 0; q < 4; q++) acc[i][j][q] = 0.0f;

    stage_gemm<BN>(base, 0, 0, tid, m0, n0, Ah, Al, lda, B, ldb);
    CP_COMMIT();

    int st = 0;
    for (int kc = 0; kc < kch; kc++) {
        if (kc + 1 < kch) {
            stage_gemm<BN>(base, st ^ 1, kc + 1, tid, m0, n0, Ah, Al, lda, B, ldb);
            CP_COMMIT();
            CP_WAIT1();
        } else {
            CP_WAIT0();
        }
        __syncthreads();

        #pragma unroll
        for (int s = 0; s < 2; s++) {
            uint32_t ah[2][4], al[2][4], bh[NJ][2];
            #pragma unroll
            for (int i = 0; i < 2; i++) {
                int r  = warp_m * 32 + i * 16 + (lane & 15);
                int kb = s * 16 + ((lane >> 4) << 3);
                uint32_t so = (uint32_t)(st * ASZ + r * AMS + kb) * 2;
                ldm4(ah[i], base + oAh + so);
                ldm4(al[i], base + oAl + so);
            }
            #pragma unroll
            for (int j2 = 0; j2 < NJ / 2; j2++) {
                int kk = s * 16 + (lane & 7) + ((lane >> 3) & 1) * 8;
                int nn = warp_n * (BN / 2) + j2 * 16 + (lane >> 4) * 8;
                uint32_t so = (uint32_t)(st * BSZ + kk * BNS_ + nn) * 2;
                uint32_t q[4];
                ldm4t(q, base + oB + so);
                bh[2*j2][0] = q[0]; bh[2*j2][1] = q[1];
                bh[2*j2+1][0] = q[2]; bh[2*j2+1][1] = q[3];
            }
            #pragma unroll
            for (int i = 0; i < 2; i++)
                #pragma unroll
                for (int j = 0; j < NJ; j++) {
                    mma_f16(acc[i][j], ah[i], bh[j]);
                    mma_f16(acc[i][j], al[i], bh[j]);
                }
        }
        __syncthreads();
        st ^= 1;
    }

    #pragma unroll
    for (int i = 0; i < 2; i++) {
        int m = m0 + warp_m * 32 + i * 16 + (lane >> 2);
        #pragma unroll
        for (int j = 0; j < NJ; j++) {
            int n = n0 + warp_n * (BN / 2) + j * 8 + (lane & 3) * 2;
            float v0 = acc[i][j][0], v1 = acc[i][j][1];
            float v2 = acc[i][j][2], v3 = acc[i][j][3];
            if (epi == 5) {
                int col = n >> 1;
                Cf[(size_t)m * INNER + col]       = siluf(v0) * v1;
                Cf[(size_t)(m + 8) * INNER + col] = siluf(v2) * v3;
                continue;
            }
            size_t i0 = (size_t)m * ldc + n;
            size_t i1 = (size_t)(m + 8) * ldc + n;
            if (epi == 1 || epi == 4) {
                if (epi == 1) {
                    v0 = (v0 > 0.f) ? v0 + 1.f : expf(v0);
                    v1 = (v1 > 0.f) ? v1 + 1.f : expf(v1);
                    v2 = (v2 > 0.f) ? v2 + 1.f : expf(v2);
                    v3 = (v3 > 0.f) ? v3 + 1.f : expf(v3);
                }
                bf16 h0, h1, h2, h3, l0, l1, l2, l3;
                split1(v0, h0, l0); split1(v1, h1, l1);
                split1(v2, h2, l2); split1(v3, h3, l3);
                *(uint32_t*)(Ch + i0) = pack2(h0, h1);
                *(uint32_t*)(Cl + i0) = pack2(l0, l1);
                *(uint32_t*)(Ch + i1) = pack2(h2, h3);
                *(uint32_t*)(Cl + i1) = pack2(l2, l3);
            } else {
                if (epi == 2) {
                    v0 = addP[i0] + alpha * v0; v1 = addP[i0+1] + alpha * v1;
                    v2 = addP[i1] + alpha * v2; v3 = addP[i1+1] + alpha * v3;
                } else if (epi == 3) {
                    v0 += addP[i0]; v1 += addP[i0+1];
                    v2 += addP[i1]; v3 += addP[i1+1];
                }
                *(float2*)(Cf + i0) = make_float2(v0, v1);
                *(float2*)(Cf + i1) = make_float2(v2, v3);
            }
        }
    }
}

#define SM_G128 58368
#define SM_G64  50176
#define SM_LM   102400
#define ATT_SMEM 110592   // 6 * 128 * QS * 2  (Qh,Ql + Kh s0/s1 + Vh s0/s1)

// ---------------- GEMM wrappers (2 CTAs/SM) -----------------------------------
__global__ void __launch_bounds__(256, 2) mma_proj(
    const h16* __restrict__ Ah, const h16* __restrict__ Al, int kIdx)
{
    extern __shared__ __align__(16) h16 dsm[];
    int z = blockIdx.z;
    size_t wo = (size_t)kIdx * DD * DD;
    const h16* B = (z == 0) ? g_WQh + wo : (z == 1) ? g_WKh + wo : g_WVh + wo;
    bf16* Ch = (z == 0) ? g_PQh : (z == 1) ? g_PKh : g_Vh;
    bf16* Cl = (z == 0) ? g_PQl : (z == 1) ? g_PKl : g_Vl;
    gemm_pipe<128>(dsm, Ah, Al, DD, B, DD,
                   nullptr, Ch, Cl, DD, blockIdx.y * 128, blockIdx.x * 128,
                   DD / 32, (z < 2) ? 1 : 4, nullptr, 0.f);
}

__global__ void __launch_bounds__(256, 2) mma_wo(
    const h16* __restrict__ Ah, const h16* __restrict__ Al, int kIdx,
    float* __restrict__ C, const float* __restrict__ addP,
    const float* __restrict__ dt)
{
    extern __shared__ __align__(16) h16 dsm[];
    size_t wo = (size_t)kIdx * DD * DD;
    float d = dt[kIdx];
    float alpha = (d > 20.0f) ? d : log1pf(expf(d));
    gemm_pipe<64>(dsm, Ah, Al, DD, g_WOh + wo, DD,
                  C, nullptr, nullptr, DD, blockIdx.y * 128, blockIdx.x * 64,
                  DD / 32, 2, addP, alpha);
}

__global__ void __launch_bounds__(256, 2) mma_up(
    const h16* __restrict__ Ah, const h16* __restrict__ Al, int kIdx,
    float* __restrict__ Hf)
{
    extern __shared__ __align__(16) h16 dsm[];
    size_t wo = (size_t)kIdx * DD * 2 * INNER;
    gemm_pipe<128>(dsm, Ah, Al, DD, g_WUh + wo, 2 * INNER,
                   Hf, nullptr, nullptr, 2 * INNER, blockIdx.y * 128, blockIdx.x * 128,
                   DD / 32, 5, nullptr, 0.f);
}

__global__ void __launch_bounds__(256, 2) mma_down(
    const h16* __restrict__ Ah, const h16* __restrict__ Al, int kIdx,
    float* __restrict__ C, const float* __restrict__ addP)
{
    extern __shared__ __align__(16) h16 dsm[];
    size_t wo = (size_t)kIdx * INNER * DD;
    gemm_pipe<64>(dsm, Ah, Al, INNER, g_WDh + wo, DD,
                  C, nullptr, nullptr, DD, blockIdx.y * 128, blockIdx.x * 64,
                  INNER / 32, 3, addP, 0.f);
}

// ---------------- fused flash attention (2-term: A-lo kept, B-lo dropped) -----
// smem: [Qh | Ql | Kh s0 | Kh s1 | Vh s0 | Vh s1], each 128*QS bf16
__device__ __forceinline__ void stage_kv(
    uint32_t base, int st, int kt, int tid, size_t rowbase,
    const bf16* __restrict__ PKh, const bf16* __restrict__ Vh)
{
    const uint32_t QSZB = 128 * QS * 2;
    const uint32_t oKh = 2 * QSZB + st * QSZB;
    const uint32_t oVh = 4 * QSZB + st * QSZB;
    #pragma unroll
    for (int it2 = 0; it2 < 4; it2++) {
        int g = tid + 256 * it2;
        int row = g >> 3, c8 = (g & 7) * 8;
        size_t go = rowbase + (size_t)(kt * 128 + row) * DD + c8;
        uint32_t so = (uint32_t)(row * QS + c8) * 2;
        cpa16(base + oKh + so, PKh + go);
        cpa16(base + oVh + so, Vh + go);
    }
}

__global__ void __launch_bounds__(256) attn_fused(
    const bf16* __restrict__ PQh, const bf16* __restrict__ PQl,
    const bf16* __restrict__ PKh,
    const bf16* __restrict__ Vh,  const bf16* __restrict__ Vl,
    h16* __restrict__ Mh, h16* __restrict__ Ml)
{
    extern __shared__ __align__(16) bf16 dsmb[];
    const uint32_t base = smem_u32(dsmb);
    const uint32_t QSZB = 128 * QS * 2;

    const int tid = threadIdx.x, lane = tid & 31, w = tid >> 5;
    const int bh = blockIdx.y, b = bh >> 3, h = bh & 7;
    const int q0 = blockIdx.x * 128;
    const size_t rowbase = (size_t)(b * NN) * DD + h * DH;

    #pragma unroll
    for (int it2 = 0; it2 < 4; it2++) {
        int g = tid + 256 * it2;
        int row = g >> 3, c8 = (g & 7) * 8;
        size_t go = rowbase + (size_t)(q0 + row) * DD + c8;
        uint32_t so = (uint32_t)(row * QS + c8) * 2;
        cpa16(base + so, PQh + go);
        cpa16(base + QSZB + so, PQl + go);
    }
    stage_kv(base, 0, 0, tid, rowbase, PKh, Vh);
    CP_COMMIT();
    CP_WAIT0();
    __syncthreads();

    uint32_t qh[4][4], ql[4][4];
    #pragma unroll
    for (int s = 0; s < 4; s++) {
        int r  = w * 16 + (lane & 15);
        int kb = s * 16 + ((lane >> 4) << 3);
        uint32_t so = (uint32_t)(r * QS + kb) * 2;
        ldm4(qh[s], base + so);
        ldm4(ql[s], base + QSZB + so);
    }

    float oacc[8][4];
    #pragma unroll
    for (int j = 0; j < 8; j++)
        #pragma unroll
        for (int q = 0; q < 4; q++) oacc[j][q] = 0.0f;
    float p0 = 0.0f, p1 = 0.0f;

    int st = 0;
    for (int kt = 0; kt < NN / 128; kt++) {
        if (kt + 1 < NN / 128) {
            stage_kv(base, st ^ 1, kt + 1, tid, rowbase, PKh, Vh);
            CP_COMMIT();
            CP_WAIT1();
        } else {
            CP_WAIT0();
        }
        __syncthreads();

        const uint32_t oKh = 2 * QSZB + st * QSZB;
        const uint32_t oVh = 4 * QSZB + st * QSZB;

        #pragma unroll
        for (int t = 0; t < 8; t++) {
            float sacc[2][4] = {};
            #pragma unroll
            for (int s = 0; s < 4; s++) {
                int r  = t * 16 + (lane & 7) + ((lane >> 4) << 3);
                int kb = s * 16 + (((lane >> 3) & 1) << 3);
                uint32_t so = (uint32_t)(r * QS + kb) * 2;
                uint32_t kh[4];
                ldm4(kh, base + oKh + so);
                mma_bf16(sacc[0], qh[s], kh + 0);
                mma_bf16(sacc[0], ql[s], kh + 0);
                mma_bf16(sacc[1], qh[s], kh + 2);
                mma_bf16(sacc[1], ql[s], kh + 2);
            }
            float w2[2][4];
            #pragma unroll
            for (int f = 0; f < 2; f++)
                #pragma unroll
                for (int q = 0; q < 4; q++) {
                    float x = fmaxf(sacc[f][q], 0.0f);
                    w2[f][q] = x * x;
                }
            p0 += w2[0][0] + w2[0][1] + w2[1][0] + w2[1][1];
            p1 += w2[0][2] + w2[0][3] + w2[1][2] + w2[1][3];
            uint32_t wh[4], wl[4];
            {
                bf16 h0, h1, l0, l1;
                split1(w2[0][0], h0, l0); split1(w2[0][1], h1, l1);
                wh[0] = pack2(h0, h1); wl[0] = pack2(l0, l1);
                split1(w2[0][2], h0, l0); split1(w2[0][3], h1, l1);
                wh[1] = pack2(h0, h1); wl[1] = pack2(l0, l1);
                split1(w2[1][0], h0, l0); split1(w2[1][1], h1, l1);
                wh[2] = pack2(h0, h1); wl[2] = pack2(l0, l1);
                split1(w2[1][2], h0, l0); split1(w2[1][3], h1, l1);
                wh[3] = pack2(h0, h1); wl[3] = pack2(l0, l1);
            }
            #pragma unroll
            for (int n = 0; n < 4; n++) {
                int kk = t * 16 + (lane & 7) + ((lane >> 3) & 1) * 8;
                int nn = n * 16 + (lane >> 4) * 8;
                uint32_t so = (uint32_t)(kk * QS + nn) * 2;
                uint32_t vh[4];
                ldm4t(vh, base + oVh + so);
                mma_bf16(oacc[2*n],   wh, vh + 0);
                mma_bf16(oacc[2*n],   wl, vh + 0);
                mma_bf16(oacc[2*n+1], wh, vh + 2);
                mma_bf16(oacc[2*n+1], wl, vh + 2);
            }
        }
        __syncthreads();
        st ^= 1;
    }

    p0 += __shfl_xor_sync(0xFFFFFFFFu, p0, 1);
    p0 += __shfl_xor_sync(0xFFFFFFFFu, p0, 2);
    p1 += __shfl_xor_sync(0xFFFFFFFFu, p1, 1);
    p1 += __shfl_xor_sync(0xFFFFFFFFu, p1, 2);
    float rd0 = 1.0f / (p0 + 1.0f);
    float rd1 = 1.0f / (p1 + 1.0f);

    int r0 = q0 + w * 16 + (lane >> 2);
    int r1 = r0 + 8;
    #pragma unroll
    for (int j = 0; j < 8; j++) {
        int d = j * 8 + (lane & 3) * 2;
        size_t i0 = rowbase + (size_t)r0 * DD + d;
        size_t i1 = rowbase + (size_t)r1 * DD + d;
        uint32_t vh0 = *(const uint32_t*)(Vh + i0), vl0 = *(const uint32_t*)(Vl + i0);
        uint32_t vh1 = *(const uint32_t*)(Vh + i1), vl1 = *(const uint32_t*)(Vl + i1);
        float vp00 = __bfloat162float(__ushort_as_bfloat16((unsigned short)(vh0 & 0xFFFF))) +
                     __bfloat162float(__ushort_as_bfloat16((unsigned short)(vl0 & 0xFFFF)));
        float vp01 = __bfloat162float(__ushort_as_bfloat16((unsigned short)(vh0 >> 16))) +
                     __bfloat162float(__ushort_as_bfloat16((unsigned short)(vl0 >> 16)));
        float vp10 = __bfloat162float(__ushort_as_bfloat16((unsigned short)(vh1 & 0xFFFF))) +
                     __bfloat162float(__ushort_as_bfloat16((unsigned short)(vl1 & 0xFFFF)));
        float vp11 = __bfloat162float(__ushort_as_bfloat16((unsigned short)(vh1 >> 16))) +
                     __bfloat162float(__ushort_as_bfloat16((unsigned short)(vl1 >> 16)));
        float m00 = oacc[j][0] * rd0 - vp00;
        float m01 = oacc[j][1] * rd0 - vp01;
        float m10 = oacc[j][2] * rd1 - vp10;
        float m11 = oacc[j][3] * rd1 - vp11;
        h16 h0, h1, l0, l1;
        split1h(m00, h0, l0); split1h(m01, h1, l1);
        *(uint32_t*)(Mh + i0) = pack2h(h0, h1);
        *(uint32_t*)(Ml + i0) = pack2h(l0, l1);
        split1h(m10, h0, l0); split1h(m11, h1, l1);
        *(uint32_t*)(Mh + i1) = pack2h(h0, h1);
        *(uint32_t*)(Ml + i1) = pack2h(l0, l1);
    }
}

// ---------------- LM head: 256x128 tiles, 512 threads, fp16x2 -----------------
__device__ __forceinline__ void stage_lm(
    uint32_t base, int st, int kc, int tid, int m0, int n0,
    const h16* __restrict__ Ah, const h16* __restrict__ Al)
{
    constexpr uint32_t ASZ = 256 * AMS, BSZ = 128 * AMS;
    const uint32_t oAh = 0, oAl = 2 * ASZ * 2, oB = 4 * ASZ * 2;
    #pragma unroll
    for (int it2 = 0; it2 < 2; it2++) {
        int g = tid + 512 * it2;
        int row = g >> 2, c8 = (g & 3) * 8;
        uint32_t so = (uint32_t)(st * ASZ + row * AMS + c8) * 2;
        size_t ga = (size_t)(m0 + row) * DD + kc * 32 + c8;
        cpa16(base + oAh + so, Ah + ga);
        cpa16(base + oAl + so, Al + ga);
    }
    {
        int g = tid;
        int row = g >> 2, c8 = (g & 3) * 8;
        uint32_t so = (uint32_t)(st * BSZ + row * AMS + c8) * 2;
        size_t gb = (size_t)(n0 + row) * DD + kc * 32 + c8;
        cpa16(base + oB + so, g_LMh + gb);
    }
}

__global__ void __launch_bounds__(512)
lm_head_mma(const h16* __restrict__ Ah, const h16* __restrict__ Al,
            float* __restrict__ C)
{
    extern __shared__ __align__(16) h16 dsm[];
    constexpr uint32_t ASZ = 256 * AMS, BSZ = 128 * AMS;
    const uint32_t base = smem_u32(dsm);
    const uint32_t oAh = 0, oAl = 2 * ASZ * 2, oB = 4 * ASZ * 2;
    const int tid = threadIdx.x, lane = tid & 31, wid = tid >> 5;
    const int warp_m = wid >> 1, warp_n = wid & 1;
    const int m0 = blockIdx.y * 256, n0 = blockIdx.x * 128;

    float acc[2][8][4];
    #pragma unroll
    for (int i = 0; i < 2; i++)
        #pragma unroll
        for (int j = 0; j < 8; j++)
            #pragma unroll
            for (int q = 0; q < 4; q++) acc[i][j][q] = 0.0f;

    stage_lm(base, 0, 0, tid, m0, n0, Ah, Al);
    CP_COMMIT();

    int st = 0;
    for (int kc = 0; kc < 16; kc++) {
        if (kc + 1 < 16) {
            stage_lm(base, st ^ 1, kc + 1, tid, m0, n0, Ah, Al);
            CP_COMMIT();
            CP_WAIT1();
        } else {
            CP_WAIT0();
        }
        __syncthreads();

        #pragma unroll
        for (int s = 0; s < 2; s++) {
            uint32_t ah[2][4], al[2][4], bh[8][2];
            #pragma unroll
            for (int i = 0; i < 2; i++) {
                int r  = warp_m * 32 + i * 16 + (lane & 15);
                int kb = s * 16 + ((lane >> 4) << 3);
                uint32_t so = (uint32_t)(st * ASZ + r * AMS + kb) * 2;
                ldm4(ah[i], base + oAh + so);
                ldm4(al[i], base + oAl + so);
            }
            #pragma unroll
            for (int j = 0; j < 4; j++) {
                int r  = warp_n * 64 + j * 16 + (lane & 7) + ((lane >> 4) << 3);
                int kb = s * 16 + (((lane >> 3) & 1) << 3);
                uint32_t so = (uint32_t)(st * BSZ + r * AMS + kb) * 2;
                uint32_t q[4];
                ldm4(q, base + oB + so);
                bh[2*j][0] = q[0]; bh[2*j][1] = q[1];
                bh[2*j+1][0] = q[2]; bh[2*j+1][1] = q[3];
            }
            #pragma unroll
            for (int i = 0; i < 2; i++)
                #pragma unroll
                for (int j = 0; j < 8; j++) {
                    mma_f16(acc[i][j], ah[i], bh[j]);
                    mma_f16(acc[i][j], al[i], bh[j]);
                }
        }
        __syncthreads();
        st ^= 1;
    }

    #pragma unroll
    for (int i = 0; i < 2; i++) {
        int m = m0 + warp_m * 32 + i * 16 + (lane >> 2);
        #pragma unroll
        for (int j = 0; j < 8; j++) {
            int n = n0 + warp_n * 64 + j * 8 + (lane & 3) * 2;
            *(float2*)(C + (size_t)m * VV + n) =
                make_float2(acc[i][j][0], acc[i][j][1]);
            *(float2*)(C + (size_t)(m + 8) * VV + n) =
                make_float2(acc[i][j][2], acc[i][j][3]);
        }
    }
}

// ---------------- init -------------------------------------------------------
__global__ void init_kernel(const int* __restrict__ inputs,
                            const int* __restrict__ carry_inputs,
                            const void* __restrict__ halted,
                            const float* __restrict__ carry_hidden,
                            const float* __restrict__ init_hidden,
                            const float* __restrict__ emb,
                            const float* __restrict__ pos,
                            const float* __restrict__ in_s,
                            const float* __restrict__ in_b)
{
    int r = blockIdx.x;
    int b = r / NN, n = r % NN;
    int t = threadIdx.x;
    bool h = read_halted(halted, b);
    int idx = h ? inputs[r] : carry_inputs[r];
    const float* e = emb + (size_t)idx * DD;
    const float* p = pos + (size_t)n * DD;

    float x0 = e[t]       + p[t];
    float x1 = e[t + 256] + p[t + 256];

    size_t base = (size_t)r * DD;
    g_Q[base + t]       = h ? init_hidden[t]       : carry_hidden[base + t];
    g_Q[base + t + 256] = h ? init_hidden[t + 256] : carry_hidden[base + t + 256];

    __shared__ float s_sum[256], s_sq[256];
    s_sum[t] = x0 + x1;
    s_sq[t]  = x0 * x0 + x1 * x1;
    __syncthreads();
    for (int o = 128; o > 0; o >>= 1) {
        if (t < o) { s_sum[t] += s_sum[t + o]; s_sq[t] += s_sq[t + o]; }
        __syncthreads();
    }
    float mu   = s_sum[0] * (1.0f / DD);
    float var  = s_sq[0] * (1.0f / DD) - mu * mu;
    float rstd = rsqrtf(var + 1e-5f);
    g_X[base + t]       = (x0 - mu) * rstd * in_s[t]       + in_b[t];
    g_X[base + t + 256] = (x1 - mu) * rstd * in_s[t + 256] + in_b[t + 256];
}

// ---------------- LayerNorm (fp32 in; optional fp32 out; fp16 hi/lo out) -----
__global__ void ln_kernel(const float* __restrict__ in, float* __restrict__ outf,
                          h16* __restrict__ outh, h16* __restrict__ outl,
                          const float* __restrict__ s, const float* __restrict__ bia,
                          const float* __restrict__ add)
{
    int r = blockIdx.x;
    int t = threadIdx.x;
    size_t base = (size_t)r * DD;
    float x0 = in[base + t];
    float x1 = in[base + t + 256];

    __shared__ float s_sum[256], s_sq[256];
    s_sum[t] = x0 + x1;
    s_sq[t]  = x0 * x0 + x1 * x1;
    __syncthreads();
    for (int o = 128; o > 0; o >>= 1) {
        if (t < o) { s_sum[t] += s_sum[t + o]; s_sq[t] += s_sq[t + o]; }
        __syncthreads();
    }
    float mu   = s_sum[0] * (1.0f / DD);
    float var  = s_sq[0] * (1.0f / DD) - mu * mu;
    float rstd = rsqrtf(var + 1e-5f);
    float v0 = (x0 - mu) * rstd * s[t]       + bia[t];
    float v1 = (x1 - mu) * rstd * s[t + 256] + bia[t + 256];
    if (add) { v0 += add[base + t]; v1 += add[base + t + 256]; }
    if (outf) { outf[base + t] = v0; outf[base + t + 256] = v1; }
    if (outh) {
        h16 h0, l0, h1, l1;
        split1h(v0, h0, l0); split1h(v1, h1, l1);
        outh[base + t] = h0;       outl[base + t] = l0;
        outh[base + t + 256] = h1; outl[base + t + 256] = l1;
    }
}

// ---------------- depthwise conv k=3 + bias + silu -> fp16 hi/lo --------------
__global__ void conv_kernel(const float* __restrict__ Hf, const float* __restrict__ w,
                            const float* __restrict__ bias,
                            h16* __restrict__ outh, h16* __restrict__ outl)
{
    size_t i = (size_t)blockIdx.x * 256 + threadIdx.x;
    if (i >= (size_t)MROWS * INNER) return;
    size_t row = i / INNER;
    int c = (int)(i % INNER);
    int n = (int)(row % NN);
    const float* wc = w + (size_t)c * CKW;
    float acc = bias[c];
    if (n > 0)      acc += wc[0] * Hf[(row - 1) * INNER + c];
    acc += wc[1] * Hf[row * INNER + c];
    if (n < NN - 1) acc += wc[2] * Hf[(row + 1) * INNER + c];
    float v = siluf(acc);
    h16 h, l;
    split1h(v, h, l);
    outh[i] = h;
    outl[i] = l;
}

// ---------------- halt head --------------------------------------------------
__global__ void halt_kernel(const float* __restrict__ Qn, const float* __restrict__ hw,
                            const float* __restrict__ hb, float* __restrict__ out)
{
    int b = blockIdx.x;
    int t = threadIdx.x;
    __shared__ float md[DD];
    for (int d = t; d < DD; d += 256) {
        float s = 0.0f;
        for (int n = 0; n < NN; n++)
            s += Qn[((size_t)(b * NN + n)) * DD + d];
        md[d] = s * (1.0f / NN);
    }
    __syncthreads();
    __shared__ float r0[256], r1[256];
    float p0 = 0.0f, p1 = 0.0f;
    for (int d = t; d < DD; d += 256) {
        p0 += md[d] * hw[d];
        p1 += md[d] * hw[DD + d];
    }
    r0[t] = p0; r1[t] = p1;
    __syncthreads();
    for (int o = 128; o > 0; o >>= 1) {
        if (t < o) { r0[t] += r0[t + o]; r1[t] += r1[t + o]; }
        __syncthreads();
    }
    if (t == 0) {
        out[b * 2 + 0] = r0[0] + hb[0];
        out[b * 2 + 1] = r1[0] + hb[1];
    }
}

// ---------------- host orchestration -----------------------------------------
static void cvt_h(const float* src, h16* d, size_t n)
{
    int n4 = (int)(n / 4);
    cvt_h_kernel<<<(n4 + 255) / 256, 256>>>(src, d, n4);
}

extern "C" void kernel_launch(void* const* d_in, const int* in_sizes, int n_in,
                              void* d_out, int out_size)
{
    const int*   inputs       = (const int*)d_in[0];
    const float* carry_hidden = (const float*)d_in[2];
    const void*  halted       = d_in[4];
    const int*   carry_inputs = (const int*)d_in[5];
    const float* init_hidden  = (const float*)d_in[7];
    const float* emb          = (const float*)d_in[8];
    const float* pos          = (const float*)d_in[9];
    const float* in_s         = (const float*)d_in[10];
    const float* in_b         = (const float*)d_in[11];
    const float* fin_s        = (const float*)d_in[12];
    const float* fin_b        = (const float*)d_in[13];
    const float* lm_w         = (const float*)d_in[14];
    const float* halt_w       = (const float*)d_in[15];
    const float* halt_b       = (const float*)d_in[16];
    const float* dt           = (const float*)d_in[17];
    const float* W_Q          = (const float*)d_in[18];
    const float* W_K          = (const float*)d_in[19];
    const float* W_V          = (const float*)d_in[20];
    const float* W_O          = (const float*)d_in[21];
    const float* W_up         = (const float*)d_in[22];
    const float* dw_w         = (const float*)d_in[23];
    const float* dw_b         = (const float*)d_in[24];
    const float* W_down       = (const float*)d_in[25];
    const float* n1_s         = (const float*)d_in[26];
    const float* n1_b         = (const float*)d_in[27];
    const float* n2_s         = (const float*)d_in[28];
    const float* n2_b         = (const float*)d_in[29];

    float *X, *Q, *Qi, *Qn, *Hf;
    h16 *Hch, *Hcl, *mbh, *mbl, *Q2h, *Q2l, *Hvh, *Hvl, *Qnh, *Qnl;
    bf16 *PQh, *PQl, *PKh, *Vh, *Vl;
    h16 *WQh, *WKh, *WVh, *WOh, *WUh, *WDh, *LMh;
    cudaGetSymbolAddress((void**)&X,   g_X);
    cudaGetSymbolAddress((void**)&Q,   g_Q);
    cudaGetSymbolAddress((void**)&Qi,  g_Qi);
    cudaGetSymbolAddress((void**)&Qn,  g_Qn);
    cudaGetSymbolAddress((void**)&Hf,  g_Hf);
    cudaGetSymbolAddress((void**)&Hch, g_Hch); cudaGetSymbolAddress((void**)&Hcl, g_Hcl);
    cudaGetSymbolAddress((void**)&PQh, g_PQh); cudaGetSymbolAddress((void**)&PQl, g_PQl);
    cudaGetSymbolAddress((void**)&PKh, g_PKh);
    cudaGetSymbolAddress((void**)&Vh,  g_Vh);  cudaGetSymbolAddress((void**)&Vl,  g_Vl);
    cudaGetSymbolAddress((void**)&mbh, g_mbh); cudaGetSymbolAddress((void**)&mbl, g_mbl);
    cudaGetSymbolAddress((void**)&Q2h, g_Q2h); cudaGetSymbolAddress((void**)&Q2l, g_Q2l);
    cudaGetSymbolAddress((void**)&Hvh, g_Hvh); cudaGetSymbolAddress((void**)&Hvl, g_Hvl);
    cudaGetSymbolAddress((void**)&Qnh, g_Qnh); cudaGetSymbolAddress((void**)&Qnl, g_Qnl);
    cudaGetSymbolAddress((void**)&WQh, g_WQh);
    cudaGetSymbolAddress((void**)&WKh, g_WKh);
    cudaGetSymbolAddress((void**)&WVh, g_WVh);
    cudaGetSymbolAddress((void**)&WOh, g_WOh);
    cudaGetSymbolAddress((void**)&WUh, g_WUh);
    cudaGetSymbolAddress((void**)&WDh, g_WDh);
    cudaGetSymbolAddress((void**)&LMh, g_LMh);

    float* out = (float*)d_out;

    cudaFuncSetAttribute(attn_fused, cudaFuncAttributeMaxDynamicSharedMemorySize, ATT_SMEM);
    cudaFuncSetAttribute(mma_proj,   cudaFuncAttributeMaxDynamicSharedMemorySize, SM_G128);
    cudaFuncSetAttribute(mma_up,     cudaFuncAttributeMaxDynamicSharedMemorySize, SM_G128);
    cudaFuncSetAttribute(mma_wo,     cudaFuncAttributeMaxDynamicSharedMemorySize, SM_G64);
    cudaFuncSetAttribute(mma_down,   cudaFuncAttributeMaxDynamicSharedMemorySize, SM_G64);
    cudaFuncSetAttribute(lm_head_mma, cudaFuncAttributeMaxDynamicSharedMemorySize, SM_LM);

    cvt_h(W_Q,    WQh, (size_t)KKB * DD * DD);
    cvt_h(W_K,    WKh, (size_t)KKB * DD * DD);
    cvt_h(W_V,    WVh, (size_t)KKB * DD * DD);
    cvt_h(W_O,    WOh, (size_t)KKB * DD * DD);
    {
        int total = KKB * DD * (2 * INNER) / 8;
        cvt_up_kernel<<<(total + 255) / 256, 256>>>(W_up, WUh);
    }
    cvt_h(W_down, WDh, (size_t)KKB * INNER * DD);
    cvt_h(lm_w,   LMh, (size_t)VV * DD);

    init_kernel<<<MROWS, 256>>>(inputs, carry_inputs, halted, carry_hidden,
                                init_hidden, emb, pos, in_s, in_b);

    dim3 gP(DD / 128, MROWS / 128, 3);        // (4, 16, 3)
    dim3 gO64(DD / 64, MROWS / 128);          // (8, 16) = 128 CTAs
    dim3 gUP(2 * INNER / 128, MROWS / 128);   // (24, 16)
    dim3 gAT(NN / 128, BHN);                  // (8, 16)

    for (int it = 0; it < TOTAL_PASSES; it++) {
        int k = it % KKB;

        ln_kernel<<<MROWS, 256>>>(Q, nullptr, Hch, Hcl,
                                  n1_s + k * DD, n1_b + k * DD, X);

        mma_proj<<<gP, 256, SM_G128>>>(Hch, Hcl, k);

        attn_fused<<<gAT, 256, ATT_SMEM>>>(PQh, PQl, PKh, Vh, Vl, mbh, mbl);

        mma_wo<<<gO64, 256, SM_G64>>>(mbh, mbl, k, Qi, Q, dt);

        ln_kernel<<<MROWS, 256>>>(Qi, nullptr, Q2h, Q2l,
                                  n2_s + k * DD, n2_b + k * DD, nullptr);
        mma_up<<<gUP, 256, SM_G128>>>(Q2h, Q2l, k, Hf);    // fused swiglu
        int tot = MROWS * INNER;
        conv_kernel<<<(tot + 255) / 256, 256>>>(Hf, dw_w + (size_t)k * INNER * CKW,
                                                dw_b + (size_t)k * INNER, Hvh, Hvl);
        mma_down<<<gO64, 256, SM_G64>>>(Hvh, Hvl, k, Q, Qi);
    }

    ln_kernel<<<MROWS, 256>>>(Q, Qn, Qnh, Qnl, fin_s, fin_b, nullptr);
    dim3 gLM(VV / 128, MROWS / 256);          // (250, 8)
    lm_head_mma<<<gLM, 512, SM_LM>>>(Qnh, Qnl, out);
    halt_kernel<<<BB, 256>>>(Qn, halt_w, halt_b, out + (size_t)MROWS * VV);
}

// round 15
// speedup vs baseline: 1.0913x; 1.0238x over previous
#include <cuda_runtime.h>
#include <cuda_bf16.h>
#include <cuda_fp16.h>
#include <math.h>
#include <stdint.h>

// Problem constants
#define BB    2
#define NN    1024
#define DD    512
#define HH    8
#define DH    64
#define KKB   4
#define VV    32000
#define INNER 1536
#define CKW   3
#define MROWS (BB*NN)     // 2048
#define BHN   (BB*HH)     // 16
#define TOTAL_PASSES 8

#define AMS  40    // A smem stride (16-bit elems): 32 data + 8 pad
#define QS   72    // attention smem stride (64 + 8)

typedef __nv_bfloat16 bf16;
typedef __half h16;

// ---------------- fp32 scratch ----------------------------------------------
__device__ __align__(16) float g_X  [MROWS*DD];
__device__ __align__(16) float g_Q  [MROWS*DD];
__device__ __align__(16) float g_Qi [MROWS*DD];
__device__ __align__(16) float g_Qn [MROWS*DD];
__device__ __align__(16) float g_Hf [(size_t)MROWS*INNER];

// ---------------- activation scratch -----------------------------------------
__device__ __align__(16) h16 g_Hch [MROWS*DD], g_Hcl [MROWS*DD];
__device__ __align__(16) h16 g_mbh [MROWS*DD], g_mbl [MROWS*DD];
__device__ __align__(16) h16 g_Q2h [MROWS*DD], g_Q2l [MROWS*DD];
__device__ __align__(16) h16 g_Hvh [(size_t)MROWS*INNER], g_Hvl [(size_t)MROWS*INNER];
__device__ __align__(16) h16 g_Qnh [MROWS*DD], g_Qnl [MROWS*DD];
__device__ __align__(16) bf16 g_PQh [MROWS*DD], g_PQl [MROWS*DD];
__device__ __align__(16) bf16 g_PKh [MROWS*DD], g_PKl [MROWS*DD];
__device__ __align__(16) bf16 g_Vh  [MROWS*DD], g_Vl  [MROWS*DD];

// ---------------- single-fp16 weight scratch ---------------------------------
__device__ __align__(16) h16 g_WQh [KKB*DD*DD];
__device__ __align__(16) h16 g_WKh [KKB*DD*DD];
__device__ __align__(16) h16 g_WVh [KKB*DD*DD];
__device__ __align__(16) h16 g_WOh [KKB*DD*DD];
__device__ __align__(16) h16 g_WUh [(size_t)KKB*DD*2*INNER];
__device__ __align__(16) h16 g_WDh [(size_t)KKB*INNER*DD];
__device__ __align__(16) h16 g_LMh [(size_t)VV*DD];

// ---------------- helpers ----------------------------------------------------
__device__ __forceinline__ float siluf(float x) { return x / (1.0f + expf(-x)); }

__device__ __forceinline__ bool read_halted(const void* p, int b)
{
    const unsigned char* u8 = (const unsigned char*)p;
    if (u8[1] != 0) return u8[b] != 0;
    return ((const int*)p)[b] != 0;
}
__device__ __forceinline__ uint32_t smem_u32(const void* p) {
    uint32_t a;
    asm("{ .reg .u64 t; cvta.to.shared.u64 t, %1; cvt.u32.u64 %0, t; }"
        : "=r"(a) : "l"(p));
    return a;
}
__device__ __forceinline__ void ldm4(uint32_t* r, uint32_t a) {
    asm volatile("ldmatrix.sync.aligned.m8n8.x4.shared.b16 {%0,%1,%2,%3}, [%4];"
                 : "=r"(r[0]), "=r"(r[1]), "=r"(r[2]), "=r"(r[3]) : "r"(a));
}
__device__ __forceinline__ void ldm4t(uint32_t* r, uint32_t a) {
    asm volatile("ldmatrix.sync.aligned.m8n8.x4.trans.shared.b16 {%0,%1,%2,%3}, [%4];"
                 : "=r"(r[0]), "=r"(r[1]), "=r"(r[2]), "=r"(r[3]) : "r"(a));
}
__device__ __forceinline__ void mma_bf16(float* c, const uint32_t* a, const uint32_t* b) {
    asm volatile("mma.sync.aligned.m16n8k16.row.col.f32.bf16.bf16.f32 "
                 "{%0,%1,%2,%3}, {%4,%5,%6,%7}, {%8,%9}, {%0,%1,%2,%3};"
                 : "+f"(c[0]), "+f"(c[1]), "+f"(c[2]), "+f"(c[3])
                 : "r"(a[0]), "r"(a[1]), "r"(a[2]), "r"(a[3]),
                   "r"(b[0]), "r"(b[1]));
}
__device__ __forceinline__ void mma_f16(float* c, const uint32_t* a, const uint32_t* b) {
    asm volatile("mma.sync.aligned.m16n8k16.row.col.f32.f16.f16.f32 "
                 "{%0,%1,%2,%3}, {%4,%5,%6,%7}, {%8,%9}, {%0,%1,%2,%3};"
                 : "+f"(c[0]), "+f"(c[1]), "+f"(c[2]), "+f"(c[3])
                 : "r"(a[0]), "r"(a[1]), "r"(a[2]), "r"(a[3]),
                   "r"(b[0]), "r"(b[1]));
}
__device__ __forceinline__ uint32_t pack2(bf16 a, bf16 b) {
    return (uint32_t)__bfloat16_as_ushort(a) |
           ((uint32_t)__bfloat16_as_ushort(b) << 16);
}
__device__ __forceinline__ uint32_t pack2h(h16 a, h16 b) {
    return (uint32_t)__half_as_ushort(a) |
           ((uint32_t)__half_as_ushort(b) << 16);
}
__device__ __forceinline__ void split1(float v, bf16& h, bf16& l) {
    h = __float2bfloat16(v);
    l = __float2bfloat16(v - __bfloat162float(h));
}
__device__ __forceinline__ void split1h(float v, h16& h, h16& l) {
    h = __float2half_rn(v);
    l = __float2half_rn(v - __half2float(h));
}
__device__ __forceinline__ void cpa16(uint32_t s, const void* g) {
    asm volatile("cp.async.cg.shared.global [%0], [%1], 16;" :: "r"(s), "l"(g));
}
#define CP_COMMIT() asm volatile("cp.async.commit_group;" ::: "memory")
#define CP_WAIT0()  asm volatile("cp.async.wait_group 0;" ::: "memory")
#define CP_WAIT1()  asm volatile("cp.async.wait_group 1;" ::: "memory")

// ---------------- converters --------------------------------------------------
__global__ void cvt_h_kernel(const float* __restrict__ src, h16* __restrict__ d, int n4)
{
    int i = blockIdx.x * 256 + threadIdx.x;
    if (i >= n4) return;
    float4 v = *(const float4*)(src + (size_t)i * 4);
    uint2 o;
    o.x = pack2h(__float2half_rn(v.x), __float2half_rn(v.y));
    o.y = pack2h(__float2half_rn(v.z), __float2half_rn(v.w));
    *(uint2*)(d + (size_t)i * 4) = o;
}

__global__ void cvt_up_kernel(const float* __restrict__ src, h16* __restrict__ d)
{
    int gi = blockIdx.x * 256 + threadIdx.x;
    int total = KKB * DD * (2 * INNER) / 8;
    if (gi >= total) return;
    int cg8 = gi % (2 * INNER / 8);
    int row = gi / (2 * INNER / 8);
    int cg = cg8 * 4;
    size_t rb = (size_t)row * (2 * INNER);
    float4 gsrc = *(const float4*)(src + rb + cg);
    float4 usrc = *(const float4*)(src + rb + INNER + cg);
    float gv[4] = {gsrc.x, gsrc.y, gsrc.z, gsrc.w};
    float uv[4] = {usrc.x, usrc.y, usrc.z, usrc.w};
    uint32_t w[4];
    #pragma unroll
    for (int q = 0; q < 4; q++)
        w[q] = pack2h(__float2half_rn(gv[q]), __float2half_rn(uv[q]));
    size_t db = rb + (size_t)cg8 * 8;
    *(uint4*)(d + db) = make_uint4(w[0], w[1], w[2], w[3]);
}

// ---------------- 2-stage pipelined fp16x2 GEMM body -------------------------
template <int BN>
__device__ __forceinline__ void stage_gemm(
    uint32_t base, int st, int kc, int tid, int m0, int n0,
    const h16* __restrict__ Ah, const h16* __restrict__ Al, int lda,
    const h16* __restrict__ B, int ldb)
{
    constexpr int BNS_ = (BN == 128) ? 136 : 72;
    constexpr uint32_t ASZ = 128 * AMS, BSZ = 32 * BNS_;
    const uint32_t oAh = 0, oAl = 2 * ASZ * 2, oB = 4 * ASZ * 2;
    #pragma unroll
    for (int it2 = 0; it2 < 2; it2++) {
        int g = tid + 256 * it2;
        int row = g >> 2, c8 = (g & 3) * 8;
        size_t go = (size_t)(m0 + row) * lda + kc * 32 + c8;
        uint32_t so = (uint32_t)(st * ASZ + row * AMS + c8) * 2;
        cpa16(base + oAh + so, Ah + go);
        cpa16(base + oAl + so, Al + go);
    }
    {
        if (BN == 128) {
            #pragma unroll
            for (int it2 = 0; it2 < 2; it2++) {
                int g = tid + 256 * it2;
                int row = g >> 4, c8 = (g & 15) * 8;
                size_t go = (size_t)(kc * 32 + row) * ldb + n0 + c8;
                uint32_t so = (uint32_t)(st * BSZ + row * BNS_ + c8) * 2;
                cpa16(base + oB + so, B + go);
            }
        } else {
            int g = tid;
            int row = g >> 3, c8 = (g & 7) * 8;
            size_t go = (size_t)(kc * 32 + row) * ldb + n0 + c8;
            uint32_t so = (uint32_t)(st * BSZ + row * BNS_ + c8) * 2;
            cpa16(base + oB + so, B + go);
        }
    }
}

// epi: 0 fp32, 1 bf16 hi/lo elu+1, 2 fp32 addP+alpha*acc, 3 fp32 addP+acc,
//      4 bf16 hi/lo plain, 5 fused swiglu -> fp32 Hf
template <int BN>
__device__ __forceinline__ void gemm_pipe(
    h16* smem,
    const h16* __restrict__ Ah, const h16* __restrict__ Al, int lda,
    const h16* __restrict__ B, int ldb,
    float* __restrict__ Cf, bf16* __restrict__ Ch, bf16* __restrict__ Cl, int ldc,
    int m0, int n0, int kch, int epi, const float* __restrict__ addP, float alpha)
{
    constexpr int BNS_ = (BN == 128) ? 136 : 72;
    constexpr int NJ = BN / 16;
    constexpr uint32_t ASZ = 128 * AMS, BSZ = 32 * BNS_;
    const uint32_t base = smem_u32(smem);
    const uint32_t oAh = 0, oAl = 2 * ASZ * 2, oB = 4 * ASZ * 2;
    const int tid = threadIdx.x, lane = tid & 31, wid = tid >> 5;
    const int warp_m = wid >> 1, warp_n = wid & 1;

    float acc[2][NJ][4];
    #pragma unroll
    for (int i = 0; i < 2; i++)
        #pragma unroll
        for (int j = 0; j < NJ; j++)
            #pragma unroll
            for (int q = 0; q < 4; q++) acc[i][j][q] = 0.0f;

    stage_gemm<BN>(base, 0, 0, tid, m0, n0, Ah, Al, lda, B, ldb);
    CP_COMMIT();

    int st = 0;
    for (int kc = 0; kc < kch; kc++) {
        if (kc + 1 < kch) {
            stage_gemm<BN>(base, st ^ 1, kc + 1, tid, m0, n0, Ah, Al, lda, B, ldb);
            CP_COMMIT();
            CP_WAIT1();
        } else {
            CP_WAIT0();
        }
        __syncthreads();

        #pragma unroll
        for (int s = 0; s < 2; s++) {
            uint32_t ah[2][4], al[2][4], bh[NJ][2];
            #pragma unroll
            for (int i = 0; i < 2; i++) {
                int r  = warp_m * 32 + i * 16 + (lane & 15);
                int kb = s * 16 + ((lane >> 4) << 3);
                uint32_t so = (uint32_t)(st * ASZ + r * AMS + kb) * 2;
                ldm4(ah[i], base + oAh + so);
                ldm4(al[i], base + oAl + so);
            }
            #pragma unroll
            for (int j2 = 0; j2 < NJ / 2; j2++) {
                int kk = s * 16 + (lane & 7) + ((lane >> 3) & 1) * 8;
                int nn = warp_n * (BN / 2) + j2 * 16 + (lane >> 4) * 8;
                uint32_t so = (uint32_t)(st * BSZ + kk * BNS_ + nn) * 2;
                uint32_t q[4];
                ldm4t(q, base + oB + so);
                bh[2*j2][0] = q[0]; bh[2*j2][1] = q[1];
                bh[2*j2+1][0] = q[2]; bh[2*j2+1][1] = q[3];
            }
            #pragma unroll
            for (int i = 0; i < 2; i++)
                #pragma unroll
                for (int j = 0; j < NJ; j++) {
                    mma_f16(acc[i][j], ah[i], bh[j]);
                    mma_f16(acc[i][j], al[i], bh[j]);
                }
        }
        __syncthreads();
        st ^= 1;
    }

    #pragma unroll
    for (int i = 0; i < 2; i++) {
        int m = m0 + warp_m * 32 + i * 16 + (lane >> 2);
        #pragma unroll
        for (int j = 0; j < NJ; j++) {
            int n = n0 + warp_n * (BN / 2) + j * 8 + (lane & 3) * 2;
            float v0 = acc[i][j][0], v1 = acc[i][j][1];
            float v2 = acc[i][j][2], v3 = acc[i][j][3];
            if (epi == 5) {
                int col = n >> 1;
                Cf[(size_t)m * INNER + col]       = siluf(v0) * v1;
                Cf[(size_t)(m + 8) * INNER + col] = siluf(v2) * v3;
                continue;
            }
            size_t i0 = (size_t)m * ldc + n;
            size_t i1 = (size_t)(m + 8) * ldc + n;
            if (epi == 1 || epi == 4) {
                if (epi == 1) {
                    v0 = (v0 > 0.f) ? v0 + 1.f : expf(v0);
                    v1 = (v1 > 0.f) ? v1 + 1.f : expf(v1);
                    v2 = (v2 > 0.f) ? v2 + 1.f : expf(v2);
                    v3 = (v3 > 0.f) ? v3 + 1.f : expf(v3);
                }
                bf16 h0, h1, h2, h3, l0, l1, l2, l3;
                split1(v0, h0, l0); split1(v1, h1, l1);
                split1(v2, h2, l2); split1(v3, h3, l3);
                *(uint32_t*)(Ch + i0) = pack2(h0, h1);
                *(uint32_t*)(Cl + i0) = pack2(l0, l1);
                *(uint32_t*)(Ch + i1) = pack2(h2, h3);
                *(uint32_t*)(Cl + i1) = pack2(l2, l3);
            } else {
                if (epi == 2) {
                    v0 = addP[i0] + alpha * v0; v1 = addP[i0+1] + alpha * v1;
                    v2 = addP[i1] + alpha * v2; v3 = addP[i1+1] + alpha * v3;
                } else if (epi == 3) {
                    v0 += addP[i0]; v1 += addP[i0+1];
                    v2 += addP[i1]; v3 += addP[i1+1];
                }
                *(float2*)(Cf + i0) = make_float2(v0, v1);
                *(float2*)(Cf + i1) = make_float2(v2, v3);
            }
        }
    }
}

#define SM_G128 58368
#define SM_G64  50176
#define SM_LM   102400
#define ATT_SMEM 110592   // 6 * 128 * QS * 2  (Qh,Ql + Kh s0/s1 + Vh s0/s1)

// ---------------- GEMM wrappers (2 CTAs/SM) -----------------------------------
__global__ void __launch_bounds__(256, 2) mma_proj(
    const h16* __restrict__ Ah, const h16* __restrict__ Al, int kIdx)
{
    extern __shared__ __align__(16) h16 dsm[];
    int z = blockIdx.z;
    size_t wo = (size_t)kIdx * DD * DD;
    const h16* B = (z == 0) ? g_WQh + wo : (z == 1) ? g_WKh + wo : g_WVh + wo;
    bf16* Ch = (z == 0) ? g_PQh : (z == 1) ? g_PKh : g_Vh;
    bf16* Cl = (z == 0) ? g_PQl : (z == 1) ? g_PKl : g_Vl;
    gemm_pipe<128>(dsm, Ah, Al, DD, B, DD,
                   nullptr, Ch, Cl, DD, blockIdx.y * 128, blockIdx.x * 128,
                   DD / 32, (z < 2) ? 1 : 4, nullptr, 0.f);
}

__global__ void __launch_bounds__(256, 2) mma_wo(
    const h16* __restrict__ Ah, const h16* __restrict__ Al, int kIdx,
    float* __restrict__ C, const float* __restrict__ addP,
    const float* __restrict__ dt)
{
    extern __shared__ __align__(16) h16 dsm[];
    size_t wo = (size_t)kIdx * DD * DD;
    float d = dt[kIdx];
    float alpha = (d > 20.0f) ? d : log1pf(expf(d));
    gemm_pipe<64>(dsm, Ah, Al, DD, g_WOh + wo, DD,
                  C, nullptr, nullptr, DD, blockIdx.y * 128, blockIdx.x * 64,
                  DD / 32, 2, addP, alpha);
}

__global__ void __launch_bounds__(256, 2) mma_up(
    const h16* __restrict__ Ah, const h16* __restrict__ Al, int kIdx,
    float* __restrict__ Hf)
{
    extern __shared__ __align__(16) h16 dsm[];
    size_t wo = (size_t)kIdx * DD * 2 * INNER;
    gemm_pipe<128>(dsm, Ah, Al, DD, g_WUh + wo, 2 * INNER,
                   Hf, nullptr, nullptr, 2 * INNER, blockIdx.y * 128, blockIdx.x * 128,
                   DD / 32, 5, nullptr, 0.f);
}

__global__ void __launch_bounds__(256, 2) mma_down(
    const h16* __restrict__ Ah, const h16* __restrict__ Al, int kIdx,
    float* __restrict__ C, const float* __restrict__ addP)
{
    extern __shared__ __align__(16) h16 dsm[];
    size_t wo = (size_t)kIdx * INNER * DD;
    gemm_pipe<64>(dsm, Ah, Al, INNER, g_WDh + wo, DD,
                  C, nullptr, nullptr, DD, blockIdx.y * 128, blockIdx.x * 64,
                  INNER / 32, 3, addP, 0.f);
}

// ---------------- fused flash attention (2-term) ------------------------------
__device__ __forceinline__ void stage_kv(
    uint32_t base, int st, int kt, int tid, size_t rowbase,
    const bf16* __restrict__ PKh, const bf16* __restrict__ Vh)
{
    const uint32_t QSZB = 128 * QS * 2;
    const uint32_t oKh = 2 * QSZB + st * QSZB;
    const uint32_t oVh = 4 * QSZB + st * QSZB;
    #pragma unroll
    for (int it2 = 0; it2 < 4; it2++) {
        int g = tid + 256 * it2;
        int row = g >> 3, c8 = (g & 7) * 8;
        size_t go = rowbase + (size_t)(kt * 128 + row) * DD + c8;
        uint32_t so = (uint32_t)(row * QS + c8) * 2;
        cpa16(base + oKh + so, PKh + go);
        cpa16(base + oVh + so, Vh + go);
    }
}

__global__ void __launch_bounds__(256) attn_fused(
    const bf16* __restrict__ PQh, const bf16* __restrict__ PQl,
    const bf16* __restrict__ PKh,
    const bf16* __restrict__ Vh,  const bf16* __restrict__ Vl,
    h16* __restrict__ Mh, h16* __restrict__ Ml)
{
    extern __shared__ __align__(16) bf16 dsmb[];
    const uint32_t base = smem_u32(dsmb);
    const uint32_t QSZB = 128 * QS * 2;

    const int tid = threadIdx.x, lane = tid & 31, w = tid >> 5;
    const int bh = blockIdx.y, b = bh >> 3, h = bh & 7;
    const int q0 = blockIdx.x * 128;
    const size_t rowbase = (size_t)(b * NN) * DD + h * DH;

    #pragma unroll
    for (int it2 = 0; it2 < 4; it2++) {
        int g = tid + 256 * it2;
        int row = g >> 3, c8 = (g & 7) * 8;
        size_t go = rowbase + (size_t)(q0 + row) * DD + c8;
        uint32_t so = (uint32_t)(row * QS + c8) * 2;
        cpa16(base + so, PQh + go);
        cpa16(base + QSZB + so, PQl + go);
    }
    stage_kv(base, 0, 0, tid, rowbase, PKh, Vh);
    CP_COMMIT();
    CP_WAIT0();
    __syncthreads();

    uint32_t qh[4][4], ql[4][4];
    #pragma unroll
    for (int s = 0; s < 4; s++) {
        int r  = w * 16 + (lane & 15);
        int kb = s * 16 + ((lane >> 4) << 3);
        uint32_t so = (uint32_t)(r * QS + kb) * 2;
        ldm4(qh[s], base + so);
        ldm4(ql[s], base + QSZB + so);
    }

    float oacc[8][4];
    #pragma unroll
    for (int j = 0; j < 8; j++)
        #pragma unroll
        for (int q = 0; q < 4; q++) oacc[j][q] = 0.0f;
    float p0 = 0.0f, p1 = 0.0f;

    int st = 0;
    for (int kt = 0; kt < NN / 128; kt++) {
        if (kt + 1 < NN / 128) {
            stage_kv(base, st ^ 1, kt + 1, tid, rowbase, PKh, Vh);
            CP_COMMIT();
            CP_WAIT1();
        } else {
            CP_WAIT0();
        }
        __syncthreads();

        const uint32_t oKh = 2 * QSZB + st * QSZB;
        const uint32_t oVh = 4 * QSZB + st * QSZB;

        #pragma unroll
        for (int t = 0; t < 8; t++) {
            float sacc[2][4] = {};
            #pragma unroll
            for (int s = 0; s < 4; s++) {
                int r  = t * 16 + (lane & 7) + ((lane >> 4) << 3);
                int kb = s * 16 + (((lane >> 3) & 1) << 3);
                uint32_t so = (uint32_t)(r * QS + kb) * 2;
                uint32_t kh[4];
                ldm4(kh, base + oKh + so);
                mma_bf16(sacc[0], qh[s], kh + 0);
                mma_bf16(sacc[0], ql[s], kh + 0);
                mma_bf16(sacc[1], qh[s], kh + 2);
                mma_bf16(sacc[1], ql[s], kh + 2);
            }
            float w2[2][4];
            #pragma unroll
            for (int f = 0; f < 2; f++)
                #pragma unroll
                for (int q = 0; q < 4; q++) {
                    float x = fmaxf(sacc[f][q], 0.0f);
                    w2[f][q] = x * x;
                }
            p0 += w2[0][0] + w2[0][1] + w2[1][0] + w2[1][1];
            p1 += w2[0][2] + w2[0][3] + w2[1][2] + w2[1][3];
            uint32_t wh[4], wl[4];
            {
                bf16 h0, h1, l0, l1;
                split1(w2[0][0], h0, l0); split1(w2[0][1], h1, l1);
                wh[0] = pack2(h0, h1); wl[0] = pack2(l0, l1);
                split1(w2[0][2], h0, l0); split1(w2[0][3], h1, l1);
                wh[1] = pack2(h0, h1); wl[1] = pack2(l0, l1);
                split1(w2[1][0], h0, l0); split1(w2[1][1], h1, l1);
                wh[2] = pack2(h0, h1); wl[2] = pack2(l0, l1);
                split1(w2[1][2], h0, l0); split1(w2[1][3], h1, l1);
                wh[3] = pack2(h0, h1); wl[3] = pack2(l0, l1);
            }
            #pragma unroll
            for (int n = 0; n < 4; n++) {
                int kk = t * 16 + (lane & 7) + ((lane >> 3) & 1) * 8;
                int nn = n * 16 + (lane >> 4) * 8;
                uint32_t so = (uint32_t)(kk * QS + nn) * 2;
                uint32_t vh[4];
                ldm4t(vh, base + oVh + so);
                mma_bf16(oacc[2*n],   wh, vh + 0);
                mma_bf16(oacc[2*n],   wl, vh + 0);
                mma_bf16(oacc[2*n+1], wh, vh + 2);
                mma_bf16(oacc[2*n+1], wl, vh + 2);
            }
        }
        __syncthreads();
        st ^= 1;
    }

    p0 += __shfl_xor_sync(0xFFFFFFFFu, p0, 1);
    p0 += __shfl_xor_sync(0xFFFFFFFFu, p0, 2);
    p1 += __shfl_xor_sync(0xFFFFFFFFu, p1, 1);
    p1 += __shfl_xor_sync(0xFFFFFFFFu, p1, 2);
    float rd0 = 1.0f / (p0 + 1.0f);
    float rd1 = 1.0f / (p1 + 1.0f);

    int r0 = q0 + w * 16 + (lane >> 2);
    int r1 = r0 + 8;
    #pragma unroll
    for (int j = 0; j < 8; j++) {
        int d = j * 8 + (lane & 3) * 2;
        size_t i0 = rowbase + (size_t)r0 * DD + d;
        size_t i1 = rowbase + (size_t)r1 * DD + d;
        uint32_t vh0 = *(const uint32_t*)(Vh + i0), vl0 = *(const uint32_t*)(Vl + i0);
        uint32_t vh1 = *(const uint32_t*)(Vh + i1), vl1 = *(const uint32_t*)(Vl + i1);
        float vp00 = __bfloat162float(__ushort_as_bfloat16((unsigned short)(vh0 & 0xFFFF))) +
                     __bfloat162float(__ushort_as_bfloat16((unsigned short)(vl0 & 0xFFFF)));
        float vp01 = __bfloat162float(__ushort_as_bfloat16((unsigned short)(vh0 >> 16))) +
                     __bfloat162float(__ushort_as_bfloat16((unsigned short)(vl0 >> 16)));
        float vp10 = __bfloat162float(__ushort_as_bfloat16((unsigned short)(vh1 & 0xFFFF))) +
                     __bfloat162float(__ushort_as_bfloat16((unsigned short)(vl1 & 0xFFFF)));
        float vp11 = __bfloat162float(__ushort_as_bfloat16((unsigned short)(vh1 >> 16))) +
                     __bfloat162float(__ushort_as_bfloat16((unsigned short)(vl1 >> 16)));
        float m00 = oacc[j][0] * rd0 - vp00;
        float m01 = oacc[j][1] * rd0 - vp01;
        float m10 = oacc[j][2] * rd1 - vp10;
        float m11 = oacc[j][3] * rd1 - vp11;
        h16 h0, h1, l0, l1;
        split1h(m00, h0, l0); split1h(m01, h1, l1);
        *(uint32_t*)(Mh + i0) = pack2h(h0, h1);
        *(uint32_t*)(Ml + i0) = pack2h(l0, l1);
        split1h(m10, h0, l0); split1h(m11, h1, l1);
        *(uint32_t*)(Mh + i1) = pack2h(h0, h1);
        *(uint32_t*)(Ml + i1) = pack2h(l0, l1);
    }
}

// ---------------- LM head: 256x128 tiles, 512 threads, fp16x2 -----------------
__device__ __forceinline__ void stage_lm(
    uint32_t base, int st, int kc, int tid, int m0, int n0,
    const h16* __restrict__ Ah, const h16* __restrict__ Al)
{
    constexpr uint32_t ASZ = 256 * AMS, BSZ = 128 * AMS;
    const uint32_t oAh = 0, oAl = 2 * ASZ * 2, oB = 4 * ASZ * 2;
    #pragma unroll
    for (int it2 = 0; it2 < 2; it2++) {
        int g = tid + 512 * it2;
        int row = g >> 2, c8 = (g & 3) * 8;
        uint32_t so = (uint32_t)(st * ASZ + row * AMS + c8) * 2;
        size_t ga = (size_t)(m0 + row) * DD + kc * 32 + c8;
        cpa16(base + oAh + so, Ah + ga);
        cpa16(base + oAl + so, Al + ga);
    }
    {
        int g = tid;
        int row = g >> 2, c8 = (g & 3) * 8;
        uint32_t so = (uint32_t)(st * BSZ + row * AMS + c8) * 2;
        size_t gb = (size_t)(n0 + row) * DD + kc * 32 + c8;
        cpa16(base + oB + so, g_LMh + gb);
    }
}

__global__ void __launch_bounds__(512)
lm_head_mma(const h16* __restrict__ Ah, const h16* __restrict__ Al,
            float* __restrict__ C)
{
    extern __shared__ __align__(16) h16 dsm[];
    constexpr uint32_t ASZ = 256 * AMS, BSZ = 128 * AMS;
    const uint32_t base = smem_u32(dsm);
    const uint32_t oAh = 0, oAl = 2 * ASZ * 2, oB = 4 * ASZ * 2;
    const int tid = threadIdx.x, lane = tid & 31, wid = tid >> 5;
    const int warp_m = wid >> 1, warp_n = wid & 1;
    const int m0 = blockIdx.y * 256, n0 = blockIdx.x * 128;

    float acc[2][8][4];
    #pragma unroll
    for (int i = 0; i < 2; i++)
        #pragma unroll
        for (int j = 0; j < 8; j++)
            #pragma unroll
            for (int q = 0; q < 4; q++) acc[i][j][q] = 0.0f;

    stage_lm(base, 0, 0, tid, m0, n0, Ah, Al);
    CP_COMMIT();

    int st = 0;
    for (int kc = 0; kc < 16; kc++) {
        if (kc + 1 < 16) {
            stage_lm(base, st ^ 1, kc + 1, tid, m0, n0, Ah, Al);
            CP_COMMIT();
            CP_WAIT1();
        } else {
            CP_WAIT0();
        }
        __syncthreads();

        #pragma unroll
        for (int s = 0; s < 2; s++) {
            uint32_t ah[2][4], al[2][4], bh[8][2];
            #pragma unroll
            for (int i = 0; i < 2; i++) {
                int r  = warp_m * 32 + i * 16 + (lane & 15);
                int kb = s * 16 + ((lane >> 4) << 3);
                uint32_t so = (uint32_t)(st * ASZ + r * AMS + kb) * 2;
                ldm4(ah[i], base + oAh + so);
                ldm4(al[i], base + oAl + so);
            }
            #pragma unroll
            for (int j = 0; j < 4; j++) {
                int r  = warp_n * 64 + j * 16 + (lane & 7) + ((lane >> 4) << 3);
                int kb = s * 16 + (((lane >> 3) & 1) << 3);
                uint32_t so = (uint32_t)(st * BSZ + r * AMS + kb) * 2;
                uint32_t q[4];
                ldm4(q, base + oB + so);
                bh[2*j][0] = q[0]; bh[2*j][1] = q[1];
                bh[2*j+1][0] = q[2]; bh[2*j+1][1] = q[3];
            }
            #pragma unroll
            for (int i = 0; i < 2; i++)
                #pragma unroll
                for (int j = 0; j < 8; j++) {
                    mma_f16(acc[i][j], ah[i], bh[j]);
                    mma_f16(acc[i][j], al[i], bh[j]);
                }
        }
        __syncthreads();
        st ^= 1;
    }

    #pragma unroll
    for (int i = 0; i < 2; i++) {
        int m = m0 + warp_m * 32 + i * 16 + (lane >> 2);
        #pragma unroll
        for (int j = 0; j < 8; j++) {
            int n = n0 + warp_n * 64 + j * 8 + (lane & 3) * 2;
            *(float2*)(C + (size_t)m * VV + n) =
                make_float2(acc[i][j][0], acc[i][j][1]);
            *(float2*)(C + (size_t)(m + 8) * VV + n) =
                make_float2(acc[i][j][2], acc[i][j][3]);
        }
    }
}

// ---------------- init -------------------------------------------------------
__global__ void init_kernel(const int* __restrict__ inputs,
                            const int* __restrict__ carry_inputs,
                            const void* __restrict__ halted,
                            const float* __restrict__ carry_hidden,
                            const float* __restrict__ init_hidden,
                            const float* __restrict__ emb,
                            const float* __restrict__ pos,
                            const float* __restrict__ in_s,
                            const float* __restrict__ in_b)
{
    int r = blockIdx.x;
    int b = r / NN, n = r % NN;
    int t = threadIdx.x;
    bool h = read_halted(halted, b);
    int idx = h ? inputs[r] : carry_inputs[r];
    const float* e = emb + (size_t)idx * DD;
    const float* p = pos + (size_t)n * DD;

    float x0 = e[t]       + p[t];
    float x1 = e[t + 256] + p[t + 256];

    size_t base = (size_t)r * DD;
    g_Q[base + t]       = h ? init_hidden[t]       : carry_hidden[base + t];
    g_Q[base + t + 256] = h ? init_hidden[t + 256] : carry_hidden[base + t + 256];

    __shared__ float s_sum[256], s_sq[256];
    s_sum[t] = x0 + x1;
    s_sq[t]  = x0 * x0 + x1 * x1;
    __syncthreads();
    for (int o = 128; o > 0; o >>= 1) {
        if (t < o) { s_sum[t] += s_sum[t + o]; s_sq[t] += s_sq[t + o]; }
        __syncthreads();
    }
    float mu   = s_sum[0] * (1.0f / DD);
    float var  = s_sq[0] * (1.0f / DD) - mu * mu;
    float rstd = rsqrtf(var + 1e-5f);
    g_X[base + t]       = (x0 - mu) * rstd * in_s[t]       + in_b[t];
    g_X[base + t + 256] = (x1 - mu) * rstd * in_s[t + 256] + in_b[t + 256];
}

// ---------------- LayerNorm: warp-per-row, 8 rows/CTA -------------------------
__global__ void __launch_bounds__(256) ln_kernel(
    const float* __restrict__ in, float* __restrict__ outf,
    h16* __restrict__ outh, h16* __restrict__ outl,
    const float* __restrict__ s, const float* __restrict__ bia,
    const float* __restrict__ add)
{
    const int warp = threadIdx.x >> 5, lane = threadIdx.x & 31;
    const int r = blockIdx.x * 8 + warp;
    const size_t base = (size_t)r * DD;

    float x[16];
    float sum = 0.0f, sq = 0.0f;
    #pragma unroll
    for (int i = 0; i < 4; i++) {
        float4 v = *(const float4*)(in + base + lane * 4 + i * 128);
        x[4*i+0] = v.x; x[4*i+1] = v.y; x[4*i+2] = v.z; x[4*i+3] = v.w;
        sum += v.x + v.y + v.z + v.w;
        sq  += v.x*v.x + v.y*v.y + v.z*v.z + v.w*v.w;
    }
    #pragma unroll
    for (int o = 16; o > 0; o >>= 1) {
        sum += __shfl_xor_sync(0xFFFFFFFFu, sum, o);
        sq  += __shfl_xor_sync(0xFFFFFFFFu, sq,  o);
    }
    float mu   = sum * (1.0f / DD);
    float var  = sq * (1.0f / DD) - mu * mu;
    float rstd = rsqrtf(var + 1e-5f);

    #pragma unroll
    for (int i = 0; i < 4; i++) {
        int c = lane * 4 + i * 128;
        float4 sv = *(const float4*)(s + c);
        float4 bv = *(const float4*)(bia + c);
        float v0 = (x[4*i+0] - mu) * rstd * sv.x + bv.x;
        float v1 = (x[4*i+1] - mu) * rstd * sv.y + bv.y;
        float v2 = (x[4*i+2] - mu) * rstd * sv.z + bv.z;
        float v3 = (x[4*i+3] - mu) * rstd * sv.w + bv.w;
        if (add) {
            float4 av = *(const float4*)(add + base + c);
            v0 += av.x; v1 += av.y; v2 += av.z; v3 += av.w;
        }
        if (outf) *(float4*)(outf + base + c) = make_float4(v0, v1, v2, v3);
        if (outh) {
            h16 h0, l0, h1, l1, h2, l2, h3, l3;
            split1h(v0, h0, l0); split1h(v1, h1, l1);
            split1h(v2, h2, l2); split1h(v3, h3, l3);
            *(uint2*)(outh + base + c) = make_uint2(pack2h(h0, h1), pack2h(h2, h3));
            *(uint2*)(outl + base + c) = make_uint2(pack2h(l0, l1), pack2h(l2, l3));
        }
    }
}

// ---------------- depthwise conv k=3 + bias + silu -> fp16 hi/lo --------------
__global__ void conv_kernel(const float* __restrict__ Hf, const float* __restrict__ w,
                            const float* __restrict__ bias,
                            h16* __restrict__ outh, h16* __restrict__ outl)
{
    size_t i = (size_t)blockIdx.x * 256 + threadIdx.x;
    if (i >= (size_t)MROWS * INNER) return;
    size_t row = i / INNER;
    int c = (int)(i % INNER);
    int n = (int)(row % NN);
    const float* wc = w + (size_t)c * CKW;
    float acc = bias[c];
    if (n > 0)      acc += wc[0] * Hf[(row - 1) * INNER + c];
    acc += wc[1] * Hf[row * INNER + c];
    if (n < NN - 1) acc += wc[2] * Hf[(row + 1) * INNER + c];
    float v = siluf(acc);
    h16 h, l;
    split1h(v, h, l);
    outh[i] = h;
    outl[i] = l;
}

// ---------------- halt head --------------------------------------------------
__global__ void halt_kernel(const float* __restrict__ Qn, const float* __restrict__ hw,
                            const float* __restrict__ hb, float* __restrict__ out)
{
    int b = blockIdx.x;
    int t = threadIdx.x;
    __shared__ float md[DD];
    for (int d = t; d < DD; d += 256) {
        float s = 0.0f;
        for (int n = 0; n < NN; n++)
            s += Qn[((size_t)(b * NN + n)) * DD + d];
        md[d] = s * (1.0f / NN);
    }
    __syncthreads();
    __shared__ float r0[256], r1[256];
    float p0 = 0.0f, p1 = 0.0f;
    for (int d = t; d < DD; d += 256) {
        p0 += md[d] * hw[d];
        p1 += md[d] * hw[DD + d];
    }
    r0[t] = p0; r1[t] = p1;
    __syncthreads();
    for (int o = 128; o > 0; o >>= 1) {
        if (t < o) { r0[t] += r0[t + o]; r1[t] += r1[t + o]; }
        __syncthreads();
    }
    if (t == 0) {
        out[b * 2 + 0] = r0[0] + hb[0];
        out[b * 2 + 1] = r1[0] + hb[1];
    }
}

// ---------------- host orchestration -----------------------------------------
static void cvt_h(const float* src, h16* d, size_t n)
{
    int n4 = (int)(n / 4);
    cvt_h_kernel<<<(n4 + 255) / 256, 256>>>(src, d, n4);
}

extern "C" void kernel_launch(void* const* d_in, const int* in_sizes, int n_in,
                              void* d_out, int out_size)
{
    const int*   inputs       = (const int*)d_in[0];
    const float* carry_hidden = (const float*)d_in[2];
    const void*  halted       = d_in[4];
    const int*   carry_inputs = (const int*)d_in[5];
    const float* init_hidden  = (const float*)d_in[7];
    const float* emb          = (const float*)d_in[8];
    const float* pos          = (const float*)d_in[9];
    const float* in_s         = (const float*)d_in[10];
    const float* in_b         = (const float*)d_in[11];
    const float* fin_s        = (const float*)d_in[12];
    const float* fin_b        = (const float*)d_in[13];
    const float* lm_w         = (const float*)d_in[14];
    const float* halt_w       = (const float*)d_in[15];
    const float* halt_b       = (const float*)d_in[16];
    const float* dt           = (const float*)d_in[17];
    const float* W_Q          = (const float*)d_in[18];
    const float* W_K          = (const float*)d_in[19];
    const float* W_V          = (const float*)d_in[20];
    const float* W_O          = (const float*)d_in[21];
    const float* W_up         = (const float*)d_in[22];
    const float* dw_w         = (const float*)d_in[23];
    const float* dw_b         = (const float*)d_in[24];
    const float* W_down       = (const float*)d_in[25];
    const float* n1_s         = (const float*)d_in[26];
    const float* n1_b         = (const float*)d_in[27];
    const float* n2_s         = (const float*)d_in[28];
    const float* n2_b         = (const float*)d_in[29];

    float *X, *Q, *Qi, *Qn, *Hf;
    h16 *Hch, *Hcl, *mbh, *mbl, *Q2h, *Q2l, *Hvh, *Hvl, *Qnh, *Qnl;
    bf16 *PQh, *PQl, *PKh, *Vh, *Vl;
    h16 *WQh, *WKh, *WVh, *WOh, *WUh, *WDh, *LMh;
    cudaGetSymbolAddress((void**)&X,   g_X);
    cudaGetSymbolAddress((void**)&Q,   g_Q);
    cudaGetSymbolAddress((void**)&Qi,  g_Qi);
    cudaGetSymbolAddress((void**)&Qn,  g_Qn);
    cudaGetSymbolAddress((void**)&Hf,  g_Hf);
    cudaGetSymbolAddress((void**)&Hch, g_Hch); cudaGetSymbolAddress((void**)&Hcl, g_Hcl);
    cudaGetSymbolAddress((void**)&PQh, g_PQh); cudaGetSymbolAddress((void**)&PQl, g_PQl);
    cudaGetSymbolAddress((void**)&PKh, g_PKh);
    cudaGetSymbolAddress((void**)&Vh,  g_Vh);  cudaGetSymbolAddress((void**)&Vl,  g_Vl);
    cudaGetSymbolAddress((void**)&mbh, g_mbh); cudaGetSymbolAddress((void**)&mbl, g_mbl);
    cudaGetSymbolAddress((void**)&Q2h, g_Q2h); cudaGetSymbolAddress((void**)&Q2l, g_Q2l);
    cudaGetSymbolAddress((void**)&Hvh, g_Hvh); cudaGetSymbolAddress((void**)&Hvl, g_Hvl);
    cudaGetSymbolAddress((void**)&Qnh, g_Qnh); cudaGetSymbolAddress((void**)&Qnl, g_Qnl);
    cudaGetSymbolAddress((void**)&WQh, g_WQh);
    cudaGetSymbolAddress((void**)&WKh, g_WKh);
    cudaGetSymbolAddress((void**)&WVh, g_WVh);
    cudaGetSymbolAddress((void**)&WOh, g_WOh);
    cudaGetSymbolAddress((void**)&WUh, g_WUh);
    cudaGetSymbolAddress((void**)&WDh, g_WDh);
    cudaGetSymbolAddress((void**)&LMh, g_LMh);

    float* out = (float*)d_out;

    cudaFuncSetAttribute(attn_fused, cudaFuncAttributeMaxDynamicSharedMemorySize, ATT_SMEM);
    cudaFuncSetAttribute(mma_proj,   cudaFuncAttributeMaxDynamicSharedMemorySize, SM_G128);
    cudaFuncSetAttribute(mma_up,     cudaFuncAttributeMaxDynamicSharedMemorySize, SM_G128);
    cudaFuncSetAttribute(mma_wo,     cudaFuncAttributeMaxDynamicSharedMemorySize, SM_G64);
    cudaFuncSetAttribute(mma_down,   cudaFuncAttributeMaxDynamicSharedMemorySize, SM_G64);
    cudaFuncSetAttribute(lm_head_mma, cudaFuncAttributeMaxDynamicSharedMemorySize, SM_LM);

    cvt_h(W_Q,    WQh, (size_t)KKB * DD * DD);
    cvt_h(W_K,    WKh, (size_t)KKB * DD * DD);
    cvt_h(W_V,    WVh, (size_t)KKB * DD * DD);
    cvt_h(W_O,    WOh, (size_t)KKB * DD * DD);
    {
        int total = KKB * DD * (2 * INNER) / 8;
        cvt_up_kernel<<<(total + 255) / 256, 256>>>(W_up, WUh);
    }
    cvt_h(W_down, WDh, (size_t)KKB * INNER * DD);
    cvt_h(lm_w,   LMh, (size_t)VV * DD);

    init_kernel<<<MROWS, 256>>>(inputs, carry_inputs, halted, carry_hidden,
                                init_hidden, emb, pos, in_s, in_b);

    dim3 gP(DD / 128, MROWS / 128, 3);        // (4, 16, 3)
    dim3 gO64(DD / 64, MROWS / 128);          // (8, 16) = 128 CTAs
    dim3 gUP(2 * INNER / 128, MROWS / 128);   // (24, 16)
    dim3 gAT(NN / 128, BHN);                  // (8, 16)
    const int gLN = MROWS / 8;                // 256 CTAs, warp-per-row

    for (int it = 0; it < TOTAL_PASSES; it++) {
        int k = it % KKB;

        ln_kernel<<<gLN, 256>>>(Q, nullptr, Hch, Hcl,
                                n1_s + k * DD, n1_b + k * DD, X);

        mma_proj<<<gP, 256, SM_G128>>>(Hch, Hcl, k);

        attn_fused<<<gAT, 256, ATT_SMEM>>>(PQh, PQl, PKh, Vh, Vl, mbh, mbl);

        mma_wo<<<gO64, 256, SM_G64>>>(mbh, mbl, k, Qi, Q, dt);

        ln_kernel<<<gLN, 256>>>(Qi, nullptr, Q2h, Q2l,
                                n2_s + k * DD, n2_b + k * DD, nullptr);
        mma_up<<<gUP, 256, SM_G128>>>(Q2h, Q2l, k, Hf);    // fused swiglu
        int tot = MROWS * INNER;
        conv_kernel<<<(tot + 255) / 256, 256>>>(Hf, dw_w + (size_t)k * INNER * CKW,
                                                dw_b + (size_t)k * INNER, Hvh, Hvl);
        mma_down<<<gO64, 256, SM_G64>>>(Hvh, Hvl, k, Q, Qi);
    }

    ln_kernel<<<gLN, 256>>>(Q, Qn, Qnh, Qnl, fin_s, fin_b, nullptr);
    dim3 gLM(VV / 128, MROWS / 256);          // (250, 8)
    lm_head_mma<<<gLM, 512, SM_LM>>>(Qnh, Qnl, out);
    halt_kernel<<<BB, 256>>>(Qn, halt_w, halt_b, out + (size_t)MROWS * VV);
}

// round 17
// speedup vs baseline: 1.1836x; 1.0846x over previous
#include <cuda_runtime.h>
#include <cuda_bf16.h>
#include <cuda_fp16.h>
#include <math.h>
#include <stdint.h>

// Problem constants
#define BB    2
#define NN    1024
#define DD    512
#define HH    8
#define DH    64
#define KKB   4
#define VV    32000
#define INNER 1536
#define CKW   3
#define MROWS (BB*NN)     // 2048
#define BHN   (BB*HH)     // 16
#define TOTAL_PASSES 8

#define AMS  72    // A smem stride for 64-wide K chunk (64 + 8)
#define QS   72    // attention smem stride (64 + 8)

typedef __nv_bfloat16 bf16;
typedef __half h16;

// ---------------- fp32 scratch ----------------------------------------------
__device__ __align__(16) float g_X  [MROWS*DD];
__device__ __align__(16) float g_Q  [MROWS*DD];
__device__ __align__(16) float g_Qi [MROWS*DD];
__device__ __align__(16) float g_Qn [MROWS*DD];
__device__ __align__(16) float g_Hf [(size_t)MROWS*INNER];

// ---------------- activation scratch -----------------------------------------
__device__ __align__(16) h16 g_Hch [MROWS*DD], g_Hcl [MROWS*DD];
__device__ __align__(16) h16 g_mbh [MROWS*DD], g_mbl [MROWS*DD];
__device__ __align__(16) h16 g_Q2h [MROWS*DD], g_Q2l [MROWS*DD];
__device__ __align__(16) h16 g_Hvh [(size_t)MROWS*INNER], g_Hvl [(size_t)MROWS*INNER];
__device__ __align__(16) h16 g_Qnh [MROWS*DD], g_Qnl [MROWS*DD];
__device__ __align__(16) bf16 g_PQh [MROWS*DD], g_PQl [MROWS*DD];
__device__ __align__(16) bf16 g_PKh [MROWS*DD];
__device__ __align__(16) bf16 g_Vh  [MROWS*DD], g_Vl  [MROWS*DD];

// ---------------- single-fp16 weight scratch ---------------------------------
__device__ __align__(16) h16 g_WQh [KKB*DD*DD];
__device__ __align__(16) h16 g_WKh [KKB*DD*DD];
__device__ __align__(16) h16 g_WVh [KKB*DD*DD];
__device__ __align__(16) h16 g_WOh [KKB*DD*DD];
__device__ __align__(16) h16 g_WUh [(size_t)KKB*DD*2*INNER];
__device__ __align__(16) h16 g_WDh [(size_t)KKB*INNER*DD];
__device__ __align__(16) h16 g_LMh [(size_t)VV*DD];

// ---------------- helpers ----------------------------------------------------
__device__ __forceinline__ float siluf(float x) { return x / (1.0f + expf(-x)); }

__device__ __forceinline__ bool read_halted(const void* p, int b)
{
    const unsigned char* u8 = (const unsigned char*)p;
    if (u8[1] != 0) return u8[b] != 0;
    return ((const int*)p)[b] != 0;
}
__device__ __forceinline__ uint32_t smem_u32(const void* p) {
    uint32_t a;
    asm("{ .reg .u64 t; cvta.to.shared.u64 t, %1; cvt.u32.u64 %0, t; }"
        : "=r"(a) : "l"(p));
    return a;
}
__device__ __forceinline__ void ldm4(uint32_t* r, uint32_t a) {
    asm volatile("ldmatrix.sync.aligned.m8n8.x4.shared.b16 {%0,%1,%2,%3}, [%4];"
                 : "=r"(r[0]), "=r"(r[1]), "=r"(r[2]), "=r"(r[3]) : "r"(a));
}
__device__ __forceinline__ void ldm4t(uint32_t* r, uint32_t a) {
    asm volatile("ldmatrix.sync.aligned.m8n8.x4.trans.shared.b16 {%0,%1,%2,%3}, [%4];"
                 : "=r"(r[0]), "=r"(r[1]), "=r"(r[2]), "=r"(r[3]) : "r"(a));
}
__device__ __forceinline__ void mma_bf16(float* c, const uint32_t* a, const uint32_t* b) {
    asm volatile("mma.sync.aligned.m16n8k16.row.col.f32.bf16.bf16.f32 "
                 "{%0,%1,%2,%3}, {%4,%5,%6,%7}, {%8,%9}, {%0,%1,%2,%3};"
                 : "+f"(c[0]), "+f"(c[1]), "+f"(c[2]), "+f"(c[3])
                 : "r"(a[0]), "r"(a[1]), "r"(a[2]), "r"(a[3]),
                   "r"(b[0]), "r"(b[1]));
}
__device__ __forceinline__ void mma_f16(float* c, const uint32_t* a, const uint32_t* b) {
    asm volatile("mma.sync.aligned.m16n8k16.row.col.f32.f16.f16.f32 "
                 "{%0,%1,%2,%3}, {%4,%5,%6,%7}, {%8,%9}, {%0,%1,%2,%3};"
                 : "+f"(c[0]), "+f"(c[1]), "+f"(c[2]), "+f"(c[3])
                 : "r"(a[0]), "r"(a[1]), "r"(a[2]), "r"(a[3]),
                   "r"(b[0]), "r"(b[1]));
}
__device__ __forceinline__ uint32_t pack2(bf16 a, bf16 b) {
    return (uint32_t)__bfloat16_as_ushort(a) |
           ((uint32_t)__bfloat16_as_ushort(b) << 16);
}
__device__ __forceinline__ uint32_t pack2h(h16 a, h16 b) {
    return (uint32_t)__half_as_ushort(a) |
           ((uint32_t)__half_as_ushort(b) << 16);
}
__device__ __forceinline__ void split1(float v, bf16& h, bf16& l) {
    h = __float2bfloat16(v);
    l = __float2bfloat16(v - __bfloat162float(h));
}
__device__ __forceinline__ void split1h(float v, h16& h, h16& l) {
    h = __float2half_rn(v);
    l = __float2half_rn(v - __half2float(h));
}
__device__ __forceinline__ void cpa16(uint32_t s, const void* g) {
    asm volatile("cp.async.cg.shared.global [%0], [%1], 16;" :: "r"(s), "l"(g));
}
#define CP_COMMIT() asm volatile("cp.async.commit_group;" ::: "memory")
#define CP_WAIT0()  asm volatile("cp.async.wait_group 0;" ::: "memory")
#define CP_WAIT1()  asm volatile("cp.async.wait_group 1;" ::: "memory")

// ---------------- converters --------------------------------------------------
__global__ void cvt_h_kernel(const float* __restrict__ src, h16* __restrict__ d, int n4)
{
    int i = blockIdx.x * 256 + threadIdx.x;
    if (i >= n4) return;
    float4 v = *(const float4*)(src + (size_t)i * 4);
    uint2 o;
    o.x = pack2h(__float2half_rn(v.x), __float2half_rn(v.y));
    o.y = pack2h(__float2half_rn(v.z), __float2half_rn(v.w));
    *(uint2*)(d + (size_t)i * 4) = o;
}

__global__ void cvt_up_kernel(const float* __restrict__ src, h16* __restrict__ d)
{
    int gi = blockIdx.x * 256 + threadIdx.x;
    int total = KKB * DD * (2 * INNER) / 8;
    if (gi >= total) return;
    int cg8 = gi % (2 * INNER / 8);
    int row = gi / (2 * INNER / 8);
    int cg = cg8 * 4;
    size_t rb = (size_t)row * (2 * INNER);
    float4 gsrc = *(const float4*)(src + rb + cg);
    float4 usrc = *(const float4*)(src + rb + INNER + cg);
    float gv[4] = {gsrc.x, gsrc.y, gsrc.z, gsrc.w};
    float uv[4] = {usrc.x, usrc.y, usrc.z, usrc.w};
    uint32_t w[4];
    #pragma unroll
    for (int q = 0; q < 4; q++)
        w[q] = pack2h(__float2half_rn(gv[q]), __float2half_rn(uv[q]));
    size_t db = rb + (size_t)cg8 * 8;
    *(uint4*)(d + db) = make_uint4(w[0], w[1], w[2], w[3]);
}

// ---------------- 2-stage pipelined fp16x2 GEMM body, K-chunk = 64 -----------
// A: fp16 hi/lo [M,K]; B: single fp16 [K,N] (trans ldmatrix).
// smem: [Ah s0 | Ah s1 | Al s0 | Al s1 | B s0 | B s1]
template <int BN>
__device__ __forceinline__ void stage_gemm(
    uint32_t base, int st, int kc, int tid, int m0, int n0,
    const h16* __restrict__ Ah, const h16* __restrict__ Al, int lda,
    const h16* __restrict__ B, int ldb)
{
    constexpr int BNS_ = (BN == 128) ? 136 : 72;
    constexpr uint32_t ASZ = 128 * AMS, BSZ = 64 * BNS_;
    const uint32_t oAh = 0, oAl = 2 * ASZ * 2, oB = 4 * ASZ * 2;
    #pragma unroll
    for (int it2 = 0; it2 < 4; it2++) {        // 128x64 A: 1024 groups
        int g = tid + 256 * it2;
        int row = g >> 3, c8 = (g & 7) * 8;
        size_t go = (size_t)(m0 + row) * lda + kc * 64 + c8;
        uint32_t so = (uint32_t)(st * ASZ + row * AMS + c8) * 2;
        cpa16(base + oAh + so, Ah + go);
        cpa16(base + oAl + so, Al + go);
    }
    {
        if (BN == 128) {                       // 64x128 B: 1024 groups
            #pragma unroll
            for (int it2 = 0; it2 < 4; it2++) {
                int g = tid + 256 * it2;
                int row = g >> 4, c8 = (g & 15) * 8;
                size_t go = (size_t)(kc * 64 + row) * ldb + n0 + c8;
                uint32_t so = (uint32_t)(st * BSZ + row * BNS_ + c8) * 2;
                cpa16(base + oB + so, B + go);
            }
        } else {                               // 64x64 B: 512 groups
            #pragma unroll
            for (int it2 = 0; it2 < 2; it2++) {
                int g = tid + 256 * it2;
                int row = g >> 3, c8 = (g & 7) * 8;
                size_t go = (size_t)(kc * 64 + row) * ldb + n0 + c8;
                uint32_t so = (uint32_t)(st * BSZ + row * BNS_ + c8) * 2;
                cpa16(base + oB + so, B + go);
            }
        }
    }
}

// epi: 0 fp32, 1 bf16 hi/lo elu+1, 2 fp32 addP+alpha*acc, 3 fp32 addP+acc,
//      4 bf16 hi/lo plain, 5 fused swiglu -> fp32 Hf, 6 bf16 HI-ONLY elu+1
template <int BN>
__device__ __forceinline__ void gemm_pipe(
    h16* smem,
    const h16* __restrict__ Ah, const h16* __restrict__ Al, int lda,
    const h16* __restrict__ B, int ldb,
    float* __restrict__ Cf, bf16* __restrict__ Ch, bf16* __restrict__ Cl, int ldc,
    int m0, int n0, int kch, int epi, const float* __restrict__ addP, float alpha)
{
    constexpr int BNS_ = (BN == 128) ? 136 : 72;
    constexpr int NJ = BN / 16;
    constexpr uint32_t ASZ = 128 * AMS, BSZ = 64 * BNS_;
    const uint32_t base = smem_u32(smem);
    const uint32_t oAh = 0, oAl = 2 * ASZ * 2, oB = 4 * ASZ * 2;
    const int tid = threadIdx.x, lane = tid & 31, wid = tid >> 5;
    const int warp_m = wid >> 1, warp_n = wid & 1;

    float acc[2][NJ][4];
    #pragma unroll
    for (int i = 0; i < 2; i++)
        #pragma unroll
        for (int j = 0; j < NJ; j++)
            #pragma unroll
            for (int q = 0; q < 4; q++) acc[i][j][q] = 0.0f;

    stage_gemm<BN>(base, 0, 0, tid, m0, n0, Ah, Al, lda, B, ldb);
    CP_COMMIT();

    int st = 0;
    for (int kc = 0; kc < kch; kc++) {
        if (kc + 1 < kch) {
            stage_gemm<BN>(base, st ^ 1, kc + 1, tid, m0, n0, Ah, Al, lda, B, ldb);
            CP_COMMIT();
            CP_WAIT1();
        } else {
            CP_WAIT0();
        }
        __syncthreads();

        #pragma unroll
        for (int s = 0; s < 4; s++) {          // 4 k-steps of 16 per 64-chunk
            uint32_t ah[2][4], al[2][4], bh[NJ][2];
            #pragma unroll
            for (int i = 0; i < 2; i++) {
                int r  = warp_m * 32 + i * 16 + (lane & 15);
                int kb = s * 16 + ((lane >> 4) << 3);
                uint32_t so = (uint32_t)(st * ASZ + r * AMS + kb) * 2;
                ldm4(ah[i], base + oAh + so);
                ldm4(al[i], base + oAl + so);
            }
            #pragma unroll
            for (int j2 = 0; j2 < NJ / 2; j2++) {
                int kk = s * 16 + (lane & 7) + ((lane >> 3) & 1) * 8;
                int nn = warp_n * (BN / 2) + j2 * 16 + (lane >> 4) * 8;
                uint32_t so = (uint32_t)(st * BSZ + kk * BNS_ + nn) * 2;
                uint32_t q[4];
                ldm4t(q, base + oB + so);
                bh[2*j2][0] = q[0]; bh[2*j2][1] = q[1];
                bh[2*j2+1][0] = q[2]; bh[2*j2+1][1] = q[3];
            }
            #pragma unroll
            for (int i = 0; i < 2; i++)
                #pragma unroll
                for (int j = 0; j < NJ; j++) {
                    mma_f16(acc[i][j], ah[i], bh[j]);
                    mma_f16(acc[i][j], al[i], bh[j]);
                }
        }
        __syncthreads();
        st ^= 1;
    }

    #pragma unroll
    for (int i = 0; i < 2; i++) {
        int m = m0 + warp_m * 32 + i * 16 + (lane >> 2);
        #pragma unroll
        for (int j = 0; j < NJ; j++) {
            int n = n0 + warp_n * (BN / 2) + j * 8 + (lane & 3) * 2;
            float v0 = acc[i][j][0], v1 = acc[i][j][1];
            float v2 = acc[i][j][2], v3 = acc[i][j][3];
            if (epi == 5) {
                int col = n >> 1;
                Cf[(size_t)m * INNER + col]       = siluf(v0) * v1;
                Cf[(size_t)(m + 8) * INNER + col] = siluf(v2) * v3;
                continue;
            }
            size_t i0 = (size_t)m * ldc + n;
            size_t i1 = (size_t)(m + 8) * ldc + n;
            if (epi == 1 || epi == 4 || epi == 6) {
                if (epi != 4) {
                    v0 = (v0 > 0.f) ? v0 + 1.f : expf(v0);
                    v1 = (v1 > 0.f) ? v1 + 1.f : expf(v1);
                    v2 = (v2 > 0.f) ? v2 + 1.f : expf(v2);
                    v3 = (v3 > 0.f) ? v3 + 1.f : expf(v3);
                }
                bf16 h0, h1, h2, h3, l0, l1, l2, l3;
                split1(v0, h0, l0); split1(v1, h1, l1);
                split1(v2, h2, l2); split1(v3, h3, l3);
                *(uint32_t*)(Ch + i0) = pack2(h0, h1);
                *(uint32_t*)(Ch + i1) = pack2(h2, h3);
                if (epi != 6) {
                    *(uint32_t*)(Cl + i0) = pack2(l0, l1);
                    *(uint32_t*)(Cl + i1) = pack2(l2, l3);
                }
            } else {
                if (epi == 2) {
                    v0 = addP[i0] + alpha * v0; v1 = addP[i0+1] + alpha * v1;
                    v2 = addP[i1] + alpha * v2; v3 = addP[i1+1] + alpha * v3;
                } else if (epi == 3) {
                    v0 += addP[i0]; v1 += addP[i0+1];
                    v2 += addP[i1]; v3 += addP[i1+1];
                }
                *(float2*)(Cf + i0) = make_float2(v0, v1);
                *(float2*)(Cf + i1) = make_float2(v2, v3);
            }
        }
    }
}

// smem (bytes), K-chunk 64 (CORRECTED):
#define SM_G128 108544   // (4*128*72 + 2*64*136) * 2 = (36864 + 17408) * 2
#define SM_G64  92160    // (4*128*72 + 2*64*72) * 2
#define SM_LM   184320   // (4*256*72 + 2*128*72) * 2
#define ATT_SMEM 110592  // 6 * 128 * QS * 2

// ---------------- GEMM wrappers (2 CTAs/SM) -----------------------------------
__global__ void __launch_bounds__(256, 2) mma_proj(
    const h16* __restrict__ Ah, const h16* __restrict__ Al, int kIdx)
{
    extern __shared__ __align__(16) h16 dsm[];
    int z = blockIdx.z;
    size_t wo = (size_t)kIdx * DD * DD;
    const h16* B = (z == 0) ? g_WQh + wo : (z == 1) ? g_WKh + wo : g_WVh + wo;
    bf16* Ch = (z == 0) ? g_PQh : (z == 1) ? g_PKh : g_Vh;
    bf16* Cl = (z == 0) ? g_PQl : (z == 1) ? nullptr : g_Vl;
    int epi = (z == 0) ? 1 : (z == 1) ? 6 : 4;   // K: hi-only (lo never consumed)
    gemm_pipe<128>(dsm, Ah, Al, DD, B, DD,
                   nullptr, Ch, Cl, DD, blockIdx.y * 128, blockIdx.x * 128,
                   DD / 64, epi, nullptr, 0.f);
}

__global__ void __launch_bounds__(256, 2) mma_wo(
    const h16* __restrict__ Ah, const h16* __restrict__ Al, int kIdx,
    float* __restrict__ C, const float* __restrict__ addP,
    const float* __restrict__ dt)
{
    extern __shared__ __align__(16) h16 dsm[];
    size_t wo = (size_t)kIdx * DD * DD;
    float d = dt[kIdx];
    float alpha = (d > 20.0f) ? d : log1pf(expf(d));
    gemm_pipe<64>(dsm, Ah, Al, DD, g_WOh + wo, DD,
                  C, nullptr, nullptr, DD, blockIdx.y * 128, blockIdx.x * 64,
                  DD / 64, 2, addP, alpha);
}

__global__ void __launch_bounds__(256, 2) mma_up(
    const h16* __restrict__ Ah, const h16* __restrict__ Al, int kIdx,
    float* __restrict__ Hf)
{
    extern __shared__ __align__(16) h16 dsm[];
    size_t wo = (size_t)kIdx * DD * 2 * INNER;
    gemm_pipe<128>(dsm, Ah, Al, DD, g_WUh + wo, 2 * INNER,
                   Hf, nullptr, nullptr, 2 * INNER, blockIdx.y * 128, blockIdx.x * 128,
                   DD / 64, 5, nullptr, 0.f);
}

__global__ void __launch_bounds__(256, 2) mma_down(
    const h16* __restrict__ Ah, const h16* __restrict__ Al, int kIdx,
    float* __restrict__ C, const float* __restrict__ addP)
{
    extern __shared__ __align__(16) h16 dsm[];
    size_t wo = (size_t)kIdx * INNER * DD;
    gemm_pipe<64>(dsm, Ah, Al, INNER, g_WDh + wo, DD,
                  C, nullptr, nullptr, DD, blockIdx.y * 128, blockIdx.x * 64,
                  INNER / 64, 3, addP, 0.f);
}

// ---------------- fused flash attention (2-term, unchanged from R15) ----------
__device__ __forceinline__ void stage_kv(
    uint32_t base, int st, int kt, int tid, size_t rowbase,
    const bf16* __restrict__ PKh, const bf16* __restrict__ Vh)
{
    const uint32_t QSZB = 128 * QS * 2;
    const uint32_t oKh = 2 * QSZB + st * QSZB;
    const uint32_t oVh = 4 * QSZB + st * QSZB;
    #pragma unroll
    for (int it2 = 0; it2 < 4; it2++) {
        int g = tid + 256 * it2;
        int row = g >> 3, c8 = (g & 7) * 8;
        size_t go = rowbase + (size_t)(kt * 128 + row) * DD + c8;
        uint32_t so = (uint32_t)(row * QS + c8) * 2;
        cpa16(base + oKh + so, PKh + go);
        cpa16(base + oVh + so, Vh + go);
    }
}

__global__ void __launch_bounds__(256) attn_fused(
    const bf16* __restrict__ PQh, const bf16* __restrict__ PQl,
    const bf16* __restrict__ PKh,
    const bf16* __restrict__ Vh,  const bf16* __restrict__ Vl,
    h16* __restrict__ Mh, h16* __restrict__ Ml)
{
    extern __shared__ __align__(16) bf16 dsmb[];
    const uint32_t base = smem_u32(dsmb);
    const uint32_t QSZB = 128 * QS * 2;

    const int tid = threadIdx.x, lane = tid & 31, w = tid >> 5;
    const int bh = blockIdx.y, b = bh >> 3, h = bh & 7;
    const int q0 = blockIdx.x * 128;
    const size_t rowbase = (size_t)(b * NN) * DD + h * DH;

    #pragma unroll
    for (int it2 = 0; it2 < 4; it2++) {
        int g = tid + 256 * it2;
        int row = g >> 3, c8 = (g & 7) * 8;
        size_t go = rowbase + (size_t)(q0 + row) * DD + c8;
        uint32_t so = (uint32_t)(row * QS + c8) * 2;
        cpa16(base + so, PQh + go);
        cpa16(base + QSZB + so, PQl + go);
    }
    stage_kv(base, 0, 0, tid, rowbase, PKh, Vh);
    CP_COMMIT();
    CP_WAIT0();
    __syncthreads();

    uint32_t qh[4][4], ql[4][4];
    #pragma unroll
    for (int s = 0; s < 4; s++) {
        int r  = w * 16 + (lane & 15);
        int kb = s * 16 + ((lane >> 4) << 3);
        uint32_t so = (uint32_t)(r * QS + kb) * 2;
        ldm4(qh[s], base + so);
        ldm4(ql[s], base + QSZB + so);
    }

    float oacc[8][4];
    #pragma unroll
    for (int j = 0; j < 8; j++)
        #pragma unroll
        for (int q = 0; q < 4; q++) oacc[j][q] = 0.0f;
    float p0 = 0.0f, p1 = 0.0f;

    int st = 0;
    for (int kt = 0; kt < NN / 128; kt++) {
        if (kt + 1 < NN / 128) {
            stage_kv(base, st ^ 1, kt + 1, tid, rowbase, PKh, Vh);
            CP_COMMIT();
            CP_WAIT1();
        } else {
            CP_WAIT0();
        }
        __syncthreads();

        const uint32_t oKh = 2 * QSZB + st * QSZB;
        const uint32_t oVh = 4 * QSZB + st * QSZB;

        #pragma unroll
        for (int t = 0; t < 8; t++) {
            float sacc[2][4] = {};
            #pragma unroll
            for (int s = 0; s < 4; s++) {
                int r  = t * 16 + (lane & 7) + ((lane >> 4) << 3);
                int kb = s * 16 + (((lane >> 3) & 1) << 3);
                uint32_t so = (uint32_t)(r * QS + kb) * 2;
                uint32_t kh[4];
                ldm4(kh, base + oKh + so);
                mma_bf16(sacc[0], qh[s], kh + 0);
                mma_bf16(sacc[0], ql[s], kh + 0);
                mma_bf16(sacc[1], qh[s], kh + 2);
                mma_bf16(sacc[1], ql[s], kh + 2);
            }
            float w2[2][4];
            #pragma unroll
            for (int f = 0; f < 2; f++)
                #pragma unroll
                for (int q = 0; q < 4; q++) {
                    float x = fmaxf(sacc[f][q], 0.0f);
                    w2[f][q] = x * x;
                }
            p0 += w2[0][0] + w2[0][1] + w2[1][0] + w2[1][1];
            p1 += w2[0][2] + w2[0][3] + w2[1][2] + w2[1][3];
            uint32_t wh[4], wl[4];
            {
                bf16 h0, h1, l0, l1;
                split1(w2[0][0], h0, l0); split1(w2[0][1], h1, l1);
                wh[0] = pack2(h0, h1); wl[0] = pack2(l0, l1);
                split1(w2[0][2], h0, l0); split1(w2[0][3], h1, l1);
                wh[1] = pack2(h0, h1); wl[1] = pack2(l0, l1);
                split1(w2[1][0], h0, l0); split1(w2[1][1], h1, l1);
                wh[2] = pack2(h0, h1); wl[2] = pack2(l0, l1);
                split1(w2[1][2], h0, l0); split1(w2[1][3], h1, l1);
                wh[3] = pack2(h0, h1); wl[3] = pack2(l0, l1);
            }
            #pragma unroll
            for (int n = 0; n < 4; n++) {
                int kk = t * 16 + (lane & 7) + ((lane >> 3) & 1) * 8;
                int nn = n * 16 + (lane >> 4) * 8;
                uint32_t so = (uint32_t)(kk * QS + nn) * 2;
                uint32_t vh[4];
                ldm4t(vh, base + oVh + so);
                mma_bf16(oacc[2*n],   wh, vh + 0);
                mma_bf16(oacc[2*n],   wl, vh + 0);
                mma_bf16(oacc[2*n+1], wh, vh + 2);
                mma_bf16(oacc[2*n+1], wl, vh + 2);
            }
        }
        __syncthreads();
        st ^= 1;
    }

    p0 += __shfl_xor_sync(0xFFFFFFFFu, p0, 1);
    p0 += __shfl_xor_sync(0xFFFFFFFFu, p0, 2);
    p1 += __shfl_xor_sync(0xFFFFFFFFu, p1, 1);
    p1 += __shfl_xor_sync(0xFFFFFFFFu, p1, 2);
    float rd0 = 1.0f / (p0 + 1.0f);
    float rd1 = 1.0f / (p1 + 1.0f);

    int r0 = q0 + w * 16 + (lane >> 2);
    int r1 = r0 + 8;
    #pragma unroll
    for (int j = 0; j < 8; j++) {
        int d = j * 8 + (lane & 3) * 2;
        size_t i0 = rowbase + (size_t)r0 * DD + d;
        size_t i1 = rowbase + (size_t)r1 * DD + d;
        uint32_t vh0 = *(const uint32_t*)(Vh + i0), vl0 = *(const uint32_t*)(Vl + i0);
        uint32_t vh1 = *(const uint32_t*)(Vh + i1), vl1 = *(const uint32_t*)(Vl + i1);
        float vp00 = __bfloat162float(__ushort_as_bfloat16((unsigned short)(vh0 & 0xFFFF))) +
                     __bfloat162float(__ushort_as_bfloat16((unsigned short)(vl0 & 0xFFFF)));
        float vp01 = __bfloat162float(__ushort_as_bfloat16((unsigned short)(vh0 >> 16))) +
                     __bfloat162float(__ushort_as_bfloat16((unsigned short)(vl0 >> 16)));
        float vp10 = __bfloat162float(__ushort_as_bfloat16((unsigned short)(vh1 & 0xFFFF))) +
                     __bfloat162float(__ushort_as_bfloat16((unsigned short)(vl1 & 0xFFFF)));
        float vp11 = __bfloat162float(__ushort_as_bfloat16((unsigned short)(vh1 >> 16))) +
                     __bfloat162float(__ushort_as_bfloat16((unsigned short)(vl1 >> 16)));
        float m00 = oacc[j][0] * rd0 - vp00;
        float m01 = oacc[j][1] * rd0 - vp01;
        float m10 = oacc[j][2] * rd1 - vp10;
        float m11 = oacc[j][3] * rd1 - vp11;
        h16 h0, h1, l0, l1;
        split1h(m00, h0, l0); split1h(m01, h1, l1);
        *(uint32_t*)(Mh + i0) = pack2h(h0, h1);
        *(uint32_t*)(Ml + i0) = pack2h(l0, l1);
        split1h(m10, h0, l0); split1h(m11, h1, l1);
        *(uint32_t*)(Mh + i1) = pack2h(h0, h1);
        *(uint32_t*)(Ml + i1) = pack2h(l0, l1);
    }
}

// ---------------- LM head: 256x128 tiles, 512 threads, K-chunk 64 -------------
__device__ __forceinline__ void stage_lm(
    uint32_t base, int st, int kc, int tid, int m0, int n0,
    const h16* __restrict__ Ah, const h16* __restrict__ Al)
{
    constexpr uint32_t ASZ = 256 * AMS, BSZ = 128 * AMS;
    const uint32_t oAh = 0, oAl = 2 * ASZ * 2, oB = 4 * ASZ * 2;
    #pragma unroll
    for (int it2 = 0; it2 < 4; it2++) {        // 256x64 A: 2048 groups
        int g = tid + 512 * it2;
        int row = g >> 3, c8 = (g & 7) * 8;
        uint32_t so = (uint32_t)(st * ASZ + row * AMS + c8) * 2;
        size_t ga = (size_t)(m0 + row) * DD + kc * 64 + c8;
        cpa16(base + oAh + so, Ah + ga);
        cpa16(base + oAl + so, Al + ga);
    }
    #pragma unroll
    for (int it2 = 0; it2 < 2; it2++) {        // 128x64 B: 1024 groups
        int g = tid + 512 * it2;
        int row = g >> 3, c8 = (g & 7) * 8;
        uint32_t so = (uint32_t)(st * BSZ + row * AMS + c8) * 2;
        size_t gb = (size_t)(n0 + row) * DD + kc * 64 + c8;
        cpa16(base + oB + so, g_LMh + gb);
    }
}

__global__ void __launch_bounds__(512)
lm_head_mma(const h16* __restrict__ Ah, const h16* __restrict__ Al,
            float* __restrict__ C)
{
    extern __shared__ __align__(16) h16 dsm[];
    constexpr uint32_t ASZ = 256 * AMS, BSZ = 128 * AMS;
    const uint32_t base = smem_u32(dsm);
    const uint32_t oAh = 0, oAl = 2 * ASZ * 2, oB = 4 * ASZ * 2;
    const int tid = threadIdx.x, lane = tid & 31, wid = tid >> 5;
    const int warp_m = wid >> 1, warp_n = wid & 1;
    const int m0 = blockIdx.y * 256, n0 = blockIdx.x * 128;

    float acc[2][8][4];
    #pragma unroll
    for (int i = 0; i < 2; i++)
        #pragma unroll
        for (int j = 0; j < 8; j++)
            #pragma unroll
            for (int q = 0; q < 4; q++) acc[i][j][q] = 0.0f;

    stage_lm(base, 0, 0, tid, m0, n0, Ah, Al);
    CP_COMMIT();

    int st = 0;
    for (int kc = 0; kc < 8; kc++) {
        if (kc + 1 < 8) {
            stage_lm(base, st ^ 1, kc + 1, tid, m0, n0, Ah, Al);
            CP_COMMIT();
            CP_WAIT1();
        } else {
            CP_WAIT0();
        }
        __syncthreads();

        #pragma unroll
        for (int s = 0; s < 4; s++) {
            uint32_t ah[2][4], al[2][4], bh[8][2];
            #pragma unroll
            for (int i = 0; i < 2; i++) {
                int r  = warp_m * 32 + i * 16 + (lane & 15);
                int kb = s * 16 + ((lane >> 4) << 3);
                uint32_t so = (uint32_t)(st * ASZ + r * AMS + kb) * 2;
                ldm4(ah[i], base + oAh + so);
                ldm4(al[i], base + oAl + so);
            }
            #pragma unroll
            for (int j = 0; j < 4; j++) {
                int r  = warp_n * 64 + j * 16 + (lane & 7) + ((lane >> 4) << 3);
                int kb = s * 16 + (((lane >> 3) & 1) << 3);
                uint32_t so = (uint32_t)(st * BSZ + r * AMS + kb) * 2;
                uint32_t q[4];
                ldm4(q, base + oB + so);
                bh[2*j][0] = q[0]; bh[2*j][1] = q[1];
                bh[2*j+1][0] = q[2]; bh[2*j+1][1] = q[3];
            }
            #pragma unroll
            for (int i = 0; i < 2; i++)
                #pragma unroll
                for (int j = 0; j < 8; j++) {
                    mma_f16(acc[i][j], ah[i], bh[j]);
                    mma_f16(acc[i][j], al[i], bh[j]);
                }
        }
        __syncthreads();
        st ^= 1;
    }

    #pragma unroll
    for (int i = 0; i < 2; i++) {
        int m = m0 + warp_m * 32 + i * 16 + (lane >> 2);
        #pragma unroll
        for (int j = 0; j < 8; j++) {
            int n = n0 + warp_n * 64 + j * 8 + (lane & 3) * 2;
            *(float2*)(C + (size_t)m * VV + n) =
                make_float2(acc[i][j][0], acc[i][j][1]);
            *(float2*)(C + (size_t)(m + 8) * VV + n) =
                make_float2(acc[i][j][2], acc[i][j][3]);
        }
    }
}

// ---------------- init -------------------------------------------------------
__global__ void init_kernel(const int* __restrict__ inputs,
                            const int* __restrict__ carry_inputs,
                            const void* __restrict__ halted,
                            const float* __restrict__ carry_hidden,
                            const float* __restrict__ init_hidden,
                            const float* __restrict__ emb,
                            const float* __restrict__ pos,
                            const float* __restrict__ in_s,
                            const float* __restrict__ in_b)
{
    int r = blockIdx.x;
    int b = r / NN, n = r % NN;
    int t = threadIdx.x;
    bool h = read_halted(halted, b);
    int idx = h ? inputs[r] : carry_inputs[r];
    const float* e = emb + (size_t)idx * DD;
    const float* p = pos + (size_t)n * DD;

    float x0 = e[t]       + p[t];
    float x1 = e[t + 256] + p[t + 256];

    size_t base = (size_t)r * DD;
    g_Q[base + t]       = h ? init_hidden[t]       : carry_hidden[base + t];
    g_Q[base + t + 256] = h ? init_hidden[t + 256] : carry_hidden[base + t + 256];

    __shared__ float s_sum[256], s_sq[256];
    s_sum[t] = x0 + x1;
    s_sq[t]  = x0 * x0 + x1 * x1;
    __syncthreads();
    for (int o = 128; o > 0; o >>= 1) {
        if (t < o) { s_sum[t] += s_sum[t + o]; s_sq[t] += s_sq[t + o]; }
        __syncthreads();
    }
    float mu   = s_sum[0] * (1.0f / DD);
    float var  = s_sq[0] * (1.0f / DD) - mu * mu;
    float rstd = rsqrtf(var + 1e-5f);
    g_X[base + t]       = (x0 - mu) * rstd * in_s[t]       + in_b[t];
    g_X[base + t + 256] = (x1 - mu) * rstd * in_s[t + 256] + in_b[t + 256];
}

// ---------------- LayerNorm: warp-per-row, 8 rows/CTA -------------------------
__global__ void __launch_bounds__(256) ln_kernel(
    const float* __restrict__ in, float* __restrict__ outf,
    h16* __restrict__ outh, h16* __restrict__ outl,
    const float* __restrict__ s, const float* __restrict__ bia,
    const float* __restrict__ add)
{
    const int warp = threadIdx.x >> 5, lane = threadIdx.x & 31;
    const int r = blockIdx.x * 8 + warp;
    const size_t base = (size_t)r * DD;

    float x[16];
    float sum = 0.0f, sq = 0.0f;
    #pragma unroll
    for (int i = 0; i < 4; i++) {
        float4 v = *(const float4*)(in + base + lane * 4 + i * 128);
        x[4*i+0] = v.x; x[4*i+1] = v.y; x[4*i+2] = v.z; x[4*i+3] = v.w;
        sum += v.x + v.y + v.z + v.w;
        sq  += v.x*v.x + v.y*v.y + v.z*v.z + v.w*v.w;
    }
    #pragma unroll
    for (int o = 16; o > 0; o >>= 1) {
        sum += __shfl_xor_sync(0xFFFFFFFFu, sum, o);
        sq  += __shfl_xor_sync(0xFFFFFFFFu, sq,  o);
    }
    float mu   = sum * (1.0f / DD);
    float var  = sq * (1.0f / DD) - mu * mu;
    float rstd = rsqrtf(var + 1e-5f);

    #pragma unroll
    for (int i = 0; i < 4; i++) {
        int c = lane * 4 + i * 128;
        float4 sv = *(const float4*)(s + c);
        float4 bv = *(const float4*)(bia + c);
        float v0 = (x[4*i+0] - mu) * rstd * sv.x + bv.x;
        float v1 = (x[4*i+1] - mu) * rstd * sv.y + bv.y;
        float v2 = (x[4*i+2] - mu) * rstd * sv.z + bv.z;
        float v3 = (x[4*i+3] - mu) * rstd * sv.w + bv.w;
        if (add) {
            float4 av = *(const float4*)(add + base + c);
            v0 += av.x; v1 += av.y; v2 += av.z; v3 += av.w;
        }
        if (outf) *(float4*)(outf + base + c) = make_float4(v0, v1, v2, v3);
        if (outh) {
            h16 h0, l0, h1, l1, h2, l2, h3, l3;
            split1h(v0, h0, l0); split1h(v1, h1, l1);
            split1h(v2, h2, l2); split1h(v3, h3, l3);
            *(uint2*)(outh + base + c) = make_uint2(pack2h(h0, h1), pack2h(h2, h3));
            *(uint2*)(outl + base + c) = make_uint2(pack2h(l0, l1), pack2h(l2, l3));
        }
    }
}

// ---------------- depthwise conv k=3 + bias + silu -> fp16 hi/lo --------------
__global__ void conv_kernel(const float* __restrict__ Hf, const float* __restrict__ w,
                            const float* __restrict__ bias,
                            h16* __restrict__ outh, h16* __restrict__ outl)
{
    size_t i = (size_t)blockIdx.x * 256 + threadIdx.x;
    if (i >= (size_t)MROWS * INNER) return;
    size_t row = i / INNER;
    int c = (int)(i % INNER);
    int n = (int)(row % NN);
    const float* wc = w + (size_t)c * CKW;
    float acc = bias[c];
    if (n > 0)      acc += wc[0] * Hf[(row - 1) * INNER + c];
    acc += wc[1] * Hf[row * INNER + c];
    if (n < NN - 1) acc += wc[2] * Hf[(row + 1) * INNER + c];
    float v = siluf(acc);
    h16 h, l;
    split1h(v, h, l);
    outh[i] = h;
    outl[i] = l;
}

// ---------------- halt head --------------------------------------------------
__global__ void halt_kernel(const float* __restrict__ Qn, const float* __restrict__ hw,
                            const float* __restrict__ hb, float* __restrict__ out)
{
    int b = blockIdx.x;
    int t = threadIdx.x;
    __shared__ float md[DD];
    for (int d = t; d < DD; d += 256) {
        float s = 0.0f;
        for (int n = 0; n < NN; n++)
            s += Qn[((size_t)(b * NN + n)) * DD + d];
        md[d] = s * (1.0f / NN);
    }
    __syncthreads();
    __shared__ float r0[256], r1[256];
    float p0 = 0.0f, p1 = 0.0f;
    for (int d = t; d < DD; d += 256) {
        p0 += md[d] * hw[d];
        p1 += md[d] * hw[DD + d];
    }
    r0[t] = p0; r1[t] = p1;
    __syncthreads();
    for (int o = 128; o > 0; o >>= 1) {
        if (t < o) { r0[t] += r0[t + o]; r1[t] += r1[t + o]; }
        __syncthreads();
    }
    if (t == 0) {
        out[b * 2 + 0] = r0[0] + hb[0];
        out[b * 2 + 1] = r1[0] + hb[1];
    }
}

// ---------------- host orchestration -----------------------------------------
static void cvt_h(const float* src, h16* d, size_t n)
{
    int n4 = (int)(n / 4);
    cvt_h_kernel<<<(n4 + 255) / 256, 256>>>(src, d, n4);
}

extern "C" void kernel_launch(void* const* d_in, const int* in_sizes, int n_in,
                              void* d_out, int out_size)
{
    const int*   inputs       = (const int*)d_in[0];
    const float* carry_hidden = (const float*)d_in[2];
    const void*  halted       = d_in[4];
    const int*   carry_inputs = (const int*)d_in[5];
    const float* init_hidden  = (const float*)d_in[7];
    const float* emb          = (const float*)d_in[8];
    const float* pos          = (const float*)d_in[9];
    const float* in_s         = (const float*)d_in[10];
    const float* in_b         = (const float*)d_in[11];
    const float* fin_s        = (const float*)d_in[12];
    const float* fin_b        = (const float*)d_in[13];
    const float* lm_w         = (const float*)d_in[14];
    const float* halt_w       = (const float*)d_in[15];
    const float* halt_b       = (const float*)d_in[16];
    const float* dt           = (const float*)d_in[17];
    const float* W_Q          = (const float*)d_in[18];
    const float* W_K          = (const float*)d_in[19];
    const float* W_V          = (const float*)d_in[20];
    const float* W_O          = (const float*)d_in[21];
    const float* W_up         = (const float*)d_in[22];
    const float* dw_w         = (const float*)d_in[23];
    const float* dw_b         = (const float*)d_in[24];
    const float* W_down       = (const float*)d_in[25];
    const float* n1_s         = (const float*)d_in[26];
    const float* n1_b         = (const float*)d_in[27];
    const float* n2_s         = (const float*)d_in[28];
    const float* n2_b         = (const float*)d_in[29];

    float *X, *Q, *Qi, *Qn, *Hf;
    h16 *Hch, *Hcl, *mbh, *mbl, *Q2h, *Q2l, *Hvh, *Hvl, *Qnh, *Qnl;
    bf16 *PQh, *PQl, *PKh, *Vh, *Vl;
    h16 *WQh, *WKh, *WVh, *WOh, *WUh, *WDh, *LMh;
    cudaGetSymbolAddress((void**)&X,   g_X);
    cudaGetSymbolAddress((void**)&Q,   g_Q);
    cudaGetSymbolAddress((void**)&Qi,  g_Qi);
    cudaGetSymbolAddress((void**)&Qn,  g_Qn);
    cudaGetSymbolAddress((void**)&Hf,  g_Hf);
    cudaGetSymbolAddress((void**)&Hch, g_Hch); cudaGetSymbolAddress((void**)&Hcl, g_Hcl);
    cudaGetSymbolAddress((void**)&PQh, g_PQh); cudaGetSymbolAddress((void**)&PQl, g_PQl);
    cudaGetSymbolAddress((void**)&PKh, g_PKh);
    cudaGetSymbolAddress((void**)&Vh,  g_Vh);  cudaGetSymbolAddress((void**)&Vl,  g_Vl);
    cudaGetSymbolAddress((void**)&mbh, g_mbh); cudaGetSymbolAddress((void**)&mbl, g_mbl);
    cudaGetSymbolAddress((void**)&Q2h, g_Q2h); cudaGetSymbolAddress((void**)&Q2l, g_Q2l);
    cudaGetSymbolAddress((void**)&Hvh, g_Hvh); cudaGetSymbolAddress((void**)&Hvl, g_Hvl);
    cudaGetSymbolAddress((void**)&Qnh, g_Qnh); cudaGetSymbolAddress((void**)&Qnl, g_Qnl);
    cudaGetSymbolAddress((void**)&WQh, g_WQh);
    cudaGetSymbolAddress((void**)&WKh, g_WKh);
    cudaGetSymbolAddress((void**)&WVh, g_WVh);
    cudaGetSymbolAddress((void**)&WOh, g_WOh);
    cudaGetSymbolAddress((void**)&WUh, g_WUh);
    cudaGetSymbolAddress((void**)&WDh, g_WDh);
    cudaGetSymbolAddress((void**)&LMh, g_LMh);

    float* out = (float*)d_out;

    cudaFuncSetAttribute(attn_fused, cudaFuncAttributeMaxDynamicSharedMemorySize, ATT_SMEM);
    cudaFuncSetAttribute(mma_proj,   cudaFuncAttributeMaxDynamicSharedMemorySize, SM_G128);
    cudaFuncSetAttribute(mma_up,     cudaFuncAttributeMaxDynamicSharedMemorySize, SM_G128);
    cudaFuncSetAttribute(mma_wo,     cudaFuncAttributeMaxDynamicSharedMemorySize, SM_G64);
    cudaFuncSetAttribute(mma_down,   cudaFuncAttributeMaxDynamicSharedMemorySize, SM_G64);
    cudaFuncSetAttribute(lm_head_mma, cudaFuncAttributeMaxDynamicSharedMemorySize, SM_LM);

    cvt_h(W_Q,    WQh, (size_t)KKB * DD * DD);
    cvt_h(W_K,    WKh, (size_t)KKB * DD * DD);
    cvt_h(W_V,    WVh, (size_t)KKB * DD * DD);
    cvt_h(W_O,    WOh, (size_t)KKB * DD * DD);
    {
        int total = KKB * DD * (2 * INNER) / 8;
        cvt_up_kernel<<<(total + 255) / 256, 256>>>(W_up, WUh);
    }
    cvt_h(W_down, WDh, (size_t)KKB * INNER * DD);
    cvt_h(lm_w,   LMh, (size_t)VV * DD);

    init_kernel<<<MROWS, 256>>>(inputs, carry_inputs, halted, carry_hidden,
                                init_hidden, emb, pos, in_s, in_b);

    dim3 gP(DD / 128, MROWS / 128, 3);        // (4, 16, 3)
    dim3 gO64(DD / 64, MROWS / 128);          // (8, 16) = 128 CTAs
    dim3 gUP(2 * INNER / 128, MROWS / 128);   // (24, 16)
    dim3 gAT(NN / 128, BHN);                  // (8, 16)
    const int gLN = MROWS / 8;                // 256 CTAs, warp-per-row

    for (int it = 0; it < TOTAL_PASSES; it++) {
        int k = it % KKB;

        ln_kernel<<<gLN, 256>>>(Q, nullptr, Hch, Hcl,
                                n1_s + k * DD, n1_b + k * DD, X);

        mma_proj<<<gP, 256, SM_G128>>>(Hch, Hcl, k);

        attn_fused<<<gAT, 256, ATT_SMEM>>>(PQh, PQl, PKh, Vh, Vl, mbh, mbl);

        mma_wo<<<gO64, 256, SM_G64>>>(mbh, mbl, k, Qi, Q, dt);

        ln_kernel<<<gLN, 256>>>(Qi, nullptr, Q2h, Q2l,
                                n2_s + k * DD, n2_b + k * DD, nullptr);
        mma_up<<<gUP, 256, SM_G128>>>(Q2h, Q2l, k, Hf);    // fused swiglu
        int tot = MROWS * INNER;
        conv_kernel<<<(tot + 255) / 256, 256>>>(Hf, dw_w + (size_t)k * INNER * CKW,
                                                dw_b + (size_t)k * INNER, Hvh, Hvl);
        mma_down<<<gO64, 256, SM_G64>>>(Hvh, Hvl, k, Q, Qi);
    }

    ln_kernel<<<gLN, 256>>>(Q, Qn, Qnh, Qnl, fin_s, fin_b, nullptr);
    dim3 gLM(VV / 128, MROWS / 256);          // (250, 8)
    lm_head_mma<<<gLM, 512, SM_LM>>>(Qnh, Qnl, out);
    halt_kernel<<<BB, 256>>>(Qn, halt_w, halt_b, out + (size_t)MROWS * VV);
}